// round 1
// baseline (speedup 1.0000x reference)
#include <cuda_runtime.h>
#include <cuda_bf16.h>
#include <math.h>

// Problem constants
#define BB 2
#define SS 2048
#define DD 768
#define HH 12
#define FF 3072
#define HDD 64
#define ROWS (BB*SS)          // 4096
#define BH (BB*HH)            // 24

// -------------------- device scratch (static, allowed) --------------------
__device__ float g_hx [ROWS*DD];           // ln1(x)
__device__ float g_qkv[ROWS*3*DD];         // [b,s, 3, h, hd]
__device__ float g_sc [(long long)BH*SS*SS]; // scores/probs  ~402 MB
__device__ float g_o  [ROWS*DD];           // attn out (b,s,d)
__device__ float g_x1 [ROWS*DD];           // x + attn proj
__device__ float g_h2 [ROWS*DD];           // ln2(x1)
__device__ float g_ff1[ROWS*FF];           // gelu(fc1)

// -------------------- layernorm --------------------
__global__ __launch_bounds__(256) void ln_kernel(const float* __restrict__ x,
                                                 const float* __restrict__ w,
                                                 const float* __restrict__ b,
                                                 float* __restrict__ y)
{
    __shared__ float red[256];
    int tid = threadIdx.x;
    const float* xr = x + (size_t)blockIdx.x * DD;
    float*       yr = y + (size_t)blockIdx.x * DD;
    float v0 = xr[tid], v1 = xr[tid + 256], v2 = xr[tid + 512];
    red[tid] = v0 + v1 + v2;
    __syncthreads();
    for (int off = 128; off; off >>= 1) {
        if (tid < off) red[tid] += red[tid + off];
        __syncthreads();
    }
    float mean = red[0] * (1.0f / DD);
    __syncthreads();
    float d0 = v0 - mean, d1 = v1 - mean, d2 = v2 - mean;
    red[tid] = d0*d0 + d1*d1 + d2*d2;
    __syncthreads();
    for (int off = 128; off; off >>= 1) {
        if (tid < off) red[tid] += red[tid + off];
        __syncthreads();
    }
    float rstd = rsqrtf(red[0] * (1.0f / DD) + 1e-5f);
    yr[tid]       = d0 * rstd * w[tid]       + b[tid];
    yr[tid + 256] = d1 * rstd * w[tid + 256] + b[tid + 256];
    yr[tid + 512] = d2 * rstd * w[tid + 512] + b[tid + 512];
}

// -------------------- softmax over full row (masked entries are -1e30) ----
__global__ __launch_bounds__(256) void softmax_kernel(float* __restrict__ sc)
{
    __shared__ float red[256];
    int tid = threadIdx.x;
    float* r = sc + (size_t)blockIdx.x * SS;
    float v[8];
    float mx = -1e30f;
#pragma unroll
    for (int i = 0; i < 8; i++) { v[i] = r[tid + i*256]; mx = fmaxf(mx, v[i]); }
    red[tid] = mx;
    __syncthreads();
    for (int off = 128; off; off >>= 1) {
        if (tid < off) red[tid] = fmaxf(red[tid], red[tid + off]);
        __syncthreads();
    }
    mx = red[0];
    __syncthreads();
    float s = 0.f;
#pragma unroll
    for (int i = 0; i < 8; i++) { v[i] = __expf(v[i] - mx); s += v[i]; }
    red[tid] = s;
    __syncthreads();
    for (int off = 128; off; off >>= 1) {
        if (tid < off) red[tid] += red[tid + off];
        __syncthreads();
    }
    float inv = 1.0f / red[0];
#pragma unroll
    for (int i = 0; i < 8; i++) r[tid + i*256] = v[i] * inv;
}

// -------------------- generic tiled fp32 GEMM --------------------
// C[m,n] = sum_k A[m,k] * B'[k,n], where B' = B^T if B_NT (B is [N,K]) else B ([K,N]).
// Batched via blockIdx.z = bo*innerCount + bi with separate outer/inner strides.
enum { EPI_BIAS = 0, EPI_BIASRES = 1, EPI_GELU = 2, EPI_MASK = 3 };

template<int BM, int BN, int BK, int TM, int TN, bool B_NT, int EPI, bool CAUSAL_K>
__global__ __launch_bounds__(256) void gemm_kernel(
    const float* __restrict__ A, const float* __restrict__ B,
    const float* __restrict__ bias, const float* __restrict__ resid,
    float* __restrict__ C,
    int K, int lda, int ldb, int ldc,
    int innerCount,
    long long sAo, long long sAi,
    long long sBo, long long sBi,
    long long sCo, long long sCi)
{
    constexpr int NT = (BM / TM) * (BN / TN);   // 256
    constexpr int AS = BM + 4, BS = BN + 4;
    __shared__ float As[BK * AS];
    __shared__ float Bs[BK * BS];

    int bz = blockIdx.z;
    int bo = bz / innerCount, bi = bz % innerCount;
    A += bo * sAo + bi * sAi;
    B += bo * sBo + bi * sBi;
    C += bo * sCo + bi * sCi;
    if (EPI == EPI_BIASRES) resid += bo * sCo + bi * sCi;

    const int m0 = blockIdx.y * BM, n0 = blockIdx.x * BN;
    const int tid = threadIdx.x;
    const int tx = tid % (BN / TN), ty = tid / (BN / TN);

    if (EPI == EPI_MASK && n0 > m0 + BM - 1) {
        // tile fully above the causal diagonal
#pragma unroll
        for (int i = 0; i < TM; i++)
#pragma unroll
            for (int j = 0; j < TN; j++)
                C[(size_t)(m0 + ty*TM + i) * ldc + n0 + tx*TN + j] = -1e30f;
        return;
    }

    float acc[TM][TN] = {};

    int ktEnd = K / BK;
    if (CAUSAL_K) {                      // probs are zero past the diagonal
        int kmax = m0 + BM;
        if (kmax < K) ktEnd = kmax / BK;
    }

    for (int kt = 0; kt < ktEnd; ++kt) {
        // ---- load A tile (transposed into smem: As[k][m]) ----
#pragma unroll
        for (int i = 0; i < BM * BK / (NT * 4); ++i) {
            int idx = (tid + i * NT) * 4;
            int m = idx / BK, kk = idx % BK;
            const float4 v = *reinterpret_cast<const float4*>(
                A + (size_t)(m0 + m) * lda + kt * BK + kk);
            As[(kk + 0) * AS + m] = v.x;
            As[(kk + 1) * AS + m] = v.y;
            As[(kk + 2) * AS + m] = v.z;
            As[(kk + 3) * AS + m] = v.w;
        }
        // ---- load B tile ----
        if (B_NT) {
#pragma unroll
            for (int i = 0; i < BN * BK / (NT * 4); ++i) {
                int idx = (tid + i * NT) * 4;
                int n = idx / BK, kk = idx % BK;
                const float4 v = *reinterpret_cast<const float4*>(
                    B + (size_t)(n0 + n) * ldb + kt * BK + kk);
                Bs[(kk + 0) * BS + n] = v.x;
                Bs[(kk + 1) * BS + n] = v.y;
                Bs[(kk + 2) * BS + n] = v.z;
                Bs[(kk + 3) * BS + n] = v.w;
            }
        } else {
#pragma unroll
            for (int i = 0; i < BN * BK / (NT * 4); ++i) {
                int idx = (tid + i * NT) * 4;
                int kk = idx / BN, n = idx % BN;
                *reinterpret_cast<float4*>(&Bs[kk * BS + n]) =
                    *reinterpret_cast<const float4*>(
                        B + (size_t)(kt * BK + kk) * ldb + n0 + n);
            }
        }
        __syncthreads();

#pragma unroll
        for (int kk = 0; kk < BK; ++kk) {
            float a[TM], bb[TN];
#pragma unroll
            for (int i = 0; i < TM; i += 4)
                *reinterpret_cast<float4*>(&a[i]) =
                    *reinterpret_cast<const float4*>(&As[kk * AS + ty * TM + i]);
#pragma unroll
            for (int j = 0; j < TN; j += 4)
                *reinterpret_cast<float4*>(&bb[j]) =
                    *reinterpret_cast<const float4*>(&Bs[kk * BS + tx * TN + j]);
#pragma unroll
            for (int i = 0; i < TM; i++)
#pragma unroll
                for (int j = 0; j < TN; j++)
                    acc[i][j] = fmaf(a[i], bb[j], acc[i][j]);
        }
        __syncthreads();
    }

    // ---- epilogue ----
#pragma unroll
    for (int i = 0; i < TM; i++) {
        int m = m0 + ty * TM + i;
#pragma unroll
        for (int j = 0; j < TN; j++) {
            int n = n0 + tx * TN + j;
            float v = acc[i][j];
            if (EPI == EPI_MASK) {
                v *= 0.125f;               // 1/sqrt(64)
                if (n > m) v = -1e30f;     // causal
            } else {
                if (bias) v += bias[n];
                if (EPI == EPI_GELU)
                    v = 0.5f * v * (1.0f + erff(v * 0.70710678118654752f));
                if (EPI == EPI_BIASRES)
                    v += resid[(size_t)m * ldc + n];
            }
            C[(size_t)m * ldc + n] = v;
        }
    }
}

// -------------------- host launcher --------------------
extern "C" void kernel_launch(void* const* d_in, const int* in_sizes, int n_in,
                              void* d_out, int out_size)
{
    const float* x     = (const float*)d_in[0];
    // d_in[1] = mask (bool causal) — known statically, unused
    const float* qkv_w = (const float*)d_in[2];
    const float* qkv_b = (const float*)d_in[3];
    const float* out_w = (const float*)d_in[4];
    const float* out_b = (const float*)d_in[5];
    const float* fc1_w = (const float*)d_in[6];
    const float* fc1_b = (const float*)d_in[7];
    const float* fc2_w = (const float*)d_in[8];
    const float* fc2_b = (const float*)d_in[9];
    const float* ln1_w = (const float*)d_in[10];
    const float* ln1_b = (const float*)d_in[11];
    const float* ln2_w = (const float*)d_in[12];
    const float* ln2_b = (const float*)d_in[13];
    float* out = (float*)d_out;

    void *p_hx, *p_qkv, *p_sc, *p_o, *p_x1, *p_h2, *p_ff1;
    cudaGetSymbolAddress(&p_hx,  g_hx);
    cudaGetSymbolAddress(&p_qkv, g_qkv);
    cudaGetSymbolAddress(&p_sc,  g_sc);
    cudaGetSymbolAddress(&p_o,   g_o);
    cudaGetSymbolAddress(&p_x1,  g_x1);
    cudaGetSymbolAddress(&p_h2,  g_h2);
    cudaGetSymbolAddress(&p_ff1, g_ff1);
    float* hx  = (float*)p_hx;   float* qkv = (float*)p_qkv;
    float* sc  = (float*)p_sc;   float* o   = (float*)p_o;
    float* x1  = (float*)p_x1;   float* h2  = (float*)p_h2;
    float* ff1 = (float*)p_ff1;

    // 1. ln1
    ln_kernel<<<ROWS, 256>>>(x, ln1_w, ln1_b, hx);

    // 2. QKV projection: [4096,768] x [2304,768]^T -> [4096,2304]
    gemm_kernel<128,128,16,8,8,true,EPI_BIAS,false>
        <<<dim3(3*DD/128, ROWS/128, 1), 256>>>(
            hx, qkv_w, qkv_b, nullptr, qkv,
            DD, DD, DD, 3*DD, 1, 0,0, 0,0, 0,0);

    // 3. scores = Q K^T / 8 + causal mask   (per b,h; K=64)
    gemm_kernel<128,128,16,8,8,true,EPI_MASK,false>
        <<<dim3(SS/128, SS/128, BH), 256>>>(
            qkv,              /* Q base  */
            qkv + DD,         /* K base  */
            nullptr, nullptr, sc,
            HDD, 3*DD, 3*DD, SS, HH,
            (long long)SS*3*DD, HDD,          // A: b, h strides
            (long long)SS*3*DD, HDD,          // B: b, h strides
            (long long)HH*SS*SS, (long long)SS*SS);  // C

    // 4. softmax (in place)
    softmax_kernel<<<BH*SS, 256>>>(sc);

    // 5. O = P V   (per b,h; V is [K,N] row-major with stride 3D; causal K-limit)
    gemm_kernel<128,64,16,8,4,false,EPI_BIAS,true>
        <<<dim3(HDD/64, SS/128, BH), 256>>>(
            sc, qkv + 2*DD, nullptr, nullptr, o,
            SS, SS, 3*DD, DD, HH,
            (long long)HH*SS*SS, (long long)SS*SS,   // A (probs)
            (long long)SS*3*DD, HDD,                  // B (V)
            (long long)SS*DD, HDD);                   // C -> o[b,s,h*64+d]

    // 6. x1 = x + O @ out_w^T + out_b
    gemm_kernel<128,128,16,8,8,true,EPI_BIASRES,false>
        <<<dim3(DD/128, ROWS/128, 1), 256>>>(
            o, out_w, out_b, x, x1,
            DD, DD, DD, DD, 1, 0,0, 0,0, 0,0);

    // 7. ln2
    ln_kernel<<<ROWS, 256>>>(x1, ln2_w, ln2_b, h2);

    // 8. ff1 = gelu(h2 @ fc1_w^T + fc1_b)
    gemm_kernel<128,128,16,8,8,true,EPI_GELU,false>
        <<<dim3(FF/128, ROWS/128, 1), 256>>>(
            h2, fc1_w, fc1_b, nullptr, ff1,
            DD, DD, DD, FF, 1, 0,0, 0,0, 0,0);

    // 9. out = x1 + ff1 @ fc2_w^T + fc2_b
    gemm_kernel<128,128,16,8,8,true,EPI_BIASRES,false>
        <<<dim3(DD/128, ROWS/128, 1), 256>>>(
            ff1, fc2_w, fc2_b, x1, out,
            FF, FF, FF, DD, 1, 0,0, 0,0, 0,0);
}

// round 3
// speedup vs baseline: 1.9948x; 1.9948x over previous
#include <cuda_runtime.h>
#include <cuda_bf16.h>
#include <math.h>
#include <stdint.h>

// Problem constants
#define BB 2
#define SS 2048
#define DD 768
#define HH 12
#define FF 3072
#define HDD 64
#define ROWS (BB*SS)          // 4096
#define BH (BB*HH)            // 24

// -------------------- device scratch --------------------
__device__ float g_hx [ROWS*DD];
__device__ float g_qkv[ROWS*3*DD];
__device__ float g_sc [(long long)BH*SS*SS];   // scores/probs ~402MB
__device__ float g_o  [ROWS*DD];
__device__ float g_x1 [ROWS*DD];
__device__ float g_h2 [ROWS*DD];
__device__ float g_ff1[ROWS*FF];

// -------------------- warp MMA helpers (non-arch-specific) --------------------
__device__ __forceinline__ uint32_t smem_u32(const void* p){
    uint32_t a;
    asm("{ .reg .u64 t; cvta.to.shared.u64 t, %1; cvt.u32.u64 %0, t; }"
        : "=r"(a) : "l"(p));
    return a;
}
__device__ __forceinline__ void ldsm_x4(uint32_t* r, uint32_t a){
    asm volatile("ldmatrix.sync.aligned.m8n8.x4.shared.b16 {%0,%1,%2,%3}, [%4];"
        : "=r"(r[0]),"=r"(r[1]),"=r"(r[2]),"=r"(r[3]) : "r"(a));
}
__device__ __forceinline__ void ldsm_x4t(uint32_t* r, uint32_t a){
    asm volatile("ldmatrix.sync.aligned.m8n8.x4.trans.shared.b16 {%0,%1,%2,%3}, [%4];"
        : "=r"(r[0]),"=r"(r[1]),"=r"(r[2]),"=r"(r[3]) : "r"(a));
}
__device__ __forceinline__ void mma16816(float* c, const uint32_t* a, const uint32_t* b){
    asm volatile(
        "mma.sync.aligned.m16n8k16.row.col.f32.bf16.bf16.f32 "
        "{%0,%1,%2,%3}, {%4,%5,%6,%7}, {%8,%9}, {%0,%1,%2,%3};"
        : "+f"(c[0]),"+f"(c[1]),"+f"(c[2]),"+f"(c[3])
        : "r"(a[0]),"r"(a[1]),"r"(a[2]),"r"(a[3]), "r"(b[0]),"r"(b[1]));
}
static __device__ __forceinline__ uint32_t pack2(__nv_bfloat16 a, __nv_bfloat16 b){
    return (uint32_t)__bfloat16_as_ushort(a) | ((uint32_t)__bfloat16_as_ushort(b) << 16);
}
static __device__ __forceinline__ void split4(const float4 v, uint2& hi, uint2& lo){
    __nv_bfloat16 h0 = __float2bfloat16(v.x), h1 = __float2bfloat16(v.y);
    __nv_bfloat16 h2 = __float2bfloat16(v.z), h3 = __float2bfloat16(v.w);
    __nv_bfloat16 l0 = __float2bfloat16(v.x - __bfloat162float(h0));
    __nv_bfloat16 l1 = __float2bfloat16(v.y - __bfloat162float(h1));
    __nv_bfloat16 l2 = __float2bfloat16(v.z - __bfloat162float(h2));
    __nv_bfloat16 l3 = __float2bfloat16(v.w - __bfloat162float(h3));
    hi = make_uint2(pack2(h0,h1), pack2(h2,h3));
    lo = make_uint2(pack2(l0,l1), pack2(l2,l3));
}

// -------------------- layernorm --------------------
__global__ __launch_bounds__(256) void ln_kernel(const float* __restrict__ x,
                                                 const float* __restrict__ w,
                                                 const float* __restrict__ b,
                                                 float* __restrict__ y)
{
    __shared__ float red[256];
    int tid = threadIdx.x;
    const float* xr = x + (size_t)blockIdx.x * DD;
    float*       yr = y + (size_t)blockIdx.x * DD;
    float v0 = xr[tid], v1 = xr[tid + 256], v2 = xr[tid + 512];
    red[tid] = v0 + v1 + v2;
    __syncthreads();
    for (int off = 128; off; off >>= 1) {
        if (tid < off) red[tid] += red[tid + off];
        __syncthreads();
    }
    float mean = red[0] * (1.0f / DD);
    __syncthreads();
    float d0 = v0 - mean, d1 = v1 - mean, d2 = v2 - mean;
    red[tid] = d0*d0 + d1*d1 + d2*d2;
    __syncthreads();
    for (int off = 128; off; off >>= 1) {
        if (tid < off) red[tid] += red[tid + off];
        __syncthreads();
    }
    float rstd = rsqrtf(red[0] * (1.0f / DD) + 1e-5f);
    yr[tid]       = d0 * rstd * w[tid]       + b[tid];
    yr[tid + 256] = d1 * rstd * w[tid + 256] + b[tid + 256];
    yr[tid + 512] = d2 * rstd * w[tid + 512] + b[tid + 512];
}

// -------------------- causal-prefix softmax --------------------
// Row i: softmax over [0,i]; zero-fill (i, 128-tile boundary) which PV reads.
__global__ __launch_bounds__(256) void softmax_pfx(float* __restrict__ sc)
{
    __shared__ float red[256];
    long long r = blockIdx.x;                 // bh*SS + i
    int i = (int)(r % SS);
    float* row = sc + r * (long long)SS;
    int len  = i + 1;
    int wlen = ((i >> 7) + 1) << 7;
    int tid = threadIdx.x;

    float v[8];
    float mx = -1e30f;
#pragma unroll
    for (int j = 0; j < 8; j++) {
        int c = tid + j * 256;
        v[j] = (c < len) ? row[c] : -1e30f;
        mx = fmaxf(mx, v[j]);
    }
    red[tid] = mx;
    __syncthreads();
    for (int off = 128; off; off >>= 1) {
        if (tid < off) red[tid] = fmaxf(red[tid], red[tid + off]);
        __syncthreads();
    }
    mx = red[0];
    __syncthreads();
    float s = 0.f;
#pragma unroll
    for (int j = 0; j < 8; j++) {
        int c = tid + j * 256;
        v[j] = (c < len) ? __expf(v[j] - mx) : 0.f;
        s += v[j];
    }
    red[tid] = s;
    __syncthreads();
    for (int off = 128; off; off >>= 1) {
        if (tid < off) red[tid] += red[tid + off];
        __syncthreads();
    }
    float inv = 1.0f / red[0];
#pragma unroll
    for (int j = 0; j < 8; j++) {
        int c = tid + j * 256;
        if (c < len) row[c] = v[j] * inv;
    }
    for (int c = len + tid; c < wlen; c += 256) row[c] = 0.f;
}

// -------------------- warp-MMA split-bf16 GEMM --------------------
// C[m,n] = sum_k A[m,k]*B'[k,n].
//   B_NT: B rows indexed by n, K-major ([n][k]) -> plain ldmatrix
//   else: B is [k][n] row-major -> trans ldmatrix  (PV case)
// fp32 split into bf16 hi/lo; 3 MMAs per fragment (hh + hl + lh).
enum { EPI_BIAS = 0, EPI_BIASRES = 1, EPI_GELU = 2, EPI_SCALE = 3 };

template<int BN, bool B_NT, int EPI, bool CAUSAL_K, bool CAUSAL_SKIP>
__global__ __launch_bounds__(256) void mma_gemm(
    const float* __restrict__ A, const float* __restrict__ Bm,
    const float* __restrict__ bias, const float* __restrict__ resid,
    float* __restrict__ C,
    int K, int lda, int ldb, int ldc, int innerCount,
    long long sAo, long long sAi,
    long long sBo, long long sBi,
    long long sCo, long long sCi)
{
    constexpr int BM = 128, BK = 32;
    constexpr int ASTR = 80;               // bytes/row (32 bf16 + pad): conflict-free ldmatrix
    constexpr int AHI = 0, ALO = BM * ASTR;            // 10240
    constexpr int BBASE = 2 * BM * ASTR;               // 20480
    constexpr int BSTR_NT = 80, BSTR_T = 144;
    constexpr int BLO_NT = BN * 80;
    constexpr int BLO_T  = BK * 144;                   // 4608
    constexpr int WM = (BN == 128) ? 64 : 32;
    constexpr int MF = WM / 16;            // m-frags per warp
    constexpr int NF = 4;                  // 32 cols per warp

    __shared__ __align__(128) char smem[BBASE + 2 * ((BN==128)? BN*80 : BK*144)];

    const int m0 = blockIdx.y * BM, n0 = blockIdx.x * BN;
    if (CAUSAL_SKIP && n0 > m0) return;

    int bz = blockIdx.z, bo = bz / innerCount, bi = bz % innerCount;
    A  += bo * sAo + bi * sAi;
    Bm += bo * sBo + bi * sBi;
    C  += bo * sCo + bi * sCi;
    if (EPI == EPI_BIASRES) resid += bo * sCo + bi * sCi;

    const int tid = threadIdx.x, wid = tid >> 5, lane = tid & 31;
    const int wm0 = (BN == 128) ? (wid & 1) * 64 : (wid & 3) * 32;
    const int wn0 = (BN == 128) ? (wid >> 1) * 32 : (wid >> 2) * 32;
    const uint32_t sb = smem_u32(smem);

    float acc[MF][NF][4];
#pragma unroll
    for (int i = 0; i < MF; i++)
#pragma unroll
        for (int j = 0; j < NF; j++)
#pragma unroll
            for (int c = 0; c < 4; c++) acc[i][j][c] = 0.f;

    int NT = K / BK;
    if (CAUSAL_K) { int km = m0 + BM; if (km < K) NT = km / BK; }

    for (int kt = 0; kt < NT; kt++) {
        // ---- load + split A tile: 128 x 32 fp32 ----
#pragma unroll
        for (int it = 0; it < 4; it++) {
            int idx = tid + it * 256;
            int r = idx >> 3, c4 = idx & 7;
            float4 v = *reinterpret_cast<const float4*>(
                A + (size_t)(m0 + r) * lda + kt * BK + c4 * 4);
            uint2 hi, lo; split4(v, hi, lo);
            *reinterpret_cast<uint2*>(smem + AHI + r * ASTR + c4 * 8) = hi;
            *reinterpret_cast<uint2*>(smem + ALO + r * ASTR + c4 * 8) = lo;
        }
        // ---- load + split B tile ----
        if (B_NT) {
#pragma unroll
            for (int it = 0; it < BN / 32; it++) {
                int idx = tid + it * 256;
                int r = idx >> 3, c4 = idx & 7;
                float4 v = *reinterpret_cast<const float4*>(
                    Bm + (size_t)(n0 + r) * ldb + kt * BK + c4 * 4);
                uint2 hi, lo; split4(v, hi, lo);
                *reinterpret_cast<uint2*>(smem + BBASE          + r * BSTR_NT + c4 * 8) = hi;
                *reinterpret_cast<uint2*>(smem + BBASE + BLO_NT + r * BSTR_NT + c4 * 8) = lo;
            }
        } else {
            // B is [k][n], 32 x 64 fp32
#pragma unroll
            for (int it = 0; it < 2; it++) {
                int idx = tid + it * 256;
                int r = idx >> 4, c4 = idx & 15;
                float4 v = *reinterpret_cast<const float4*>(
                    Bm + (size_t)(kt * BK + r) * ldb + c4 * 4);
                uint2 hi, lo; split4(v, hi, lo);
                *reinterpret_cast<uint2*>(smem + BBASE         + r * BSTR_T + c4 * 8) = hi;
                *reinterpret_cast<uint2*>(smem + BBASE + BLO_T + r * BSTR_T + c4 * 8) = lo;
            }
        }
        __syncthreads();

        // ---- compute: 2 k-steps of 16 ----
#pragma unroll
        for (int ks = 0; ks < 2; ks++) {
            uint32_t bH[NF][2], bL[NF][2];
            if (B_NT) {
#pragma unroll
                for (int h = 0; h < 2; h++) {
                    uint32_t row = wn0 + h * 16 + (lane & 7) + ((lane >> 4) << 3);
                    uint32_t ch  = (lane >> 3) & 1;
                    uint32_t ad  = sb + BBASE + row * BSTR_NT + ks * 32 + ch * 16;
                    uint32_t r4[4];
                    ldsm_x4(r4, ad);
                    bH[h*2][0]=r4[0]; bH[h*2][1]=r4[1]; bH[h*2+1][0]=r4[2]; bH[h*2+1][1]=r4[3];
                    ldsm_x4(r4, ad + BLO_NT);
                    bL[h*2][0]=r4[0]; bL[h*2][1]=r4[1]; bL[h*2+1][0]=r4[2]; bL[h*2+1][1]=r4[3];
                }
            } else {
#pragma unroll
                for (int h = 0; h < 2; h++) {
                    uint32_t row = ks * 16 + (lane & 7) + (((lane >> 3) & 1) << 3);
                    uint32_t col = wn0 + h * 16 + ((lane >> 4) << 3);
                    uint32_t ad  = sb + BBASE + row * BSTR_T + col * 2;
                    uint32_t r4[4];
                    ldsm_x4t(r4, ad);
                    bH[h*2][0]=r4[0]; bH[h*2][1]=r4[1]; bH[h*2+1][0]=r4[2]; bH[h*2+1][1]=r4[3];
                    ldsm_x4t(r4, ad + BLO_T);
                    bL[h*2][0]=r4[0]; bL[h*2][1]=r4[1]; bL[h*2+1][0]=r4[2]; bL[h*2+1][1]=r4[3];
                }
            }
#pragma unroll
            for (int mf = 0; mf < MF; mf++) {
                uint32_t row = wm0 + mf * 16 + (lane & 15);
                uint32_t ch  = lane >> 4;
                uint32_t ad  = sb + AHI + row * ASTR + ks * 32 + ch * 16;
                uint32_t aH[4], aL[4];
                ldsm_x4(aH, ad);
                ldsm_x4(aL, ad + ALO);
#pragma unroll
                for (int nf = 0; nf < NF; nf++) {
                    mma16816(acc[mf][nf], aH, bH[nf]);
                    mma16816(acc[mf][nf], aH, bL[nf]);
                    mma16816(acc[mf][nf], aL, bH[nf]);
                }
            }
        }
        __syncthreads();
    }

    // -------- epilogue --------
#pragma unroll
    for (int mf = 0; mf < MF; mf++) {
#pragma unroll
        for (int half = 0; half < 2; half++) {
            int m = m0 + wm0 + mf * 16 + (lane >> 2) + half * 8;
            float* Crow = C + (size_t)m * ldc;
            const float* Rrow = (EPI == EPI_BIASRES) ? (resid + (size_t)m * ldc) : nullptr;
#pragma unroll
            for (int nf = 0; nf < NF; nf++) {
                int n = n0 + wn0 + nf * 8 + (lane & 3) * 2;
                float v0 = acc[mf][nf][half*2 + 0];
                float v1 = acc[mf][nf][half*2 + 1];
                if (EPI == EPI_SCALE) {
                    v0 *= 0.125f; v1 *= 0.125f;
                } else {
                    if (bias) { v0 += __ldg(&bias[n]); v1 += __ldg(&bias[n+1]); }
                    if (EPI == EPI_GELU) {
                        v0 = 0.5f * v0 * (1.0f + erff(v0 * 0.70710678118654752f));
                        v1 = 0.5f * v1 * (1.0f + erff(v1 * 0.70710678118654752f));
                    }
                    if (EPI == EPI_BIASRES) { v0 += Rrow[n]; v1 += Rrow[n+1]; }
                }
                *reinterpret_cast<float2*>(Crow + n) = make_float2(v0, v1);
            }
        }
    }
}

// -------------------- host launcher --------------------
extern "C" void kernel_launch(void* const* d_in, const int* in_sizes, int n_in,
                              void* d_out, int out_size)
{
    const float* x     = (const float*)d_in[0];
    const float* qkv_w = (const float*)d_in[2];
    const float* qkv_b = (const float*)d_in[3];
    const float* out_w = (const float*)d_in[4];
    const float* out_b = (const float*)d_in[5];
    const float* fc1_w = (const float*)d_in[6];
    const float* fc1_b = (const float*)d_in[7];
    const float* fc2_w = (const float*)d_in[8];
    const float* fc2_b = (const float*)d_in[9];
    const float* ln1_w = (const float*)d_in[10];
    const float* ln1_b = (const float*)d_in[11];
    const float* ln2_w = (const float*)d_in[12];
    const float* ln2_b = (const float*)d_in[13];
    float* out = (float*)d_out;

    void *p_hx, *p_qkv, *p_sc, *p_o, *p_x1, *p_h2, *p_ff1;
    cudaGetSymbolAddress(&p_hx,  g_hx);
    cudaGetSymbolAddress(&p_qkv, g_qkv);
    cudaGetSymbolAddress(&p_sc,  g_sc);
    cudaGetSymbolAddress(&p_o,   g_o);
    cudaGetSymbolAddress(&p_x1,  g_x1);
    cudaGetSymbolAddress(&p_h2,  g_h2);
    cudaGetSymbolAddress(&p_ff1, g_ff1);
    float* hx  = (float*)p_hx;   float* qkv = (float*)p_qkv;
    float* sc  = (float*)p_sc;   float* o   = (float*)p_o;
    float* x1  = (float*)p_x1;   float* h2  = (float*)p_h2;
    float* ff1 = (float*)p_ff1;

    // 1. ln1
    ln_kernel<<<ROWS, 256>>>(x, ln1_w, ln1_b, hx);

    // 2. QKV: [4096,768] x [2304,768]^T -> [4096,2304]
    mma_gemm<128,true,EPI_BIAS,false,false>
        <<<dim3(3*DD/128, ROWS/128, 1), 256>>>(
            hx, qkv_w, qkv_b, nullptr, qkv,
            DD, DD, DD, 3*DD, 1, 0,0, 0,0, 0,0);

    // 3. scores = Q K^T / 8 (lower-triangle tiles only)
    mma_gemm<128,true,EPI_SCALE,false,true>
        <<<dim3(SS/128, SS/128, BH), 256>>>(
            qkv, qkv + DD, nullptr, nullptr, sc,
            HDD, 3*DD, 3*DD, SS, HH,
            (long long)SS*3*DD, HDD,
            (long long)SS*3*DD, HDD,
            (long long)HH*SS*SS, (long long)SS*SS);

    // 4. causal-prefix softmax
    softmax_pfx<<<BH*SS, 256>>>(sc);

    // 5. O = P V   (V is [k][n] row-major: trans-ldmatrix path; causal K-limit)
    mma_gemm<64,false,EPI_BIAS,true,false>
        <<<dim3(1, SS/128, BH), 256>>>(
            sc, qkv + 2*DD, nullptr, nullptr, o,
            SS, SS, 3*DD, DD, HH,
            (long long)HH*SS*SS, (long long)SS*SS,
            (long long)SS*3*DD, HDD,
            (long long)SS*DD, HDD);

    // 6. x1 = x + O @ out_w^T + out_b
    mma_gemm<128,true,EPI_BIASRES,false,false>
        <<<dim3(DD/128, ROWS/128, 1), 256>>>(
            o, out_w, out_b, x, x1,
            DD, DD, DD, DD, 1, 0,0, 0,0, 0,0);

    // 7. ln2
    ln_kernel<<<ROWS, 256>>>(x1, ln2_w, ln2_b, h2);

    // 8. ff1 = gelu(h2 @ fc1_w^T + fc1_b)
    mma_gemm<128,true,EPI_GELU,false,false>
        <<<dim3(FF/128, ROWS/128, 1), 256>>>(
            h2, fc1_w, fc1_b, nullptr, ff1,
            DD, DD, DD, FF, 1, 0,0, 0,0, 0,0);

    // 9. out = x1 + ff1 @ fc2_w^T + fc2_b
    mma_gemm<128,true,EPI_BIASRES,false,false>
        <<<dim3(DD/128, ROWS/128, 1), 256>>>(
            ff1, fc2_w, fc2_b, x1, out,
            FF, FF, FF, DD, 1, 0,0, 0,0, 0,0);
}

// round 4
// speedup vs baseline: 2.3038x; 1.1549x over previous
#include <cuda_runtime.h>
#include <cuda_bf16.h>
#include <math.h>
#include <stdint.h>

typedef __nv_bfloat16 bf16;

// Problem constants
#define BB 2
#define SS 2048
#define DD 768
#define HH 12
#define FF 3072
#define HDD 64
#define ROWS (BB*SS)          // 4096
#define BH (BB*HH)            // 24

// -------------------- device scratch --------------------
// split-bf16 buffers: hi plane at [0], lo plane at [plane_elems]
__device__ __align__(16) bf16  g_hxs [2*ROWS*DD];
__device__ __align__(16) bf16  g_qkvs[2*ROWS*3*DD];
__device__ __align__(16) float g_sc  [(long long)BH*SS*SS];       // scores fp32 ~402MB
__device__ __align__(16) bf16  g_ps  [2*(long long)BH*SS*SS];     // probs split ~402MB
__device__ __align__(16) bf16  g_os  [2*ROWS*DD];
__device__ __align__(16) float g_x1  [ROWS*DD];
__device__ __align__(16) bf16  g_h2s [2*ROWS*DD];
__device__ __align__(16) bf16  g_ff1s[2*ROWS*FF];
__device__ __align__(16) bf16  g_qkvw[2*3*DD*DD];
__device__ __align__(16) bf16  g_outw[2*DD*DD];
__device__ __align__(16) bf16  g_fc1w[2*FF*DD];
__device__ __align__(16) bf16  g_fc2w[2*DD*FF];

// -------------------- helpers --------------------
__device__ __forceinline__ uint32_t smem_u32(const void* p){
    uint32_t a;
    asm("{ .reg .u64 t; cvta.to.shared.u64 t, %1; cvt.u32.u64 %0, t; }"
        : "=r"(a) : "l"(p));
    return a;
}
__device__ __forceinline__ void ldsm_x4(uint32_t* r, uint32_t a){
    asm volatile("ldmatrix.sync.aligned.m8n8.x4.shared.b16 {%0,%1,%2,%3}, [%4];"
        : "=r"(r[0]),"=r"(r[1]),"=r"(r[2]),"=r"(r[3]) : "r"(a));
}
__device__ __forceinline__ void ldsm_x4t(uint32_t* r, uint32_t a){
    asm volatile("ldmatrix.sync.aligned.m8n8.x4.trans.shared.b16 {%0,%1,%2,%3}, [%4];"
        : "=r"(r[0]),"=r"(r[1]),"=r"(r[2]),"=r"(r[3]) : "r"(a));
}
__device__ __forceinline__ void mma16816(float* c, const uint32_t* a, const uint32_t* b){
    asm volatile(
        "mma.sync.aligned.m16n8k16.row.col.f32.bf16.bf16.f32 "
        "{%0,%1,%2,%3}, {%4,%5,%6,%7}, {%8,%9}, {%0,%1,%2,%3};"
        : "+f"(c[0]),"+f"(c[1]),"+f"(c[2]),"+f"(c[3])
        : "r"(a[0]),"r"(a[1]),"r"(a[2]),"r"(a[3]), "r"(b[0]),"r"(b[1]));
}
#define CP_ASYNC16(dst, src) \
    asm volatile("cp.async.cg.shared.global [%0], [%1], 16;" :: "r"(dst), "l"(src))
#define CP_COMMIT() asm volatile("cp.async.commit_group;" ::: "memory")
#define CP_WAIT0()  asm volatile("cp.async.wait_group 0;" ::: "memory")

static __device__ __forceinline__ uint32_t pack2(bf16 a, bf16 b){
    return (uint32_t)__bfloat16_as_ushort(a) | ((uint32_t)__bfloat16_as_ushort(b) << 16);
}
static __device__ __forceinline__ void split4(const float4 v, uint2& hi, uint2& lo){
    bf16 h0 = __float2bfloat16(v.x), h1 = __float2bfloat16(v.y);
    bf16 h2 = __float2bfloat16(v.z), h3 = __float2bfloat16(v.w);
    bf16 l0 = __float2bfloat16(v.x - __bfloat162float(h0));
    bf16 l1 = __float2bfloat16(v.y - __bfloat162float(h1));
    bf16 l2 = __float2bfloat16(v.z - __bfloat162float(h2));
    bf16 l3 = __float2bfloat16(v.w - __bfloat162float(h3));
    hi = make_uint2(pack2(h0,h1), pack2(h2,h3));
    lo = make_uint2(pack2(l0,l1), pack2(l2,l3));
}

// -------------------- weight split convert --------------------
__global__ __launch_bounds__(256) void convertw(const float* __restrict__ w,
                                                bf16* __restrict__ hi, long long plane,
                                                int n4)
{
    int i = blockIdx.x * 256 + threadIdx.x;
    if (i >= n4) return;
    float4 v = reinterpret_cast<const float4*>(w)[i];
    uint2 h, l; split4(v, h, l);
    reinterpret_cast<uint2*>(hi)[i] = h;
    reinterpret_cast<uint2*>(hi + plane)[i] = l;
}

// -------------------- layernorm -> split bf16 planes --------------------
__global__ __launch_bounds__(256) void ln_split(const float* __restrict__ x,
                                                const float* __restrict__ w,
                                                const float* __restrict__ b,
                                                bf16* __restrict__ yh, long long plane)
{
    __shared__ float red[256];
    int tid = threadIdx.x;
    const float* xr = x + (size_t)blockIdx.x * DD;
    bf16* yrh = yh + (size_t)blockIdx.x * DD;
    bf16* yrl = yrh + plane;
    float v0 = xr[tid], v1 = xr[tid + 256], v2 = xr[tid + 512];
    red[tid] = v0 + v1 + v2;
    __syncthreads();
    for (int off = 128; off; off >>= 1) {
        if (tid < off) red[tid] += red[tid + off];
        __syncthreads();
    }
    float mean = red[0] * (1.0f / DD);
    __syncthreads();
    float d0 = v0 - mean, d1 = v1 - mean, d2 = v2 - mean;
    red[tid] = d0*d0 + d1*d1 + d2*d2;
    __syncthreads();
    for (int off = 128; off; off >>= 1) {
        if (tid < off) red[tid] += red[tid + off];
        __syncthreads();
    }
    float rstd = rsqrtf(red[0] * (1.0f / DD) + 1e-5f);
#pragma unroll
    for (int j = 0; j < 3; j++) {
        int c = tid + j * 256;
        float d = (j == 0) ? d0 : (j == 1) ? d1 : d2;
        float val = d * rstd * w[c] + b[c];
        bf16 h = __float2bfloat16(val);
        yrh[c] = h;
        yrl[c] = __float2bfloat16(val - __bfloat162float(h));
    }
}

// -------------------- causal softmax: fp32 scores -> split bf16 probs ----
__global__ __launch_bounds__(256) void softmax2(const float* __restrict__ sc,
                                                bf16* __restrict__ ph, long long plane)
{
    __shared__ float red[256];
    long long r = blockIdx.x;                 // bh*SS + i
    int i = (int)(r & (SS - 1));
    const float4* row4 = reinterpret_cast<const float4*>(sc + r * (long long)SS);
    bf16* oh = ph + r * (long long)SS;
    bf16* ol = oh + plane;
    int len  = i + 1;
    int wlen = ((i >> 7) + 1) << 7;
    int tid = threadIdx.x;

    float4 v[2];
    float mx = -1e30f;
#pragma unroll
    for (int j = 0; j < 2; j++) {
        int c = (tid + j * 256) * 4;
        if (c < len) {
            v[j] = row4[tid + j * 256];
            if (c + 1 >= len) v[j].y = -1e30f;
            if (c + 2 >= len) v[j].z = -1e30f;
            if (c + 3 >= len) v[j].w = -1e30f;
            mx = fmaxf(mx, fmaxf(fmaxf(v[j].x, v[j].y), fmaxf(v[j].z, v[j].w)));
        } else {
            v[j] = make_float4(-1e30f, -1e30f, -1e30f, -1e30f);
        }
    }
    red[tid] = mx;
    __syncthreads();
    for (int off = 128; off; off >>= 1) {
        if (tid < off) red[tid] = fmaxf(red[tid], red[tid + off]);
        __syncthreads();
    }
    mx = red[0];
    __syncthreads();
    float s = 0.f;
#pragma unroll
    for (int j = 0; j < 2; j++) {
        v[j].x = __expf(v[j].x - mx); v[j].y = __expf(v[j].y - mx);
        v[j].z = __expf(v[j].z - mx); v[j].w = __expf(v[j].w - mx);
        s += v[j].x + v[j].y + v[j].z + v[j].w;
    }
    red[tid] = s;
    __syncthreads();
    for (int off = 128; off; off >>= 1) {
        if (tid < off) red[tid] += red[tid + off];
        __syncthreads();
    }
    float inv = 1.0f / red[0];
#pragma unroll
    for (int j = 0; j < 2; j++) {
        int c4 = tid + j * 256;
        int c = c4 * 4;
        if (c < wlen) {
            float4 p = make_float4(v[j].x*inv, v[j].y*inv, v[j].z*inv, v[j].w*inv);
            uint2 h, l; split4(p, h, l);
            reinterpret_cast<uint2*>(oh)[c4] = h;
            reinterpret_cast<uint2*>(ol)[c4] = l;
        }
    }
}

// -------------------- split-bf16 warp-MMA GEMM, cp.async double-buffered -----
// C[m,n] = sum_k A[m,k]*B'[k,n]; operands are bf16 hi/lo planes in gmem.
//   !B_TRANS: B rows indexed by n, K-major ([n][k]) -> plain ldmatrix
//   B_TRANS : B is [k][n] row-major -> trans ldmatrix  (PV case)
enum { EPI_BIAS = 0, EPI_BIASRES = 1, EPI_GELU = 2, EPI_SCALE = 3 };

template<int BN, bool B_TRANS, int EPI, bool CAUSAL_K, bool CAUSAL_SKIP, bool OUT_SPLIT>
__global__ __launch_bounds__(256) void mma_gemm2(
    const bf16* __restrict__ A, const bf16* __restrict__ Bm,
    const float* __restrict__ bias, const float* __restrict__ resid,
    void* __restrict__ Cout,
    int K, int lda, int ldb, int ldc, int innerCount,
    long long planeA, long long planeB, long long planeC,
    long long sAo, long long sAi,
    long long sBo, long long sBi,
    long long sCo, long long sCi)
{
    constexpr int BM = 128, BK = 32;
    constexpr int ASTR = 80;                      // 64B row + 16B pad
    constexpr int APL  = BM * ASTR;               // 10240
    constexpr int BSTR = B_TRANS ? 144 : 80;
    constexpr int BPL  = B_TRANS ? BK * 144 : BN * 80;
    constexpr int BBASE = 2 * APL;                // 20480
    constexpr int BUF  = BBASE + 2 * BPL;
    constexpr int WM = (BN == 128) ? 64 : 32;
    constexpr int MF = WM / 16;
    constexpr int NF = 4;

    extern __shared__ __align__(128) char smem[];

    const int m0 = blockIdx.y * BM, n0 = blockIdx.x * BN;
    if (CAUSAL_SKIP && n0 > m0) return;

    int bz = blockIdx.z, bo = bz / innerCount, bi = bz % innerCount;
    A  += bo * sAo + bi * sAi;
    Bm += bo * sBo + bi * sBi;

    const int tid = threadIdx.x, wid = tid >> 5, lane = tid & 31;
    const int wm0 = (BN == 128) ? (wid & 1) * 64 : (wid & 3) * 32;
    const int wn0 = (BN == 128) ? (wid >> 1) * 32 : (wid >> 2) * 32;
    const uint32_t sb = smem_u32(smem);

    float acc[MF][NF][4];
#pragma unroll
    for (int i = 0; i < MF; i++)
#pragma unroll
        for (int j = 0; j < NF; j++)
#pragma unroll
            for (int c = 0; c < 4; c++) acc[i][j][c] = 0.f;

    int NT = K / BK;
    if (CAUSAL_K) { int km = m0 + BM; if (km < K) NT = km / BK; }

    const bf16* Alo = A + planeA;
    const bf16* Blo = Bm + planeB;

    auto load_tile = [&](int kt, int b) {
        uint32_t base = sb + b * BUF;
        // A: 2 planes x 128 rows x 4 chunks of 16B
#pragma unroll
        for (int it = 0; it < 4; it++) {
            int idx = tid + it * 256;
            int p = idx >> 9, rem = idx & 511, r = rem >> 2, c = rem & 3;
            const bf16* src = (p ? Alo : A) + (size_t)(m0 + r) * lda + kt * BK + c * 8;
            CP_ASYNC16(base + p * APL + r * ASTR + c * 16, src);
        }
        if (!B_TRANS) {
#pragma unroll
            for (int it = 0; it < (BN == 128 ? 4 : 2); it++) {
                int idx = tid + it * 256;
                int p, rem;
                if (BN == 128) { p = idx >> 9; rem = idx & 511; }
                else           { p = idx >> 8; rem = idx & 255; }
                int r = rem >> 2, c = rem & 3;
                const bf16* src = (p ? Blo : Bm) + (size_t)(n0 + r) * ldb + kt * BK + c * 8;
                CP_ASYNC16(base + BBASE + p * BPL + r * BSTR + c * 16, src);
            }
        } else {
            // B tile: 32 rows (k) x 64 cols (n), 8 chunks per row
#pragma unroll
            for (int it = 0; it < 2; it++) {
                int idx = tid + it * 256;
                int p = idx >> 8, rem = idx & 255, r = rem >> 3, c = rem & 7;
                const bf16* src = (p ? Blo : Bm) + (size_t)(kt * BK + r) * ldb + n0 + c * 8;
                CP_ASYNC16(base + BBASE + p * BPL + r * BSTR + c * 16, src);
            }
        }
        CP_COMMIT();
    };

    load_tile(0, 0);

    for (int kt = 0; kt < NT; kt++) {
        int buf = kt & 1;
        CP_WAIT0();
        __syncthreads();
        if (kt + 1 < NT) load_tile(kt + 1, buf ^ 1);

        uint32_t base = sb + buf * BUF;
#pragma unroll
        for (int ks = 0; ks < 2; ks++) {
            uint32_t bH[NF][2], bL[NF][2];
            if (!B_TRANS) {
#pragma unroll
                for (int h = 0; h < 2; h++) {
                    uint32_t row = wn0 + h * 16 + (lane & 7) + ((lane >> 4) << 3);
                    uint32_t ch  = (lane >> 3) & 1;
                    uint32_t ad  = base + BBASE + row * BSTR + ks * 32 + ch * 16;
                    uint32_t r4[4];
                    ldsm_x4(r4, ad);
                    bH[h*2][0]=r4[0]; bH[h*2][1]=r4[1]; bH[h*2+1][0]=r4[2]; bH[h*2+1][1]=r4[3];
                    ldsm_x4(r4, ad + BPL);
                    bL[h*2][0]=r4[0]; bL[h*2][1]=r4[1]; bL[h*2+1][0]=r4[2]; bL[h*2+1][1]=r4[3];
                }
            } else {
#pragma unroll
                for (int h = 0; h < 2; h++) {
                    uint32_t row = ks * 16 + (lane & 7) + (((lane >> 3) & 1) << 3);
                    uint32_t col = wn0 + h * 16 + ((lane >> 4) << 3);
                    uint32_t ad  = base + BBASE + row * BSTR + col * 2;
                    uint32_t r4[4];
                    ldsm_x4t(r4, ad);
                    bH[h*2][0]=r4[0]; bH[h*2][1]=r4[1]; bH[h*2+1][0]=r4[2]; bH[h*2+1][1]=r4[3];
                    ldsm_x4t(r4, ad + BPL);
                    bL[h*2][0]=r4[0]; bL[h*2][1]=r4[1]; bL[h*2+1][0]=r4[2]; bL[h*2+1][1]=r4[3];
                }
            }
#pragma unroll
            for (int mf = 0; mf < MF; mf++) {
                uint32_t row = wm0 + mf * 16 + (lane & 15);
                uint32_t ch  = lane >> 4;
                uint32_t ad  = base + row * ASTR + ks * 32 + ch * 16;
                uint32_t aH[4], aL[4];
                ldsm_x4(aH, ad);
                ldsm_x4(aL, ad + APL);
#pragma unroll
                for (int nf = 0; nf < NF; nf++) {
                    mma16816(acc[mf][nf], aH, bH[nf]);
                    mma16816(acc[mf][nf], aH, bL[nf]);
                    mma16816(acc[mf][nf], aL, bH[nf]);
                }
            }
        }
        __syncthreads();
    }

    // -------- epilogue --------
    long long cOff = (long long)bo * sCo + (long long)bi * sCi;
#pragma unroll
    for (int mf = 0; mf < MF; mf++) {
#pragma unroll
        for (int half = 0; half < 2; half++) {
            int m = m0 + wm0 + mf * 16 + (lane >> 2) + half * 8;
#pragma unroll
            for (int nf = 0; nf < NF; nf++) {
                int n = n0 + wn0 + nf * 8 + (lane & 3) * 2;
                float v0 = acc[mf][nf][half*2 + 0];
                float v1 = acc[mf][nf][half*2 + 1];
                if (EPI == EPI_SCALE) {
                    v0 *= 0.125f; v1 *= 0.125f;
                } else {
                    if (bias) { v0 += __ldg(&bias[n]); v1 += __ldg(&bias[n+1]); }
                    if (EPI == EPI_GELU) {
                        v0 = 0.5f * v0 * (1.0f + erff(v0 * 0.70710678118654752f));
                        v1 = 0.5f * v1 * (1.0f + erff(v1 * 0.70710678118654752f));
                    }
                    if (EPI == EPI_BIASRES) {
                        const float* Rrow = resid + cOff + (size_t)m * ldc;
                        v0 += Rrow[n]; v1 += Rrow[n+1];
                    }
                }
                if (OUT_SPLIT) {
                    bf16* Ch = (bf16*)Cout + cOff + (size_t)m * ldc;
                    bf16 h0 = __float2bfloat16(v0), h1 = __float2bfloat16(v1);
                    bf16 l0 = __float2bfloat16(v0 - __bfloat162float(h0));
                    bf16 l1 = __float2bfloat16(v1 - __bfloat162float(h1));
                    *reinterpret_cast<uint32_t*>(Ch + n)          = pack2(h0, h1);
                    *reinterpret_cast<uint32_t*>(Ch + planeC + n) = pack2(l0, l1);
                } else {
                    float* Crow = (float*)Cout + cOff + (size_t)m * ldc;
                    *reinterpret_cast<float2*>(Crow + n) = make_float2(v0, v1);
                }
            }
        }
    }
}

// -------------------- host launcher --------------------
extern "C" void kernel_launch(void* const* d_in, const int* in_sizes, int n_in,
                              void* d_out, int out_size)
{
    const float* x     = (const float*)d_in[0];
    const float* qkv_w = (const float*)d_in[2];
    const float* qkv_b = (const float*)d_in[3];
    const float* out_w = (const float*)d_in[4];
    const float* out_b = (const float*)d_in[5];
    const float* fc1_w = (const float*)d_in[6];
    const float* fc1_b = (const float*)d_in[7];
    const float* fc2_w = (const float*)d_in[8];
    const float* fc2_b = (const float*)d_in[9];
    const float* ln1_w = (const float*)d_in[10];
    const float* ln1_b = (const float*)d_in[11];
    const float* ln2_w = (const float*)d_in[12];
    const float* ln2_b = (const float*)d_in[13];
    float* out = (float*)d_out;

    void *p0,*p1,*p2,*p3,*p4,*p5,*p6,*p7,*p8,*p9,*p10,*p11;
    cudaGetSymbolAddress(&p0,  g_hxs);
    cudaGetSymbolAddress(&p1,  g_qkvs);
    cudaGetSymbolAddress(&p2,  g_sc);
    cudaGetSymbolAddress(&p3,  g_ps);
    cudaGetSymbolAddress(&p4,  g_os);
    cudaGetSymbolAddress(&p5,  g_x1);
    cudaGetSymbolAddress(&p6,  g_h2s);
    cudaGetSymbolAddress(&p7,  g_ff1s);
    cudaGetSymbolAddress(&p8,  g_qkvw);
    cudaGetSymbolAddress(&p9,  g_outw);
    cudaGetSymbolAddress(&p10, g_fc1w);
    cudaGetSymbolAddress(&p11, g_fc2w);
    bf16* hxs  = (bf16*)p0;  bf16* qkvs = (bf16*)p1;
    float* sc  = (float*)p2; bf16* ps   = (bf16*)p3;
    bf16* os   = (bf16*)p4;  float* x1  = (float*)p5;
    bf16* h2s  = (bf16*)p6;  bf16* ff1s = (bf16*)p7;
    bf16* qkvw = (bf16*)p8;  bf16* outw = (bf16*)p9;
    bf16* fc1w = (bf16*)p10; bf16* fc2w = (bf16*)p11;

    const int SMEM_N128 = 2 * (20480 + 20480);   // 81920
    const int SMEM_PV   = 2 * (20480 + 2*4608);  // 59392

    cudaFuncSetAttribute(mma_gemm2<128,false,EPI_BIAS,   false,false,true >,
                         cudaFuncAttributeMaxDynamicSharedMemorySize, SMEM_N128);
    cudaFuncSetAttribute(mma_gemm2<128,false,EPI_SCALE,  false,true ,false>,
                         cudaFuncAttributeMaxDynamicSharedMemorySize, SMEM_N128);
    cudaFuncSetAttribute(mma_gemm2<64, true, EPI_BIAS,   true ,false,true >,
                         cudaFuncAttributeMaxDynamicSharedMemorySize, SMEM_PV);
    cudaFuncSetAttribute(mma_gemm2<128,false,EPI_BIASRES,false,false,false>,
                         cudaFuncAttributeMaxDynamicSharedMemorySize, SMEM_N128);
    cudaFuncSetAttribute(mma_gemm2<128,false,EPI_GELU,   false,false,true >,
                         cudaFuncAttributeMaxDynamicSharedMemorySize, SMEM_N128);

    // 0. weight splits
    convertw<<<(3*DD*DD/4 + 255)/256, 256>>>(qkv_w, qkvw, (long long)3*DD*DD, 3*DD*DD/4);
    convertw<<<(DD*DD/4   + 255)/256, 256>>>(out_w, outw, (long long)DD*DD,   DD*DD/4);
    convertw<<<(FF*DD/4   + 255)/256, 256>>>(fc1_w, fc1w, (long long)FF*DD,   FF*DD/4);
    convertw<<<(DD*FF/4   + 255)/256, 256>>>(fc2_w, fc2w, (long long)DD*FF,   DD*FF/4);

    // 1. ln1 -> hx split
    ln_split<<<ROWS, 256>>>(x, ln1_w, ln1_b, hxs, (long long)ROWS*DD);

    // 2. QKV: [4096,768] x [2304,768]^T -> qkv split planes
    mma_gemm2<128,false,EPI_BIAS,false,false,true>
        <<<dim3(3*DD/128, ROWS/128, 1), 256, SMEM_N128>>>(
            hxs, qkvw, qkv_b, nullptr, qkvs,
            DD, DD, DD, 3*DD, 1,
            (long long)ROWS*DD, (long long)3*DD*DD, (long long)ROWS*3*DD,
            0,0, 0,0, 0,0);

    // 3. scores = Q K^T / 8 (lower-triangle tiles only), fp32
    mma_gemm2<128,false,EPI_SCALE,false,true,false>
        <<<dim3(SS/128, SS/128, BH), 256, SMEM_N128>>>(
            qkvs, qkvs + DD, nullptr, nullptr, sc,
            HDD, 3*DD, 3*DD, SS, HH,
            (long long)ROWS*3*DD, (long long)ROWS*3*DD, 0,
            (long long)SS*3*DD, HDD,
            (long long)SS*3*DD, HDD,
            (long long)HH*SS*SS, (long long)SS*SS);

    // 4. causal softmax -> P split planes
    softmax2<<<BH*SS, 256>>>(sc, ps, (long long)BH*SS*SS);

    // 5. O = P V  (V is [k][n]: trans path; causal K-limit) -> o split planes
    mma_gemm2<64,true,EPI_BIAS,true,false,true>
        <<<dim3(1, SS/128, BH), 256, SMEM_PV>>>(
            ps, qkvs + 2*DD, nullptr, nullptr, os,
            SS, SS, 3*DD, DD, HH,
            (long long)BH*SS*SS, (long long)ROWS*3*DD, (long long)ROWS*DD,
            (long long)HH*SS*SS, (long long)SS*SS,
            (long long)SS*3*DD, HDD,
            (long long)SS*DD, HDD);

    // 6. x1 = x + O @ out_w^T + out_b   (fp32 out)
    mma_gemm2<128,false,EPI_BIASRES,false,false,false>
        <<<dim3(DD/128, ROWS/128, 1), 256, SMEM_N128>>>(
            os, outw, out_b, x, x1,
            DD, DD, DD, DD, 1,
            (long long)ROWS*DD, (long long)DD*DD, 0,
            0,0, 0,0, 0,0);

    // 7. ln2 -> h2 split
    ln_split<<<ROWS, 256>>>(x1, ln2_w, ln2_b, h2s, (long long)ROWS*DD);

    // 8. ff1 = gelu(h2 @ fc1_w^T + fc1_b) -> split planes
    mma_gemm2<128,false,EPI_GELU,false,false,true>
        <<<dim3(FF/128, ROWS/128, 1), 256, SMEM_N128>>>(
            h2s, fc1w, fc1_b, nullptr, ff1s,
            DD, DD, DD, FF, 1,
            (long long)ROWS*DD, (long long)FF*DD, (long long)ROWS*FF,
            0,0, 0,0, 0,0);

    // 9. out = x1 + ff1 @ fc2_w^T + fc2_b   (fp32 out)
    mma_gemm2<128,false,EPI_BIASRES,false,false,false>
        <<<dim3(DD/128, ROWS/128, 1), 256, SMEM_N128>>>(
            ff1s, fc2w, fc2_b, x1, out,
            FF, FF, FF, DD, 1,
            (long long)ROWS*FF, (long long)DD*FF, 0,
            0,0, 0,0, 0,0);
}

// round 7
// speedup vs baseline: 2.9549x; 1.2826x over previous
#include <cuda_runtime.h>
#include <cuda_bf16.h>
#include <math.h>
#include <stdint.h>

typedef __nv_bfloat16 bf16;

// Problem constants
#define BB 2
#define SS 2048
#define DD 768
#define HH 12
#define FF 3072
#define HDD 64
#define ROWS (BB*SS)          // 4096
#define BH (BB*HH)            // 24

// -------------------- device scratch --------------------
// split-bf16 buffers: hi plane at [0], lo plane at [plane_elems]
__device__ __align__(16) bf16  g_hxs [2*ROWS*DD];
__device__ __align__(16) bf16  g_qkvs[2*ROWS*3*DD];
__device__ __align__(16) bf16  g_os  [2*ROWS*DD];
__device__ __align__(16) float g_x1  [ROWS*DD];
__device__ __align__(16) bf16  g_h2s [2*ROWS*DD];
__device__ __align__(16) bf16  g_ff1s[2*ROWS*FF];
__device__ __align__(16) bf16  g_qkvw[2*3*DD*DD];
__device__ __align__(16) bf16  g_outw[2*DD*DD];
__device__ __align__(16) bf16  g_fc1w[2*FF*DD];
__device__ __align__(16) bf16  g_fc2w[2*DD*FF];

// -------------------- helpers --------------------
__device__ __forceinline__ uint32_t smem_u32(const void* p){
    uint32_t a;
    asm("{ .reg .u64 t; cvta.to.shared.u64 t, %1; cvt.u32.u64 %0, t; }"
        : "=r"(a) : "l"(p));
    return a;
}
__device__ __forceinline__ void ldsm_x4(uint32_t* r, uint32_t a){
    asm volatile("ldmatrix.sync.aligned.m8n8.x4.shared.b16 {%0,%1,%2,%3}, [%4];"
        : "=r"(r[0]),"=r"(r[1]),"=r"(r[2]),"=r"(r[3]) : "r"(a));
}
__device__ __forceinline__ void ldsm_x4t(uint32_t* r, uint32_t a){
    asm volatile("ldmatrix.sync.aligned.m8n8.x4.trans.shared.b16 {%0,%1,%2,%3}, [%4];"
        : "=r"(r[0]),"=r"(r[1]),"=r"(r[2]),"=r"(r[3]) : "r"(a));
}
__device__ __forceinline__ void mma16816(float* c, const uint32_t* a, const uint32_t* b){
    asm volatile(
        "mma.sync.aligned.m16n8k16.row.col.f32.bf16.bf16.f32 "
        "{%0,%1,%2,%3}, {%4,%5,%6,%7}, {%8,%9}, {%0,%1,%2,%3};"
        : "+f"(c[0]),"+f"(c[1]),"+f"(c[2]),"+f"(c[3])
        : "r"(a[0]),"r"(a[1]),"r"(a[2]),"r"(a[3]), "r"(b[0]),"r"(b[1]));
}
#define CP_ASYNC16(dst, src) \
    asm volatile("cp.async.cg.shared.global [%0], [%1], 16;" :: "r"(dst), "l"(src))
#define CP_COMMIT() asm volatile("cp.async.commit_group;" ::: "memory")
#define CP_WAIT0()  asm volatile("cp.async.wait_group 0;" ::: "memory")
#define CP_WAIT1()  asm volatile("cp.async.wait_group 1;" ::: "memory")

static __device__ __forceinline__ uint32_t pack2(bf16 a, bf16 b){
    return (uint32_t)__bfloat16_as_ushort(a) | ((uint32_t)__bfloat16_as_ushort(b) << 16);
}
static __device__ __forceinline__ void split4(const float4 v, uint2& hi, uint2& lo){
    bf16 h0 = __float2bfloat16(v.x), h1 = __float2bfloat16(v.y);
    bf16 h2 = __float2bfloat16(v.z), h3 = __float2bfloat16(v.w);
    bf16 l0 = __float2bfloat16(v.x - __bfloat162float(h0));
    bf16 l1 = __float2bfloat16(v.y - __bfloat162float(h1));
    bf16 l2 = __float2bfloat16(v.z - __bfloat162float(h2));
    bf16 l3 = __float2bfloat16(v.w - __bfloat162float(h3));
    hi = make_uint2(pack2(h0,h1), pack2(h2,h3));
    lo = make_uint2(pack2(l0,l1), pack2(l2,l3));
}

// -------------------- weight split convert --------------------
__global__ __launch_bounds__(256) void convertw(const float* __restrict__ w,
                                                bf16* __restrict__ hi, long long plane,
                                                int n4)
{
    int i = blockIdx.x * 256 + threadIdx.x;
    if (i >= n4) return;
    float4 v = reinterpret_cast<const float4*>(w)[i];
    uint2 h, l; split4(v, h, l);
    reinterpret_cast<uint2*>(hi)[i] = h;
    reinterpret_cast<uint2*>(hi + plane)[i] = l;
}

// -------------------- layernorm -> split bf16 planes --------------------
__global__ __launch_bounds__(256) void ln_split(const float* __restrict__ x,
                                                const float* __restrict__ w,
                                                const float* __restrict__ b,
                                                bf16* __restrict__ yh, long long plane)
{
    __shared__ float red[256];
    int tid = threadIdx.x;
    const float* xr = x + (size_t)blockIdx.x * DD;
    bf16* yrh = yh + (size_t)blockIdx.x * DD;
    bf16* yrl = yrh + plane;
    float v0 = xr[tid], v1 = xr[tid + 256], v2 = xr[tid + 512];
    red[tid] = v0 + v1 + v2;
    __syncthreads();
    for (int off = 128; off; off >>= 1) {
        if (tid < off) red[tid] += red[tid + off];
        __syncthreads();
    }
    float mean = red[0] * (1.0f / DD);
    __syncthreads();
    float d0 = v0 - mean, d1 = v1 - mean, d2 = v2 - mean;
    red[tid] = d0*d0 + d1*d1 + d2*d2;
    __syncthreads();
    for (int off = 128; off; off >>= 1) {
        if (tid < off) red[tid] += red[tid + off];
        __syncthreads();
    }
    float rstd = rsqrtf(red[0] * (1.0f / DD) + 1e-5f);
#pragma unroll
    for (int j = 0; j < 3; j++) {
        int c = tid + j * 256;
        float d = (j == 0) ? d0 : (j == 1) ? d1 : d2;
        float val = d * rstd * w[c] + b[c];
        bf16 h = __float2bfloat16(val);
        yrh[c] = h;
        yrl[c] = __float2bfloat16(val - __bfloat162float(h));
    }
}

// -------------------- flash attention (split-bf16, causal) --------------------
// Grid: (SS/128 q-tiles, BH). 8 warps, each owns 16 q-rows x full 128-col KV tile.
// SMEM: Q[2 planes][128][64], K same, V same; stride 144B/row.
__global__ __launch_bounds__(256) void flash_attn(
    const bf16* __restrict__ qkvs, long long planeQKV,
    bf16* __restrict__ os, long long planeO)
{
    constexpr int STR = 144;
    constexpr int PL  = 128 * STR;       // 18432 per plane
    extern __shared__ __align__(128) char smem[];
    // Q: [0, 2PL)  K: [2PL, 4PL)  V: [4PL, 6PL)

    const int qt = blockIdx.x, bh = blockIdx.y;
    const int b = bh / HH, h = bh % HH;
    const int tid = threadIdx.x, wid = tid >> 5, lane = tid & 31;
    const uint32_t sb = smem_u32(smem);

    const bf16* Qb = qkvs + (size_t)(b * SS + qt * 128) * (3 * DD) + h * HDD;
    const bf16* Kb = qkvs + (size_t)(b * SS) * (3 * DD) + DD + h * HDD;
    const bf16* Vb = Kb + DD;

    auto loadQ = [&]() {
#pragma unroll
        for (int it = 0; it < 8; it++) {
            int idx = tid + it * 256;
            int p = idx >> 10, rem = idx & 1023, r = rem >> 3, c = rem & 7;
            CP_ASYNC16(sb + p * PL + r * STR + c * 16,
                       Qb + p * planeQKV + (size_t)r * (3 * DD) + c * 8);
        }
        CP_COMMIT();
    };
    auto loadK = [&](int j) {
#pragma unroll
        for (int it = 0; it < 8; it++) {
            int idx = tid + it * 256;
            int p = idx >> 10, rem = idx & 1023, r = rem >> 3, c = rem & 7;
            CP_ASYNC16(sb + 2 * PL + p * PL + r * STR + c * 16,
                       Kb + p * planeQKV + (size_t)(j * 128 + r) * (3 * DD) + c * 8);
        }
        CP_COMMIT();
    };
    auto loadV = [&](int j) {
#pragma unroll
        for (int it = 0; it < 8; it++) {
            int idx = tid + it * 256;
            int p = idx >> 10, rem = idx & 1023, r = rem >> 3, c = rem & 7;
            CP_ASYNC16(sb + 4 * PL + p * PL + r * STR + c * 16,
                       Vb + p * planeQKV + (size_t)(j * 128 + r) * (3 * DD) + c * 8);
        }
        CP_COMMIT();
    };

    loadQ();
    loadK(0);
    loadV(0);

    // softmax state: each thread handles rows r0 = wid*16 + lane>>2, r1 = r0+8
    float mo0 = -1e30f, mo1 = -1e30f;
    float l0 = 0.f, l1 = 0.f;
    float oacc[8][4];
#pragma unroll
    for (int f = 0; f < 8; f++)
#pragma unroll
        for (int c = 0; c < 4; c++) oacc[f][c] = 0.f;

    const float SCL = 0.125f * 1.4426950408889634f;  // 1/sqrt(64) * log2(e)

    for (int j = 0; j <= qt; j++) {
        CP_WAIT1();            // Q (first iter) + K_j arrived
        __syncthreads();

        // ---- S = Q K^T ----
        float sacc[16][4];
#pragma unroll
        for (int f = 0; f < 16; f++)
#pragma unroll
            for (int c = 0; c < 4; c++) sacc[f][c] = 0.f;

#pragma unroll
        for (int ks = 0; ks < 4; ks++) {
            uint32_t aH[4], aL[4];
            uint32_t qaddr = sb + (wid * 16 + (lane & 15)) * STR + ks * 32 + ((lane >> 4) << 4);
            ldsm_x4(aH, qaddr);
            ldsm_x4(aL, qaddr + PL);
#pragma unroll
            for (int h8 = 0; h8 < 8; h8++) {
                uint32_t row = h8 * 16 + (lane & 7) + ((lane >> 4) << 3);
                uint32_t ch  = (lane >> 3) & 1;
                uint32_t ka  = sb + 2 * PL + row * STR + ks * 32 + ch * 16;
                uint32_t bHk[4], bLk[4];
                ldsm_x4(bHk, ka);
                ldsm_x4(bLk, ka + PL);
                mma16816(sacc[2*h8],   aH, bHk);
                mma16816(sacc[2*h8],   aH, bLk);
                mma16816(sacc[2*h8],   aL, bHk);
                mma16816(sacc[2*h8+1], aH, bHk + 2);
                mma16816(sacc[2*h8+1], aH, bLk + 2);
                mma16816(sacc[2*h8+1], aL, bHk + 2);
            }
        }

        // ---- online softmax (log2 domain) ----
        const bool diag = (j == qt);
        int rl0 = wid * 16 + (lane >> 2), rl1 = rl0 + 8;
        float mn0 = mo0, mn1 = mo1;
#pragma unroll
        for (int f = 0; f < 16; f++) {
            int cl = f * 8 + (lane & 3) * 2;
            float t0 = sacc[f][0] * SCL, t1 = sacc[f][1] * SCL;
            float t2 = sacc[f][2] * SCL, t3 = sacc[f][3] * SCL;
            if (diag) {
                if (cl     > rl0) t0 = -1e30f;
                if (cl + 1 > rl0) t1 = -1e30f;
                if (cl     > rl1) t2 = -1e30f;
                if (cl + 1 > rl1) t3 = -1e30f;
            }
            sacc[f][0] = t0; sacc[f][1] = t1; sacc[f][2] = t2; sacc[f][3] = t3;
            mn0 = fmaxf(mn0, fmaxf(t0, t1));
            mn1 = fmaxf(mn1, fmaxf(t2, t3));
        }
        mn0 = fmaxf(mn0, __shfl_xor_sync(0xffffffffu, mn0, 1));
        mn0 = fmaxf(mn0, __shfl_xor_sync(0xffffffffu, mn0, 2));
        mn1 = fmaxf(mn1, __shfl_xor_sync(0xffffffffu, mn1, 1));
        mn1 = fmaxf(mn1, __shfl_xor_sync(0xffffffffu, mn1, 2));

        float f0 = exp2f(mo0 - mn0), f1 = exp2f(mo1 - mn1);
        l0 *= f0; l1 *= f1;
#pragma unroll
        for (int f = 0; f < 8; f++) {
            oacc[f][0] *= f0; oacc[f][1] *= f0;
            oacc[f][2] *= f1; oacc[f][3] *= f1;
        }
        float s0 = 0.f, s1 = 0.f;
#pragma unroll
        for (int f = 0; f < 16; f++) {
            float p0 = exp2f(sacc[f][0] - mn0);
            float p1 = exp2f(sacc[f][1] - mn0);
            float p2 = exp2f(sacc[f][2] - mn1);
            float p3 = exp2f(sacc[f][3] - mn1);
            sacc[f][0] = p0; sacc[f][1] = p1; sacc[f][2] = p2; sacc[f][3] = p3;
            s0 += p0 + p1; s1 += p2 + p3;
        }
        // CRITICAL: reduce row-sum across the 4-lane quad (was missing -> 0*inf=NaN
        // on rows whose valid columns fall outside a lane's fragment).
        s0 += __shfl_xor_sync(0xffffffffu, s0, 1);
        s0 += __shfl_xor_sync(0xffffffffu, s0, 2);
        s1 += __shfl_xor_sync(0xffffffffu, s1, 1);
        s1 += __shfl_xor_sync(0xffffffffu, s1, 2);
        l0 += s0; l1 += s1;
        mo0 = mn0; mo1 = mn1;

        // all warps done with K_j -> prefetch K_{j+1}, then make sure V_j landed.
        __syncthreads();
        if (j < qt) {
            loadK(j + 1);
            CP_WAIT1();        // completes V_j (K_{j+1} may stay in flight)
        } else {
            CP_WAIT0();        // last tile: drain queue so V_j is guaranteed
        }
        __syncthreads();

        // ---- O += P V ----
#pragma unroll
        for (int kk = 0; kk < 8; kk++) {
            uint32_t aH[4], aL[4];
#pragma unroll
            for (int half = 0; half < 2; half++) {
                const float* pr = sacc[2*kk + half];
                bf16 h0 = __float2bfloat16(pr[0]), h1 = __float2bfloat16(pr[1]);
                bf16 h2 = __float2bfloat16(pr[2]), h3 = __float2bfloat16(pr[3]);
                aH[half*2 + 0] = pack2(h0, h1);
                aH[half*2 + 1] = pack2(h2, h3);
                bf16 e0 = __float2bfloat16(pr[0] - __bfloat162float(h0));
                bf16 e1 = __float2bfloat16(pr[1] - __bfloat162float(h1));
                bf16 e2 = __float2bfloat16(pr[2] - __bfloat162float(h2));
                bf16 e3 = __float2bfloat16(pr[3] - __bfloat162float(h3));
                aL[half*2 + 0] = pack2(e0, e1);
                aL[half*2 + 1] = pack2(e2, e3);
            }
#pragma unroll
            for (int h4 = 0; h4 < 4; h4++) {
                uint32_t row = kk * 16 + (lane & 7) + (((lane >> 3) & 1) << 3);
                uint32_t col = h4 * 16 + ((lane >> 4) << 3);
                uint32_t va  = sb + 4 * PL + row * STR + col * 2;
                uint32_t bHv[4], bLv[4];
                ldsm_x4t(bHv, va);
                ldsm_x4t(bLv, va + PL);
                mma16816(oacc[2*h4],   aH, bHv);
                mma16816(oacc[2*h4],   aH, bLv);
                mma16816(oacc[2*h4],   aL, bHv);
                mma16816(oacc[2*h4+1], aH, bHv + 2);
                mma16816(oacc[2*h4+1], aH, bLv + 2);
                mma16816(oacc[2*h4+1], aL, bHv + 2);
            }
        }
        __syncthreads();
        if (j < qt) loadV(j + 1);
    }

    // ---- epilogue: O /= l, write split planes ----
    float li0 = 1.0f / l0, li1 = 1.0f / l1;
    int m0r = b * SS + qt * 128 + wid * 16 + (lane >> 2);
    bf16* oh = os + (size_t)m0r * DD + h * HDD;
#pragma unroll
    for (int f = 0; f < 8; f++) {
        int n = f * 8 + (lane & 3) * 2;
        float v0 = oacc[f][0] * li0, v1 = oacc[f][1] * li0;
        float v2 = oacc[f][2] * li1, v3 = oacc[f][3] * li1;
        bf16 h0 = __float2bfloat16(v0), h1 = __float2bfloat16(v1);
        bf16 h2 = __float2bfloat16(v2), h3 = __float2bfloat16(v3);
        *reinterpret_cast<uint32_t*>(oh + n)                    = pack2(h0, h1);
        *reinterpret_cast<uint32_t*>(oh + 8 * DD + n)           = pack2(h2, h3);
        bf16 e0 = __float2bfloat16(v0 - __bfloat162float(h0));
        bf16 e1 = __float2bfloat16(v1 - __bfloat162float(h1));
        bf16 e2 = __float2bfloat16(v2 - __bfloat162float(h2));
        bf16 e3 = __float2bfloat16(v3 - __bfloat162float(h3));
        *reinterpret_cast<uint32_t*>(oh + planeO + n)           = pack2(e0, e1);
        *reinterpret_cast<uint32_t*>(oh + planeO + 8 * DD + n)  = pack2(e2, e3);
    }
}

// -------------------- split-bf16 warp-MMA GEMM, cp.async double-buffered -----
enum { EPI_BIAS = 0, EPI_BIASRES = 1, EPI_GELU = 2 };

template<int BN, int EPI, bool OUT_SPLIT>
__global__ __launch_bounds__(256) void mma_gemm2(
    const bf16* __restrict__ A, const bf16* __restrict__ Bm,
    const float* __restrict__ bias, const float* __restrict__ resid,
    void* __restrict__ Cout,
    int K, int lda, int ldb, int ldc,
    long long planeA, long long planeB, long long planeC)
{
    constexpr int BM = 128, BK = 32;
    constexpr int ASTR = 80;
    constexpr int APL  = BM * ASTR;
    constexpr int BSTR = 80;
    constexpr int BPL  = BN * 80;
    constexpr int BBASE = 2 * APL;
    constexpr int BUF  = BBASE + 2 * BPL;
    constexpr int MF = 4, NF = 4;

    extern __shared__ __align__(128) char smem[];

    const int m0 = blockIdx.y * BM, n0 = blockIdx.x * BN;
    const int tid = threadIdx.x, wid = tid >> 5, lane = tid & 31;
    const int wm0 = (wid & 1) * 64;
    const int wn0 = (wid >> 1) * 32;
    const uint32_t sb = smem_u32(smem);

    float acc[MF][NF][4];
#pragma unroll
    for (int i = 0; i < MF; i++)
#pragma unroll
        for (int jj = 0; jj < NF; jj++)
#pragma unroll
            for (int c = 0; c < 4; c++) acc[i][jj][c] = 0.f;

    int NT = K / BK;
    const bf16* Alo = A + planeA;
    const bf16* Blo = Bm + planeB;

    auto load_tile = [&](int kt, int bsel) {
        uint32_t base = sb + bsel * BUF;
#pragma unroll
        for (int it = 0; it < 4; it++) {
            int idx = tid + it * 256;
            int p = idx >> 9, rem = idx & 511, r = rem >> 2, c = rem & 3;
            const bf16* src = (p ? Alo : A) + (size_t)(m0 + r) * lda + kt * BK + c * 8;
            CP_ASYNC16(base + p * APL + r * ASTR + c * 16, src);
        }
#pragma unroll
        for (int it = 0; it < 4; it++) {
            int idx = tid + it * 256;
            int p = idx >> 9, rem = idx & 511, r = rem >> 2, c = rem & 3;
            const bf16* src = (p ? Blo : Bm) + (size_t)(n0 + r) * ldb + kt * BK + c * 8;
            CP_ASYNC16(base + BBASE + p * BPL + r * BSTR + c * 16, src);
        }
        CP_COMMIT();
    };

    load_tile(0, 0);

    for (int kt = 0; kt < NT; kt++) {
        int buf = kt & 1;
        CP_WAIT0();
        __syncthreads();
        if (kt + 1 < NT) load_tile(kt + 1, buf ^ 1);

        uint32_t base = sb + buf * BUF;
#pragma unroll
        for (int ks = 0; ks < 2; ks++) {
            uint32_t bH[NF][2], bL[NF][2];
#pragma unroll
            for (int hh = 0; hh < 2; hh++) {
                uint32_t row = wn0 + hh * 16 + (lane & 7) + ((lane >> 4) << 3);
                uint32_t ch  = (lane >> 3) & 1;
                uint32_t ad  = base + BBASE + row * BSTR + ks * 32 + ch * 16;
                uint32_t r4[4];
                ldsm_x4(r4, ad);
                bH[hh*2][0]=r4[0]; bH[hh*2][1]=r4[1]; bH[hh*2+1][0]=r4[2]; bH[hh*2+1][1]=r4[3];
                ldsm_x4(r4, ad + BPL);
                bL[hh*2][0]=r4[0]; bL[hh*2][1]=r4[1]; bL[hh*2+1][0]=r4[2]; bL[hh*2+1][1]=r4[3];
            }
#pragma unroll
            for (int mf = 0; mf < MF; mf++) {
                uint32_t row = wm0 + mf * 16 + (lane & 15);
                uint32_t ch  = lane >> 4;
                uint32_t ad  = base + row * ASTR + ks * 32 + ch * 16;
                uint32_t aH[4], aL[4];
                ldsm_x4(aH, ad);
                ldsm_x4(aL, ad + APL);
#pragma unroll
                for (int nf = 0; nf < NF; nf++) {
                    mma16816(acc[mf][nf], aH, bH[nf]);
                    mma16816(acc[mf][nf], aH, bL[nf]);
                    mma16816(acc[mf][nf], aL, bH[nf]);
                }
            }
        }
        __syncthreads();
    }

    // -------- epilogue --------
#pragma unroll
    for (int mf = 0; mf < MF; mf++) {
#pragma unroll
        for (int half = 0; half < 2; half++) {
            int m = m0 + wm0 + mf * 16 + (lane >> 2) + half * 8;
#pragma unroll
            for (int nf = 0; nf < NF; nf++) {
                int n = n0 + wn0 + nf * 8 + (lane & 3) * 2;
                float v0 = acc[mf][nf][half*2 + 0];
                float v1 = acc[mf][nf][half*2 + 1];
                if (bias) { v0 += __ldg(&bias[n]); v1 += __ldg(&bias[n+1]); }
                if (EPI == EPI_GELU) {
                    v0 = 0.5f * v0 * (1.0f + erff(v0 * 0.70710678118654752f));
                    v1 = 0.5f * v1 * (1.0f + erff(v1 * 0.70710678118654752f));
                }
                if (EPI == EPI_BIASRES) {
                    const float* Rrow = resid + (size_t)m * ldc;
                    v0 += Rrow[n]; v1 += Rrow[n+1];
                }
                if (OUT_SPLIT) {
                    bf16* Ch = (bf16*)Cout + (size_t)m * ldc;
                    bf16 h0 = __float2bfloat16(v0), h1 = __float2bfloat16(v1);
                    bf16 l0 = __float2bfloat16(v0 - __bfloat162float(h0));
                    bf16 l1 = __float2bfloat16(v1 - __bfloat162float(h1));
                    *reinterpret_cast<uint32_t*>(Ch + n)          = pack2(h0, h1);
                    *reinterpret_cast<uint32_t*>(Ch + planeC + n) = pack2(l0, l1);
                } else {
                    float* Crow = (float*)Cout + (size_t)m * ldc;
                    *reinterpret_cast<float2*>(Crow + n) = make_float2(v0, v1);
                }
            }
        }
    }
}

// -------------------- host launcher --------------------
extern "C" void kernel_launch(void* const* d_in, const int* in_sizes, int n_in,
                              void* d_out, int out_size)
{
    const float* x     = (const float*)d_in[0];
    const float* qkv_w = (const float*)d_in[2];
    const float* qkv_b = (const float*)d_in[3];
    const float* out_w = (const float*)d_in[4];
    const float* out_b = (const float*)d_in[5];
    const float* fc1_w = (const float*)d_in[6];
    const float* fc1_b = (const float*)d_in[7];
    const float* fc2_w = (const float*)d_in[8];
    const float* fc2_b = (const float*)d_in[9];
    const float* ln1_w = (const float*)d_in[10];
    const float* ln1_b = (const float*)d_in[11];
    const float* ln2_w = (const float*)d_in[12];
    const float* ln2_b = (const float*)d_in[13];
    float* out = (float*)d_out;

    void *p0,*p1,*p4,*p5,*p6,*p7,*p8,*p9,*p10,*p11;
    cudaGetSymbolAddress(&p0,  g_hxs);
    cudaGetSymbolAddress(&p1,  g_qkvs);
    cudaGetSymbolAddress(&p4,  g_os);
    cudaGetSymbolAddress(&p5,  g_x1);
    cudaGetSymbolAddress(&p6,  g_h2s);
    cudaGetSymbolAddress(&p7,  g_ff1s);
    cudaGetSymbolAddress(&p8,  g_qkvw);
    cudaGetSymbolAddress(&p9,  g_outw);
    cudaGetSymbolAddress(&p10, g_fc1w);
    cudaGetSymbolAddress(&p11, g_fc2w);
    bf16* hxs  = (bf16*)p0;  bf16* qkvs = (bf16*)p1;
    bf16* os   = (bf16*)p4;  float* x1  = (float*)p5;
    bf16* h2s  = (bf16*)p6;  bf16* ff1s = (bf16*)p7;
    bf16* qkvw = (bf16*)p8;  bf16* outw = (bf16*)p9;
    bf16* fc1w = (bf16*)p10; bf16* fc2w = (bf16*)p11;

    const int SMEM_N128 = 2 * (20480 + 20480);   // 81920
    const int SMEM_FA   = 6 * 128 * 144;         // 110592

    cudaFuncSetAttribute(mma_gemm2<128,EPI_BIAS,   true >,
                         cudaFuncAttributeMaxDynamicSharedMemorySize, SMEM_N128);
    cudaFuncSetAttribute(mma_gemm2<128,EPI_BIASRES,false>,
                         cudaFuncAttributeMaxDynamicSharedMemorySize, SMEM_N128);
    cudaFuncSetAttribute(mma_gemm2<128,EPI_GELU,   true >,
                         cudaFuncAttributeMaxDynamicSharedMemorySize, SMEM_N128);
    cudaFuncSetAttribute(flash_attn,
                         cudaFuncAttributeMaxDynamicSharedMemorySize, SMEM_FA);

    // 0. weight splits
    convertw<<<(3*DD*DD/4 + 255)/256, 256>>>(qkv_w, qkvw, (long long)3*DD*DD, 3*DD*DD/4);
    convertw<<<(DD*DD/4   + 255)/256, 256>>>(out_w, outw, (long long)DD*DD,   DD*DD/4);
    convertw<<<(FF*DD/4   + 255)/256, 256>>>(fc1_w, fc1w, (long long)FF*DD,   FF*DD/4);
    convertw<<<(DD*FF/4   + 255)/256, 256>>>(fc2_w, fc2w, (long long)DD*FF,   DD*FF/4);

    // 1. ln1 -> hx split
    ln_split<<<ROWS, 256>>>(x, ln1_w, ln1_b, hxs, (long long)ROWS*DD);

    // 2. QKV: [4096,768] x [2304,768]^T -> qkv split planes
    mma_gemm2<128,EPI_BIAS,true>
        <<<dim3(3*DD/128, ROWS/128, 1), 256, SMEM_N128>>>(
            hxs, qkvw, qkv_b, nullptr, qkvs,
            DD, DD, DD, 3*DD,
            (long long)ROWS*DD, (long long)3*DD*DD, (long long)ROWS*3*DD);

    // 3-5. flash attention -> o split planes
    flash_attn<<<dim3(SS/128, BH), 256, SMEM_FA>>>(
        qkvs, (long long)ROWS*3*DD, os, (long long)ROWS*DD);

    // 6. x1 = x + O @ out_w^T + out_b   (fp32 out)
    mma_gemm2<128,EPI_BIASRES,false>
        <<<dim3(DD/128, ROWS/128, 1), 256, SMEM_N128>>>(
            os, outw, out_b, x, x1,
            DD, DD, DD, DD,
            (long long)ROWS*DD, (long long)DD*DD, 0);

    // 7. ln2 -> h2 split
    ln_split<<<ROWS, 256>>>(x1, ln2_w, ln2_b, h2s, (long long)ROWS*DD);

    // 8. ff1 = gelu(h2 @ fc1_w^T + fc1_b) -> split planes
    mma_gemm2<128,EPI_GELU,true>
        <<<dim3(FF/128, ROWS/128, 1), 256, SMEM_N128>>>(
            h2s, fc1w, fc1_b, nullptr, ff1s,
            DD, DD, DD, FF,
            (long long)ROWS*DD, (long long)FF*DD, (long long)ROWS*FF);

    // 9. out = x1 + ff1 @ fc2_w^T + fc2_b   (fp32 out)
    mma_gemm2<128,EPI_BIASRES,false>
        <<<dim3(DD/128, ROWS/128, 1), 256, SMEM_N128>>>(
            ff1s, fc2w, fc2_b, x1, out,
            FF, FF, FF, DD,
            (long long)ROWS*FF, (long long)DD*FF, 0);
}

// round 8
// speedup vs baseline: 3.8955x; 1.3183x over previous
#include <cuda_runtime.h>
#include <cuda_fp16.h>
#include <math.h>
#include <stdint.h>

typedef __half h16;

// Problem constants
#define BB 2
#define SS 2048
#define DD 768
#define HH 12
#define FF 3072
#define HDD 64
#define ROWS (BB*SS)          // 4096
#define BH (BB*HH)            // 24

// -------------------- device scratch --------------------
// activations: split fp16 (hi plane at [0], lo plane at [plane]); weights: single fp16
__device__ __align__(16) h16  g_hxs [2*ROWS*DD];
__device__ __align__(16) h16  g_qkvs[2*ROWS*3*DD];
__device__ __align__(16) h16  g_os  [2*ROWS*DD];
__device__ __align__(16) float g_x1 [ROWS*DD];
__device__ __align__(16) h16  g_h2s [2*ROWS*DD];
__device__ __align__(16) h16  g_ff1s[2*ROWS*FF];
__device__ __align__(16) h16  g_qkvw[3*DD*DD];
__device__ __align__(16) h16  g_outw[DD*DD];
__device__ __align__(16) h16  g_fc1w[FF*DD];
__device__ __align__(16) h16  g_fc2w[DD*FF];

// -------------------- helpers --------------------
__device__ __forceinline__ uint32_t smem_u32(const void* p){
    uint32_t a;
    asm("{ .reg .u64 t; cvta.to.shared.u64 t, %1; cvt.u32.u64 %0, t; }"
        : "=r"(a) : "l"(p));
    return a;
}
__device__ __forceinline__ void ldsm_x4(uint32_t* r, uint32_t a){
    asm volatile("ldmatrix.sync.aligned.m8n8.x4.shared.b16 {%0,%1,%2,%3}, [%4];"
        : "=r"(r[0]),"=r"(r[1]),"=r"(r[2]),"=r"(r[3]) : "r"(a));
}
__device__ __forceinline__ void ldsm_x4t(uint32_t* r, uint32_t a){
    asm volatile("ldmatrix.sync.aligned.m8n8.x4.trans.shared.b16 {%0,%1,%2,%3}, [%4];"
        : "=r"(r[0]),"=r"(r[1]),"=r"(r[2]),"=r"(r[3]) : "r"(a));
}
__device__ __forceinline__ void mma16816(float* c, const uint32_t* a, const uint32_t* b){
    asm volatile(
        "mma.sync.aligned.m16n8k16.row.col.f32.f16.f16.f32 "
        "{%0,%1,%2,%3}, {%4,%5,%6,%7}, {%8,%9}, {%0,%1,%2,%3};"
        : "+f"(c[0]),"+f"(c[1]),"+f"(c[2]),"+f"(c[3])
        : "r"(a[0]),"r"(a[1]),"r"(a[2]),"r"(a[3]), "r"(b[0]),"r"(b[1]));
}
#define CP_ASYNC16(dst, src) \
    asm volatile("cp.async.cg.shared.global [%0], [%1], 16;" :: "r"(dst), "l"(src))
#define CP_COMMIT() asm volatile("cp.async.commit_group;" ::: "memory")
#define CP_WAIT0()  asm volatile("cp.async.wait_group 0;" ::: "memory")
#define CP_WAIT1()  asm volatile("cp.async.wait_group 1;" ::: "memory")

static __device__ __forceinline__ uint32_t pack2(h16 a, h16 b){
    return (uint32_t)__half_as_ushort(a) | ((uint32_t)__half_as_ushort(b) << 16);
}

// -------------------- weight convert (single fp16) --------------------
__global__ __launch_bounds__(256) void convertw1(const float* __restrict__ w,
                                                 h16* __restrict__ o, int n4)
{
    int i = blockIdx.x * 256 + threadIdx.x;
    if (i >= n4) return;
    float4 v = reinterpret_cast<const float4*>(w)[i];
    uint2 r;
    r.x = pack2(__float2half_rn(v.x), __float2half_rn(v.y));
    r.y = pack2(__float2half_rn(v.z), __float2half_rn(v.w));
    reinterpret_cast<uint2*>(o)[i] = r;
}

// -------------------- layernorm -> split fp16 planes --------------------
__global__ __launch_bounds__(256) void ln_split(const float* __restrict__ x,
                                                const float* __restrict__ w,
                                                const float* __restrict__ b,
                                                h16* __restrict__ yh, long long plane)
{
    __shared__ float red[256];
    int tid = threadIdx.x;
    const float* xr = x + (size_t)blockIdx.x * DD;
    h16* yrh = yh + (size_t)blockIdx.x * DD;
    h16* yrl = yrh + plane;
    float v0 = xr[tid], v1 = xr[tid + 256], v2 = xr[tid + 512];
    red[tid] = v0 + v1 + v2;
    __syncthreads();
    for (int off = 128; off; off >>= 1) {
        if (tid < off) red[tid] += red[tid + off];
        __syncthreads();
    }
    float mean = red[0] * (1.0f / DD);
    __syncthreads();
    float d0 = v0 - mean, d1 = v1 - mean, d2 = v2 - mean;
    red[tid] = d0*d0 + d1*d1 + d2*d2;
    __syncthreads();
    for (int off = 128; off; off >>= 1) {
        if (tid < off) red[tid] += red[tid + off];
        __syncthreads();
    }
    float rstd = rsqrtf(red[0] * (1.0f / DD) + 1e-5f);
#pragma unroll
    for (int j = 0; j < 3; j++) {
        int c = tid + j * 256;
        float d = (j == 0) ? d0 : (j == 1) ? d1 : d2;
        float val = d * rstd * w[c] + b[c];
        h16 h = __float2half_rn(val);
        yrh[c] = h;
        yrl[c] = __float2half_rn(val - __half2float(h));
    }
}

// -------------------- flash attention (fp16, A-split, causal) --------------------
// Grid: (SS/128 q-tiles reversed, BH). 8 warps, each 16 q-rows x 128-col KV tile.
// SMEM: Q hi/lo [0,2PL), K single [2PL,3PL), V single [3PL,4PL); stride 144B/row.
__global__ __launch_bounds__(256) void flash_attn(
    const h16* __restrict__ qkvs, long long planeQKV,
    h16* __restrict__ os, long long planeO)
{
    constexpr int STR = 144;
    constexpr int PL  = 128 * STR;       // 18432 per plane
    extern __shared__ __align__(128) char smem[];

    const int qt = gridDim.x - 1 - blockIdx.x;   // longest jobs first
    const int bh = blockIdx.y;
    const int b = bh / HH, h = bh % HH;
    const int tid = threadIdx.x, wid = tid >> 5, lane = tid & 31;
    const uint32_t sb = smem_u32(smem);

    const h16* Qb = qkvs + (size_t)(b * SS + qt * 128) * (3 * DD) + h * HDD;
    const h16* Kb = qkvs + (size_t)(b * SS) * (3 * DD) + DD + h * HDD;
    const h16* Vb = Kb + DD;

    auto loadQ = [&]() {
#pragma unroll
        for (int it = 0; it < 8; it++) {
            int idx = tid + it * 256;
            int p = idx >> 10, rem = idx & 1023, r = rem >> 3, c = rem & 7;
            CP_ASYNC16(sb + p * PL + r * STR + c * 16,
                       Qb + p * planeQKV + (size_t)r * (3 * DD) + c * 8);
        }
        CP_COMMIT();
    };
    auto loadK = [&](int j) {
#pragma unroll
        for (int it = 0; it < 4; it++) {
            int idx = tid + it * 256;
            int r = idx >> 3, c = idx & 7;
            CP_ASYNC16(sb + 2 * PL + r * STR + c * 16,
                       Kb + (size_t)(j * 128 + r) * (3 * DD) + c * 8);
        }
        CP_COMMIT();
    };
    auto loadV = [&](int j) {
#pragma unroll
        for (int it = 0; it < 4; it++) {
            int idx = tid + it * 256;
            int r = idx >> 3, c = idx & 7;
            CP_ASYNC16(sb + 3 * PL + r * STR + c * 16,
                       Vb + (size_t)(j * 128 + r) * (3 * DD) + c * 8);
        }
        CP_COMMIT();
    };

    loadQ();
    loadK(0);
    loadV(0);

    // softmax state: rows r0 = wid*16 + lane>>2, r1 = r0+8
    float mo0 = -1e30f, mo1 = -1e30f;
    float l0 = 0.f, l1 = 0.f;
    float oacc[8][4];
#pragma unroll
    for (int f = 0; f < 8; f++)
#pragma unroll
        for (int c = 0; c < 4; c++) oacc[f][c] = 0.f;

    const float SCL = 0.125f * 1.4426950408889634f;  // 1/sqrt(64) * log2(e)

    for (int j = 0; j <= qt; j++) {
        CP_WAIT1();            // Q (first iter) + K_j arrived
        __syncthreads();

        // ---- S = Q K^T ----
        float sacc[16][4];
#pragma unroll
        for (int f = 0; f < 16; f++)
#pragma unroll
            for (int c = 0; c < 4; c++) sacc[f][c] = 0.f;

#pragma unroll
        for (int ks = 0; ks < 4; ks++) {
            uint32_t aH[4], aL[4];
            uint32_t qaddr = sb + (wid * 16 + (lane & 15)) * STR + ks * 32 + ((lane >> 4) << 4);
            ldsm_x4(aH, qaddr);
            ldsm_x4(aL, qaddr + PL);
#pragma unroll
            for (int h8 = 0; h8 < 8; h8++) {
                uint32_t row = h8 * 16 + (lane & 7) + ((lane >> 4) << 3);
                uint32_t ch  = (lane >> 3) & 1;
                uint32_t ka  = sb + 2 * PL + row * STR + ks * 32 + ch * 16;
                uint32_t bK[4];
                ldsm_x4(bK, ka);
                mma16816(sacc[2*h8],   aH, bK);
                mma16816(sacc[2*h8],   aL, bK);
                mma16816(sacc[2*h8+1], aH, bK + 2);
                mma16816(sacc[2*h8+1], aL, bK + 2);
            }
        }

        // ---- online softmax (log2 domain) ----
        const bool diag = (j == qt);
        int rl0 = wid * 16 + (lane >> 2), rl1 = rl0 + 8;
        float mn0 = mo0, mn1 = mo1;
#pragma unroll
        for (int f = 0; f < 16; f++) {
            int cl = f * 8 + (lane & 3) * 2;
            float t0 = sacc[f][0] * SCL, t1 = sacc[f][1] * SCL;
            float t2 = sacc[f][2] * SCL, t3 = sacc[f][3] * SCL;
            if (diag) {
                if (cl     > rl0) t0 = -1e30f;
                if (cl + 1 > rl0) t1 = -1e30f;
                if (cl     > rl1) t2 = -1e30f;
                if (cl + 1 > rl1) t3 = -1e30f;
            }
            sacc[f][0] = t0; sacc[f][1] = t1; sacc[f][2] = t2; sacc[f][3] = t3;
            mn0 = fmaxf(mn0, fmaxf(t0, t1));
            mn1 = fmaxf(mn1, fmaxf(t2, t3));
        }
        mn0 = fmaxf(mn0, __shfl_xor_sync(0xffffffffu, mn0, 1));
        mn0 = fmaxf(mn0, __shfl_xor_sync(0xffffffffu, mn0, 2));
        mn1 = fmaxf(mn1, __shfl_xor_sync(0xffffffffu, mn1, 1));
        mn1 = fmaxf(mn1, __shfl_xor_sync(0xffffffffu, mn1, 2));

        float f0 = exp2f(mo0 - mn0), f1 = exp2f(mo1 - mn1);
        l0 *= f0; l1 *= f1;
#pragma unroll
        for (int f = 0; f < 8; f++) {
            oacc[f][0] *= f0; oacc[f][1] *= f0;
            oacc[f][2] *= f1; oacc[f][3] *= f1;
        }
        float s0 = 0.f, s1 = 0.f;
#pragma unroll
        for (int f = 0; f < 16; f++) {
            float p0 = exp2f(sacc[f][0] - mn0);
            float p1 = exp2f(sacc[f][1] - mn0);
            float p2 = exp2f(sacc[f][2] - mn1);
            float p3 = exp2f(sacc[f][3] - mn1);
            sacc[f][0] = p0; sacc[f][1] = p1; sacc[f][2] = p2; sacc[f][3] = p3;
            s0 += p0 + p1; s1 += p2 + p3;
        }
        // reduce row-sum across the 4-lane quad (R7 fix — keep!)
        s0 += __shfl_xor_sync(0xffffffffu, s0, 1);
        s0 += __shfl_xor_sync(0xffffffffu, s0, 2);
        s1 += __shfl_xor_sync(0xffffffffu, s1, 1);
        s1 += __shfl_xor_sync(0xffffffffu, s1, 2);
        l0 += s0; l1 += s1;
        mo0 = mn0; mo1 = mn1;

        // prefetch K_{j+1}, then guarantee V_j landed (R6 fix — keep!)
        __syncthreads();
        if (j < qt) {
            loadK(j + 1);
            CP_WAIT1();
        } else {
            CP_WAIT0();
        }
        __syncthreads();

        // ---- O += P V ----
#pragma unroll
        for (int kk = 0; kk < 8; kk++) {
            uint32_t aH[4], aL[4];
#pragma unroll
            for (int half = 0; half < 2; half++) {
                const float* pr = sacc[2*kk + half];
                h16 h0 = __float2half_rn(pr[0]), h1 = __float2half_rn(pr[1]);
                h16 h2 = __float2half_rn(pr[2]), h3 = __float2half_rn(pr[3]);
                aH[half*2 + 0] = pack2(h0, h1);
                aH[half*2 + 1] = pack2(h2, h3);
                h16 e0 = __float2half_rn(pr[0] - __half2float(h0));
                h16 e1 = __float2half_rn(pr[1] - __half2float(h1));
                h16 e2 = __float2half_rn(pr[2] - __half2float(h2));
                h16 e3 = __float2half_rn(pr[3] - __half2float(h3));
                aL[half*2 + 0] = pack2(e0, e1);
                aL[half*2 + 1] = pack2(e2, e3);
            }
#pragma unroll
            for (int h4 = 0; h4 < 4; h4++) {
                uint32_t row = kk * 16 + (lane & 7) + (((lane >> 3) & 1) << 3);
                uint32_t col = h4 * 16 + ((lane >> 4) << 3);
                uint32_t va  = sb + 3 * PL + row * STR + col * 2;
                uint32_t bV[4];
                ldsm_x4t(bV, va);
                mma16816(oacc[2*h4],   aH, bV);
                mma16816(oacc[2*h4],   aL, bV);
                mma16816(oacc[2*h4+1], aH, bV + 2);
                mma16816(oacc[2*h4+1], aL, bV + 2);
            }
        }
        __syncthreads();
        if (j < qt) loadV(j + 1);
    }

    // ---- epilogue: O /= l, write split fp16 planes ----
    float li0 = 1.0f / l0, li1 = 1.0f / l1;
    int m0r = b * SS + qt * 128 + wid * 16 + (lane >> 2);
    h16* oh = os + (size_t)m0r * DD + h * HDD;
#pragma unroll
    for (int f = 0; f < 8; f++) {
        int n = f * 8 + (lane & 3) * 2;
        float v0 = oacc[f][0] * li0, v1 = oacc[f][1] * li0;
        float v2 = oacc[f][2] * li1, v3 = oacc[f][3] * li1;
        h16 h0 = __float2half_rn(v0), h1 = __float2half_rn(v1);
        h16 h2 = __float2half_rn(v2), h3 = __float2half_rn(v3);
        *reinterpret_cast<uint32_t*>(oh + n)                    = pack2(h0, h1);
        *reinterpret_cast<uint32_t*>(oh + 8 * DD + n)           = pack2(h2, h3);
        h16 e0 = __float2half_rn(v0 - __half2float(h0));
        h16 e1 = __float2half_rn(v1 - __half2float(h1));
        h16 e2 = __float2half_rn(v2 - __half2float(h2));
        h16 e3 = __float2half_rn(v3 - __half2float(h3));
        *reinterpret_cast<uint32_t*>(oh + planeO + n)           = pack2(e0, e1);
        *reinterpret_cast<uint32_t*>(oh + planeO + 8 * DD + n)  = pack2(e2, e3);
    }
}

// -------------------- fp16 A-split warp-MMA GEMM, cp.async double-buffered -----
enum { EPI_BIAS = 0, EPI_BIASRES = 1, EPI_GELU = 2 };

template<int BN, int EPI, bool OUT_SPLIT>
__global__ __launch_bounds__(256) void mma_gemm2(
    const h16* __restrict__ A, const h16* __restrict__ Bm,
    const float* __restrict__ bias, const float* __restrict__ resid,
    void* __restrict__ Cout,
    int K, int lda, int ldb, int ldc,
    long long planeA, long long planeC)
{
    constexpr int BM = 128, BK = 32;
    constexpr int ASTR = 80;
    constexpr int APL  = BM * ASTR;      // 10240
    constexpr int BSTR = 80;
    constexpr int BPL  = BN * 80;        // 10240
    constexpr int BBASE = 2 * APL;       // 20480
    constexpr int BUF  = BBASE + BPL;    // 30720 (B single plane)
    constexpr int MF = 4, NF = 4;

    extern __shared__ __align__(128) char smem[];

    const int m0 = blockIdx.y * BM, n0 = blockIdx.x * BN;
    const int tid = threadIdx.x, wid = tid >> 5, lane = tid & 31;
    const int wm0 = (wid & 1) * 64;
    const int wn0 = (wid >> 1) * 32;
    const uint32_t sb = smem_u32(smem);

    float acc[MF][NF][4];
#pragma unroll
    for (int i = 0; i < MF; i++)
#pragma unroll
        for (int jj = 0; jj < NF; jj++)
#pragma unroll
            for (int c = 0; c < 4; c++) acc[i][jj][c] = 0.f;

    int NT = K / BK;
    const h16* Alo = A + planeA;

    auto load_tile = [&](int kt, int bsel) {
        uint32_t base = sb + bsel * BUF;
#pragma unroll
        for (int it = 0; it < 4; it++) {
            int idx = tid + it * 256;
            int p = idx >> 9, rem = idx & 511, r = rem >> 2, c = rem & 3;
            const h16* src = (p ? Alo : A) + (size_t)(m0 + r) * lda + kt * BK + c * 8;
            CP_ASYNC16(base + p * APL + r * ASTR + c * 16, src);
        }
#pragma unroll
        for (int it = 0; it < 2; it++) {
            int idx = tid + it * 256;
            int r = idx >> 2, c = idx & 3;
            const h16* src = Bm + (size_t)(n0 + r) * ldb + kt * BK + c * 8;
            CP_ASYNC16(base + BBASE + r * BSTR + c * 16, src);
        }
        CP_COMMIT();
    };

    load_tile(0, 0);

    for (int kt = 0; kt < NT; kt++) {
        int buf = kt & 1;
        CP_WAIT0();
        __syncthreads();
        if (kt + 1 < NT) load_tile(kt + 1, buf ^ 1);

        uint32_t base = sb + buf * BUF;
#pragma unroll
        for (int ks = 0; ks < 2; ks++) {
            uint32_t bB[NF][2];
#pragma unroll
            for (int hh = 0; hh < 2; hh++) {
                uint32_t row = wn0 + hh * 16 + (lane & 7) + ((lane >> 4) << 3);
                uint32_t ch  = (lane >> 3) & 1;
                uint32_t ad  = base + BBASE + row * BSTR + ks * 32 + ch * 16;
                uint32_t r4[4];
                ldsm_x4(r4, ad);
                bB[hh*2][0]=r4[0]; bB[hh*2][1]=r4[1]; bB[hh*2+1][0]=r4[2]; bB[hh*2+1][1]=r4[3];
            }
#pragma unroll
            for (int mf = 0; mf < MF; mf++) {
                uint32_t row = wm0 + mf * 16 + (lane & 15);
                uint32_t ch  = lane >> 4;
                uint32_t ad  = base + row * ASTR + ks * 32 + ch * 16;
                uint32_t aH[4], aL[4];
                ldsm_x4(aH, ad);
                ldsm_x4(aL, ad + APL);
#pragma unroll
                for (int nf = 0; nf < NF; nf++) {
                    mma16816(acc[mf][nf], aH, bB[nf]);
                    mma16816(acc[mf][nf], aL, bB[nf]);
                }
            }
        }
        __syncthreads();
    }

    // -------- epilogue --------
#pragma unroll
    for (int mf = 0; mf < MF; mf++) {
#pragma unroll
        for (int half = 0; half < 2; half++) {
            int m = m0 + wm0 + mf * 16 + (lane >> 2) + half * 8;
#pragma unroll
            for (int nf = 0; nf < NF; nf++) {
                int n = n0 + wn0 + nf * 8 + (lane & 3) * 2;
                float v0 = acc[mf][nf][half*2 + 0];
                float v1 = acc[mf][nf][half*2 + 1];
                if (bias) { v0 += __ldg(&bias[n]); v1 += __ldg(&bias[n+1]); }
                if (EPI == EPI_GELU) {
                    v0 = 0.5f * v0 * (1.0f + erff(v0 * 0.70710678118654752f));
                    v1 = 0.5f * v1 * (1.0f + erff(v1 * 0.70710678118654752f));
                }
                if (EPI == EPI_BIASRES) {
                    const float* Rrow = resid + (size_t)m * ldc;
                    v0 += Rrow[n]; v1 += Rrow[n+1];
                }
                if (OUT_SPLIT) {
                    h16* Ch = (h16*)Cout + (size_t)m * ldc;
                    h16 h0 = __float2half_rn(v0), h1 = __float2half_rn(v1);
                    h16 l0 = __float2half_rn(v0 - __half2float(h0));
                    h16 l1 = __float2half_rn(v1 - __half2float(h1));
                    *reinterpret_cast<uint32_t*>(Ch + n)          = pack2(h0, h1);
                    *reinterpret_cast<uint32_t*>(Ch + planeC + n) = pack2(l0, l1);
                } else {
                    float* Crow = (float*)Cout + (size_t)m * ldc;
                    *reinterpret_cast<float2*>(Crow + n) = make_float2(v0, v1);
                }
            }
        }
    }
}

// -------------------- host launcher --------------------
extern "C" void kernel_launch(void* const* d_in, const int* in_sizes, int n_in,
                              void* d_out, int out_size)
{
    const float* x     = (const float*)d_in[0];
    const float* qkv_w = (const float*)d_in[2];
    const float* qkv_b = (const float*)d_in[3];
    const float* out_w = (const float*)d_in[4];
    const float* out_b = (const float*)d_in[5];
    const float* fc1_w = (const float*)d_in[6];
    const float* fc1_b = (const float*)d_in[7];
    const float* fc2_w = (const float*)d_in[8];
    const float* fc2_b = (const float*)d_in[9];
    const float* ln1_w = (const float*)d_in[10];
    const float* ln1_b = (const float*)d_in[11];
    const float* ln2_w = (const float*)d_in[12];
    const float* ln2_b = (const float*)d_in[13];
    float* out = (float*)d_out;

    void *p0,*p1,*p4,*p5,*p6,*p7,*p8,*p9,*p10,*p11;
    cudaGetSymbolAddress(&p0,  g_hxs);
    cudaGetSymbolAddress(&p1,  g_qkvs);
    cudaGetSymbolAddress(&p4,  g_os);
    cudaGetSymbolAddress(&p5,  g_x1);
    cudaGetSymbolAddress(&p6,  g_h2s);
    cudaGetSymbolAddress(&p7,  g_ff1s);
    cudaGetSymbolAddress(&p8,  g_qkvw);
    cudaGetSymbolAddress(&p9,  g_outw);
    cudaGetSymbolAddress(&p10, g_fc1w);
    cudaGetSymbolAddress(&p11, g_fc2w);
    h16* hxs  = (h16*)p0;  h16* qkvs = (h16*)p1;
    h16* os   = (h16*)p4;  float* x1 = (float*)p5;
    h16* h2s  = (h16*)p6;  h16* ff1s = (h16*)p7;
    h16* qkvw = (h16*)p8;  h16* outw = (h16*)p9;
    h16* fc1w = (h16*)p10; h16* fc2w = (h16*)p11;

    const int SMEM_N128 = 2 * 30720;     // 61440
    const int SMEM_FA   = 4 * 128 * 144; // 73728

    cudaFuncSetAttribute(mma_gemm2<128,EPI_BIAS,   true >,
                         cudaFuncAttributeMaxDynamicSharedMemorySize, SMEM_N128);
    cudaFuncSetAttribute(mma_gemm2<128,EPI_BIASRES,false>,
                         cudaFuncAttributeMaxDynamicSharedMemorySize, SMEM_N128);
    cudaFuncSetAttribute(mma_gemm2<128,EPI_GELU,   true >,
                         cudaFuncAttributeMaxDynamicSharedMemorySize, SMEM_N128);
    cudaFuncSetAttribute(flash_attn,
                         cudaFuncAttributeMaxDynamicSharedMemorySize, SMEM_FA);

    // 0. weight converts (single fp16)
    convertw1<<<(3*DD*DD/4 + 255)/256, 256>>>(qkv_w, qkvw, 3*DD*DD/4);
    convertw1<<<(DD*DD/4   + 255)/256, 256>>>(out_w, outw, DD*DD/4);
    convertw1<<<(FF*DD/4   + 255)/256, 256>>>(fc1_w, fc1w, FF*DD/4);
    convertw1<<<(DD*FF/4   + 255)/256, 256>>>(fc2_w, fc2w, DD*FF/4);

    // 1. ln1 -> hx split
    ln_split<<<ROWS, 256>>>(x, ln1_w, ln1_b, hxs, (long long)ROWS*DD);

    // 2. QKV: [4096,768] x [2304,768]^T -> qkv split planes
    mma_gemm2<128,EPI_BIAS,true>
        <<<dim3(3*DD/128, ROWS/128, 1), 256, SMEM_N128>>>(
            hxs, qkvw, qkv_b, nullptr, qkvs,
            DD, DD, DD, 3*DD,
            (long long)ROWS*DD, (long long)ROWS*3*DD);

    // 3-5. flash attention -> o split planes
    flash_attn<<<dim3(SS/128, BH), 256, SMEM_FA>>>(
        qkvs, (long long)ROWS*3*DD, os, (long long)ROWS*DD);

    // 6. x1 = x + O @ out_w^T + out_b   (fp32 out)
    mma_gemm2<128,EPI_BIASRES,false>
        <<<dim3(DD/128, ROWS/128, 1), 256, SMEM_N128>>>(
            os, outw, out_b, x, x1,
            DD, DD, DD, DD,
            (long long)ROWS*DD, 0);

    // 7. ln2 -> h2 split
    ln_split<<<ROWS, 256>>>(x1, ln2_w, ln2_b, h2s, (long long)ROWS*DD);

    // 8. ff1 = gelu(h2 @ fc1_w^T + fc1_b) -> split planes
    mma_gemm2<128,EPI_GELU,true>
        <<<dim3(FF/128, ROWS/128, 1), 256, SMEM_N128>>>(
            h2s, fc1w, fc1_b, nullptr, ff1s,
            DD, DD, DD, FF,
            (long long)ROWS*DD, (long long)ROWS*FF);

    // 9. out = x1 + ff1 @ fc2_w^T + fc2_b   (fp32 out)
    mma_gemm2<128,EPI_BIASRES,false>
        <<<dim3(DD/128, ROWS/128, 1), 256, SMEM_N128>>>(
            ff1s, fc2w, fc2_b, x1, out,
            FF, FF, FF, DD,
            (long long)ROWS*FF, 0);
}

// round 9
// speedup vs baseline: 6.3037x; 1.6182x over previous
#include <cuda_runtime.h>
#include <cuda_fp16.h>
#include <math.h>
#include <stdint.h>

typedef __half h16;

// Problem constants
#define BB 2
#define SS 2048
#define DD 768
#define HH 12
#define FF 3072
#define HDD 64
#define ROWS (BB*SS)          // 4096
#define BH (BB*HH)            // 24

// -------------------- device scratch (single fp16 activations) --------------------
__device__ __align__(16) h16  g_hx  [ROWS*DD];
__device__ __align__(16) h16  g_qkv [ROWS*3*DD];
__device__ __align__(16) h16  g_o   [ROWS*DD];
__device__ __align__(16) float g_x1 [ROWS*DD];
__device__ __align__(16) h16  g_h2  [ROWS*DD];
__device__ __align__(16) h16  g_ff1 [ROWS*FF];
__device__ __align__(16) h16  g_qkvw[3*DD*DD];
__device__ __align__(16) h16  g_outw[DD*DD];
__device__ __align__(16) h16  g_fc1w[FF*DD];
__device__ __align__(16) h16  g_fc2w[DD*FF];

// -------------------- helpers --------------------
__device__ __forceinline__ uint32_t smem_u32(const void* p){
    uint32_t a;
    asm("{ .reg .u64 t; cvta.to.shared.u64 t, %1; cvt.u32.u64 %0, t; }"
        : "=r"(a) : "l"(p));
    return a;
}
__device__ __forceinline__ void ldsm_x4(uint32_t* r, uint32_t a){
    asm volatile("ldmatrix.sync.aligned.m8n8.x4.shared.b16 {%0,%1,%2,%3}, [%4];"
        : "=r"(r[0]),"=r"(r[1]),"=r"(r[2]),"=r"(r[3]) : "r"(a));
}
__device__ __forceinline__ void ldsm_x4t(uint32_t* r, uint32_t a){
    asm volatile("ldmatrix.sync.aligned.m8n8.x4.trans.shared.b16 {%0,%1,%2,%3}, [%4];"
        : "=r"(r[0]),"=r"(r[1]),"=r"(r[2]),"=r"(r[3]) : "r"(a));
}
__device__ __forceinline__ void mma16816(float* c, const uint32_t* a, const uint32_t* b){
    asm volatile(
        "mma.sync.aligned.m16n8k16.row.col.f32.f16.f16.f32 "
        "{%0,%1,%2,%3}, {%4,%5,%6,%7}, {%8,%9}, {%0,%1,%2,%3};"
        : "+f"(c[0]),"+f"(c[1]),"+f"(c[2]),"+f"(c[3])
        : "r"(a[0]),"r"(a[1]),"r"(a[2]),"r"(a[3]), "r"(b[0]),"r"(b[1]));
}
#define CP_ASYNC16(dst, src) \
    asm volatile("cp.async.cg.shared.global [%0], [%1], 16;" :: "r"(dst), "l"(src))
#define CP_COMMIT() asm volatile("cp.async.commit_group;" ::: "memory")
#define CP_WAIT0()  asm volatile("cp.async.wait_group 0;" ::: "memory")
#define CP_WAIT1()  asm volatile("cp.async.wait_group 1;" ::: "memory")

static __device__ __forceinline__ uint32_t pack2(h16 a, h16 b){
    return (uint32_t)__half_as_ushort(a) | ((uint32_t)__half_as_ushort(b) << 16);
}

// -------------------- all-weights fp16 convert (one launch) --------------------
__global__ __launch_bounds__(256) void convert_all(
    const float* __restrict__ w0, h16* __restrict__ o0,   // qkv_w: 442368 quads
    const float* __restrict__ w1, h16* __restrict__ o1,   // out_w: 147456
    const float* __restrict__ w2, h16* __restrict__ o2,   // fc1_w: 589824
    const float* __restrict__ w3, h16* __restrict__ o3)   // fc2_w: 589824
{
    int i = blockIdx.x * 256 + threadIdx.x;
    const float* w; h16* o; int j;
    if (i < 442368)       { w = w0; o = o0; j = i; }
    else if (i < 589824)  { w = w1; o = o1; j = i - 442368; }
    else if (i < 1179648) { w = w2; o = o2; j = i - 589824; }
    else if (i < 1769472) { w = w3; o = o3; j = i - 1179648; }
    else return;
    float4 v = reinterpret_cast<const float4*>(w)[j];
    uint2 r;
    r.x = pack2(__float2half_rn(v.x), __float2half_rn(v.y));
    r.y = pack2(__float2half_rn(v.z), __float2half_rn(v.w));
    reinterpret_cast<uint2*>(o)[j] = r;
}

// -------------------- layernorm -> fp16 --------------------
__global__ __launch_bounds__(256) void ln_h(const float* __restrict__ x,
                                            const float* __restrict__ w,
                                            const float* __restrict__ b,
                                            h16* __restrict__ y)
{
    __shared__ float red[256];
    int tid = threadIdx.x;
    const float* xr = x + (size_t)blockIdx.x * DD;
    h16* yr = y + (size_t)blockIdx.x * DD;
    float v0 = xr[tid], v1 = xr[tid + 256], v2 = xr[tid + 512];
    red[tid] = v0 + v1 + v2;
    __syncthreads();
    for (int off = 128; off; off >>= 1) {
        if (tid < off) red[tid] += red[tid + off];
        __syncthreads();
    }
    float mean = red[0] * (1.0f / DD);
    __syncthreads();
    float d0 = v0 - mean, d1 = v1 - mean, d2 = v2 - mean;
    red[tid] = d0*d0 + d1*d1 + d2*d2;
    __syncthreads();
    for (int off = 128; off; off >>= 1) {
        if (tid < off) red[tid] += red[tid + off];
        __syncthreads();
    }
    float rstd = rsqrtf(red[0] * (1.0f / DD) + 1e-5f);
    yr[tid]       = __float2half_rn(d0 * rstd * w[tid]       + b[tid]);
    yr[tid + 256] = __float2half_rn(d1 * rstd * w[tid + 256] + b[tid + 256]);
    yr[tid + 512] = __float2half_rn(d2 * rstd * w[tid + 512] + b[tid + 512]);
}

// -------------------- flash attention (fp16, causal) --------------------
// Grid: (SS/128 q-tiles reversed, BH). 8 warps, each 16 q-rows x 128-col KV tile.
// SMEM: Q [0,PL), K [PL,2PL), V [2PL,3PL); stride 144B/row.
__global__ __launch_bounds__(256) void flash_attn(
    const h16* __restrict__ qkv,
    h16* __restrict__ os)
{
    constexpr int STR = 144;
    constexpr int PL  = 128 * STR;       // 18432 per plane
    extern __shared__ __align__(128) char smem[];

    const int qt = gridDim.x - 1 - blockIdx.x;   // longest jobs first
    const int bh = blockIdx.y;
    const int b = bh / HH, h = bh % HH;
    const int tid = threadIdx.x, wid = tid >> 5, lane = tid & 31;
    const uint32_t sb = smem_u32(smem);

    const h16* Qb = qkv + (size_t)(b * SS + qt * 128) * (3 * DD) + h * HDD;
    const h16* Kb = qkv + (size_t)(b * SS) * (3 * DD) + DD + h * HDD;
    const h16* Vb = Kb + DD;

    auto loadQ = [&]() {
#pragma unroll
        for (int it = 0; it < 4; it++) {
            int idx = tid + it * 256;
            int r = idx >> 3, c = idx & 7;
            CP_ASYNC16(sb + r * STR + c * 16,
                       Qb + (size_t)r * (3 * DD) + c * 8);
        }
        CP_COMMIT();
    };
    auto loadK = [&](int j) {
#pragma unroll
        for (int it = 0; it < 4; it++) {
            int idx = tid + it * 256;
            int r = idx >> 3, c = idx & 7;
            CP_ASYNC16(sb + PL + r * STR + c * 16,
                       Kb + (size_t)(j * 128 + r) * (3 * DD) + c * 8);
        }
        CP_COMMIT();
    };
    auto loadV = [&](int j) {
#pragma unroll
        for (int it = 0; it < 4; it++) {
            int idx = tid + it * 256;
            int r = idx >> 3, c = idx & 7;
            CP_ASYNC16(sb + 2 * PL + r * STR + c * 16,
                       Vb + (size_t)(j * 128 + r) * (3 * DD) + c * 8);
        }
        CP_COMMIT();
    };

    loadQ();
    loadK(0);
    loadV(0);

    // softmax state: rows r0 = wid*16 + lane>>2, r1 = r0+8
    float mo0 = -1e30f, mo1 = -1e30f;
    float l0 = 0.f, l1 = 0.f;
    float oacc[8][4];
#pragma unroll
    for (int f = 0; f < 8; f++)
#pragma unroll
        for (int c = 0; c < 4; c++) oacc[f][c] = 0.f;

    const float SCL = 0.125f * 1.4426950408889634f;  // 1/sqrt(64) * log2(e)

    for (int j = 0; j <= qt; j++) {
        CP_WAIT1();            // Q (first iter) + K_j arrived
        __syncthreads();

        // ---- S = Q K^T ----
        float sacc[16][4];
#pragma unroll
        for (int f = 0; f < 16; f++)
#pragma unroll
            for (int c = 0; c < 4; c++) sacc[f][c] = 0.f;

#pragma unroll
        for (int ks = 0; ks < 4; ks++) {
            uint32_t aQ[4];
            uint32_t qaddr = sb + (wid * 16 + (lane & 15)) * STR + ks * 32 + ((lane >> 4) << 4);
            ldsm_x4(aQ, qaddr);
#pragma unroll
            for (int h8 = 0; h8 < 8; h8++) {
                uint32_t row = h8 * 16 + (lane & 7) + ((lane >> 4) << 3);
                uint32_t ch  = (lane >> 3) & 1;
                uint32_t ka  = sb + PL + row * STR + ks * 32 + ch * 16;
                uint32_t bK[4];
                ldsm_x4(bK, ka);
                mma16816(sacc[2*h8],   aQ, bK);
                mma16816(sacc[2*h8+1], aQ, bK + 2);
            }
        }

        // ---- online softmax (log2 domain) ----
        const bool diag = (j == qt);
        int rl0 = wid * 16 + (lane >> 2), rl1 = rl0 + 8;
        float mn0 = mo0, mn1 = mo1;
#pragma unroll
        for (int f = 0; f < 16; f++) {
            int cl = f * 8 + (lane & 3) * 2;
            float t0 = sacc[f][0] * SCL, t1 = sacc[f][1] * SCL;
            float t2 = sacc[f][2] * SCL, t3 = sacc[f][3] * SCL;
            if (diag) {
                if (cl     > rl0) t0 = -1e30f;
                if (cl + 1 > rl0) t1 = -1e30f;
                if (cl     > rl1) t2 = -1e30f;
                if (cl + 1 > rl1) t3 = -1e30f;
            }
            sacc[f][0] = t0; sacc[f][1] = t1; sacc[f][2] = t2; sacc[f][3] = t3;
            mn0 = fmaxf(mn0, fmaxf(t0, t1));
            mn1 = fmaxf(mn1, fmaxf(t2, t3));
        }
        mn0 = fmaxf(mn0, __shfl_xor_sync(0xffffffffu, mn0, 1));
        mn0 = fmaxf(mn0, __shfl_xor_sync(0xffffffffu, mn0, 2));
        mn1 = fmaxf(mn1, __shfl_xor_sync(0xffffffffu, mn1, 1));
        mn1 = fmaxf(mn1, __shfl_xor_sync(0xffffffffu, mn1, 2));

        float f0 = exp2f(mo0 - mn0), f1 = exp2f(mo1 - mn1);
        l0 *= f0; l1 *= f1;
#pragma unroll
        for (int f = 0; f < 8; f++) {
            oacc[f][0] *= f0; oacc[f][1] *= f0;
            oacc[f][2] *= f1; oacc[f][3] *= f1;
        }
        float s0 = 0.f, s1 = 0.f;
#pragma unroll
        for (int f = 0; f < 16; f++) {
            float p0 = exp2f(sacc[f][0] - mn0);
            float p1 = exp2f(sacc[f][1] - mn0);
            float p2 = exp2f(sacc[f][2] - mn1);
            float p3 = exp2f(sacc[f][3] - mn1);
            sacc[f][0] = p0; sacc[f][1] = p1; sacc[f][2] = p2; sacc[f][3] = p3;
            s0 += p0 + p1; s1 += p2 + p3;
        }
        // reduce row-sum across the 4-lane quad (R7 fix — keep!)
        s0 += __shfl_xor_sync(0xffffffffu, s0, 1);
        s0 += __shfl_xor_sync(0xffffffffu, s0, 2);
        s1 += __shfl_xor_sync(0xffffffffu, s1, 1);
        s1 += __shfl_xor_sync(0xffffffffu, s1, 2);
        l0 += s0; l1 += s1;
        mo0 = mn0; mo1 = mn1;

        // prefetch K_{j+1}, then guarantee V_j landed (R6 fix — keep!)
        __syncthreads();
        if (j < qt) {
            loadK(j + 1);
            CP_WAIT1();
        } else {
            CP_WAIT0();
        }
        __syncthreads();

        // ---- O += P V ----
#pragma unroll
        for (int kk = 0; kk < 8; kk++) {
            uint32_t aP[4];
#pragma unroll
            for (int half = 0; half < 2; half++) {
                const float* pr = sacc[2*kk + half];
                aP[half*2 + 0] = pack2(__float2half_rn(pr[0]), __float2half_rn(pr[1]));
                aP[half*2 + 1] = pack2(__float2half_rn(pr[2]), __float2half_rn(pr[3]));
            }
#pragma unroll
            for (int h4 = 0; h4 < 4; h4++) {
                uint32_t row = kk * 16 + (lane & 7) + (((lane >> 3) & 1) << 3);
                uint32_t col = h4 * 16 + ((lane >> 4) << 3);
                uint32_t va  = sb + 2 * PL + row * STR + col * 2;
                uint32_t bV[4];
                ldsm_x4t(bV, va);
                mma16816(oacc[2*h4],   aP, bV);
                mma16816(oacc[2*h4+1], aP, bV + 2);
            }
        }
        __syncthreads();
        if (j < qt) loadV(j + 1);
    }

    // ---- epilogue: O /= l, write fp16 ----
    float li0 = 1.0f / l0, li1 = 1.0f / l1;
    int m0r = b * SS + qt * 128 + wid * 16 + (lane >> 2);
    h16* oh = os + (size_t)m0r * DD + h * HDD;
#pragma unroll
    for (int f = 0; f < 8; f++) {
        int n = f * 8 + (lane & 3) * 2;
        *reinterpret_cast<uint32_t*>(oh + n) =
            pack2(__float2half_rn(oacc[f][0] * li0), __float2half_rn(oacc[f][1] * li0));
        *reinterpret_cast<uint32_t*>(oh + 8 * DD + n) =
            pack2(__float2half_rn(oacc[f][2] * li1), __float2half_rn(oacc[f][3] * li1));
    }
}

// -------------------- fp16 warp-MMA GEMM, cp.async double-buffered -----
enum { EPI_BIAS = 0, EPI_BIASRES = 1, EPI_GELU = 2 };

template<int EPI, bool OUT_HALF>
__global__ __launch_bounds__(256) void mma_gemm2(
    const h16* __restrict__ A, const h16* __restrict__ Bm,
    const float* __restrict__ bias, const float* __restrict__ resid,
    void* __restrict__ Cout,
    int K, int lda, int ldb, int ldc)
{
    constexpr int BM = 128, BN = 128, BK = 32;
    constexpr int ASTR = 80;
    constexpr int APL  = BM * ASTR;      // 10240
    constexpr int BSTR = 80;
    constexpr int BPL  = BN * 80;        // 10240
    constexpr int BUF  = APL + BPL;      // 20480
    constexpr int MF = 4, NF = 4;

    extern __shared__ __align__(128) char smem[];

    const int m0 = blockIdx.y * BM, n0 = blockIdx.x * BN;
    const int tid = threadIdx.x, wid = tid >> 5, lane = tid & 31;
    const int wm0 = (wid & 1) * 64;
    const int wn0 = (wid >> 1) * 32;
    const uint32_t sb = smem_u32(smem);

    float acc[MF][NF][4];
#pragma unroll
    for (int i = 0; i < MF; i++)
#pragma unroll
        for (int jj = 0; jj < NF; jj++)
#pragma unroll
            for (int c = 0; c < 4; c++) acc[i][jj][c] = 0.f;

    int NT = K / BK;

    auto load_tile = [&](int kt, int bsel) {
        uint32_t base = sb + bsel * BUF;
#pragma unroll
        for (int it = 0; it < 2; it++) {
            int idx = tid + it * 256;
            int r = idx >> 2, c = idx & 3;
            const h16* src = A + (size_t)(m0 + r) * lda + kt * BK + c * 8;
            CP_ASYNC16(base + r * ASTR + c * 16, src);
        }
#pragma unroll
        for (int it = 0; it < 2; it++) {
            int idx = tid + it * 256;
            int r = idx >> 2, c = idx & 3;
            const h16* src = Bm + (size_t)(n0 + r) * ldb + kt * BK + c * 8;
            CP_ASYNC16(base + APL + r * BSTR + c * 16, src);
        }
        CP_COMMIT();
    };

    load_tile(0, 0);

    for (int kt = 0; kt < NT; kt++) {
        int buf = kt & 1;
        CP_WAIT0();
        __syncthreads();
        if (kt + 1 < NT) load_tile(kt + 1, buf ^ 1);

        uint32_t base = sb + buf * BUF;
#pragma unroll
        for (int ks = 0; ks < 2; ks++) {
            uint32_t bB[NF][2];
#pragma unroll
            for (int hh = 0; hh < 2; hh++) {
                uint32_t row = wn0 + hh * 16 + (lane & 7) + ((lane >> 4) << 3);
                uint32_t ch  = (lane >> 3) & 1;
                uint32_t ad  = base + APL + row * BSTR + ks * 32 + ch * 16;
                uint32_t r4[4];
                ldsm_x4(r4, ad);
                bB[hh*2][0]=r4[0]; bB[hh*2][1]=r4[1]; bB[hh*2+1][0]=r4[2]; bB[hh*2+1][1]=r4[3];
            }
#pragma unroll
            for (int mf = 0; mf < MF; mf++) {
                uint32_t row = wm0 + mf * 16 + (lane & 15);
                uint32_t ch  = lane >> 4;
                uint32_t ad  = base + row * ASTR + ks * 32 + ch * 16;
                uint32_t aA[4];
                ldsm_x4(aA, ad);
#pragma unroll
                for (int nf = 0; nf < NF; nf++)
                    mma16816(acc[mf][nf], aA, bB[nf]);
            }
        }
        __syncthreads();
    }

    // -------- epilogue --------
#pragma unroll
    for (int mf = 0; mf < MF; mf++) {
#pragma unroll
        for (int half = 0; half < 2; half++) {
            int m = m0 + wm0 + mf * 16 + (lane >> 2) + half * 8;
#pragma unroll
            for (int nf = 0; nf < NF; nf++) {
                int n = n0 + wn0 + nf * 8 + (lane & 3) * 2;
                float v0 = acc[mf][nf][half*2 + 0];
                float v1 = acc[mf][nf][half*2 + 1];
                if (bias) { v0 += __ldg(&bias[n]); v1 += __ldg(&bias[n+1]); }
                if (EPI == EPI_GELU) {
                    v0 = 0.5f * v0 * (1.0f + erff(v0 * 0.70710678118654752f));
                    v1 = 0.5f * v1 * (1.0f + erff(v1 * 0.70710678118654752f));
                }
                if (EPI == EPI_BIASRES) {
                    const float* Rrow = resid + (size_t)m * ldc;
                    v0 += Rrow[n]; v1 += Rrow[n+1];
                }
                if (OUT_HALF) {
                    h16* Ch = (h16*)Cout + (size_t)m * ldc;
                    *reinterpret_cast<uint32_t*>(Ch + n) =
                        pack2(__float2half_rn(v0), __float2half_rn(v1));
                } else {
                    float* Crow = (float*)Cout + (size_t)m * ldc;
                    *reinterpret_cast<float2*>(Crow + n) = make_float2(v0, v1);
                }
            }
        }
    }
}

// -------------------- host launcher --------------------
extern "C" void kernel_launch(void* const* d_in, const int* in_sizes, int n_in,
                              void* d_out, int out_size)
{
    const float* x     = (const float*)d_in[0];
    const float* qkv_w = (const float*)d_in[2];
    const float* qkv_b = (const float*)d_in[3];
    const float* out_w = (const float*)d_in[4];
    const float* out_b = (const float*)d_in[5];
    const float* fc1_w = (const float*)d_in[6];
    const float* fc1_b = (const float*)d_in[7];
    const float* fc2_w = (const float*)d_in[8];
    const float* fc2_b = (const float*)d_in[9];
    const float* ln1_w = (const float*)d_in[10];
    const float* ln1_b = (const float*)d_in[11];
    const float* ln2_w = (const float*)d_in[12];
    const float* ln2_b = (const float*)d_in[13];
    float* out = (float*)d_out;

    void *p0,*p1,*p4,*p5,*p6,*p7,*p8,*p9,*p10,*p11;
    cudaGetSymbolAddress(&p0,  g_hx);
    cudaGetSymbolAddress(&p1,  g_qkv);
    cudaGetSymbolAddress(&p4,  g_o);
    cudaGetSymbolAddress(&p5,  g_x1);
    cudaGetSymbolAddress(&p6,  g_h2);
    cudaGetSymbolAddress(&p7,  g_ff1);
    cudaGetSymbolAddress(&p8,  g_qkvw);
    cudaGetSymbolAddress(&p9,  g_outw);
    cudaGetSymbolAddress(&p10, g_fc1w);
    cudaGetSymbolAddress(&p11, g_fc2w);
    h16* hx   = (h16*)p0;  h16* qkv  = (h16*)p1;
    h16* o    = (h16*)p4;  float* x1 = (float*)p5;
    h16* h2   = (h16*)p6;  h16* ff1  = (h16*)p7;
    h16* qkvw = (h16*)p8;  h16* outw = (h16*)p9;
    h16* fc1w = (h16*)p10; h16* fc2w = (h16*)p11;

    const int SMEM_GEMM = 2 * 20480;     // 40960
    const int SMEM_FA   = 3 * 128 * 144; // 55296

    cudaFuncSetAttribute(mma_gemm2<EPI_BIAS,   true >,
                         cudaFuncAttributeMaxDynamicSharedMemorySize, SMEM_GEMM);
    cudaFuncSetAttribute(mma_gemm2<EPI_BIASRES,false>,
                         cudaFuncAttributeMaxDynamicSharedMemorySize, SMEM_GEMM);
    cudaFuncSetAttribute(mma_gemm2<EPI_GELU,   true >,
                         cudaFuncAttributeMaxDynamicSharedMemorySize, SMEM_GEMM);
    cudaFuncSetAttribute(flash_attn,
                         cudaFuncAttributeMaxDynamicSharedMemorySize, SMEM_FA);

    // 0. all weight converts in one launch (1769472 quads)
    convert_all<<<(1769472 + 255)/256, 256>>>(qkv_w, qkvw, out_w, outw,
                                              fc1_w, fc1w, fc2_w, fc2w);

    // 1. ln1 -> hx fp16
    ln_h<<<ROWS, 256>>>(x, ln1_w, ln1_b, hx);

    // 2. QKV: [4096,768] x [2304,768]^T -> qkv fp16
    mma_gemm2<EPI_BIAS,true>
        <<<dim3(3*DD/128, ROWS/128, 1), 256, SMEM_GEMM>>>(
            hx, qkvw, qkv_b, nullptr, qkv,
            DD, DD, DD, 3*DD);

    // 3-5. flash attention -> o fp16
    flash_attn<<<dim3(SS/128, BH), 256, SMEM_FA>>>(qkv, o);

    // 6. x1 = x + O @ out_w^T + out_b   (fp32 out)
    mma_gemm2<EPI_BIASRES,false>
        <<<dim3(DD/128, ROWS/128, 1), 256, SMEM_GEMM>>>(
            o, outw, out_b, x, x1,
            DD, DD, DD, DD);

    // 7. ln2 -> h2 fp16
    ln_h<<<ROWS, 256>>>(x1, ln2_w, ln2_b, h2);

    // 8. ff1 = gelu(h2 @ fc1_w^T + fc1_b) -> fp16
    mma_gemm2<EPI_GELU,true>
        <<<dim3(FF/128, ROWS/128, 1), 256, SMEM_GEMM>>>(
            h2, fc1w, fc1_b, nullptr, ff1,
            DD, DD, DD, FF);

    // 9. out = x1 + ff1 @ fc2_w^T + fc2_b   (fp32 out)
    mma_gemm2<EPI_BIASRES,false>
        <<<dim3(DD/128, ROWS/128, 1), 256, SMEM_GEMM>>>(
            ff1, fc2w, fc2_b, x1, out,
            FF, FF, FF, DD);
}

// round 10
// speedup vs baseline: 6.7493x; 1.0707x over previous
#include <cuda_runtime.h>
#include <cuda_fp16.h>
#include <math.h>
#include <stdint.h>

typedef __half h16;

// Problem constants
#define BB 2
#define SS 2048
#define DD 768
#define HH 12
#define FF 3072
#define HDD 64
#define ROWS (BB*SS)          // 4096
#define BH (BB*HH)            // 24

// -------------------- device scratch (single fp16 activations) --------------------
__device__ __align__(16) h16  g_hx  [ROWS*DD];
__device__ __align__(16) h16  g_qkv [ROWS*3*DD];
__device__ __align__(16) h16  g_o   [ROWS*DD];
__device__ __align__(16) float g_x1 [ROWS*DD];
__device__ __align__(16) h16  g_h2  [ROWS*DD];
__device__ __align__(16) h16  g_ff1 [ROWS*FF];
__device__ __align__(16) h16  g_qkvw[3*DD*DD];
__device__ __align__(16) h16  g_outw[DD*DD];
__device__ __align__(16) h16  g_fc1w[FF*DD];
__device__ __align__(16) h16  g_fc2w[DD*FF];

// -------------------- helpers --------------------
__device__ __forceinline__ uint32_t smem_u32(const void* p){
    uint32_t a;
    asm("{ .reg .u64 t; cvta.to.shared.u64 t, %1; cvt.u32.u64 %0, t; }"
        : "=r"(a) : "l"(p));
    return a;
}
__device__ __forceinline__ void ldsm_x4(uint32_t* r, uint32_t a){
    asm volatile("ldmatrix.sync.aligned.m8n8.x4.shared.b16 {%0,%1,%2,%3}, [%4];"
        : "=r"(r[0]),"=r"(r[1]),"=r"(r[2]),"=r"(r[3]) : "r"(a));
}
__device__ __forceinline__ void ldsm_x4t(uint32_t* r, uint32_t a){
    asm volatile("ldmatrix.sync.aligned.m8n8.x4.trans.shared.b16 {%0,%1,%2,%3}, [%4];"
        : "=r"(r[0]),"=r"(r[1]),"=r"(r[2]),"=r"(r[3]) : "r"(a));
}
__device__ __forceinline__ void mma16816(float* c, const uint32_t* a, const uint32_t* b){
    asm volatile(
        "mma.sync.aligned.m16n8k16.row.col.f32.f16.f16.f32 "
        "{%0,%1,%2,%3}, {%4,%5,%6,%7}, {%8,%9}, {%0,%1,%2,%3};"
        : "+f"(c[0]),"+f"(c[1]),"+f"(c[2]),"+f"(c[3])
        : "r"(a[0]),"r"(a[1]),"r"(a[2]),"r"(a[3]), "r"(b[0]),"r"(b[1]));
}
#define CP_ASYNC16(dst, src) \
    asm volatile("cp.async.cg.shared.global [%0], [%1], 16;" :: "r"(dst), "l"(src))
#define CP_COMMIT() asm volatile("cp.async.commit_group;" ::: "memory")
#define CP_WAIT0()  asm volatile("cp.async.wait_group 0;" ::: "memory")
#define CP_WAIT1()  asm volatile("cp.async.wait_group 1;" ::: "memory")

static __device__ __forceinline__ uint32_t pack2(h16 a, h16 b){
    return (uint32_t)__half_as_ushort(a) | ((uint32_t)__half_as_ushort(b) << 16);
}

// -------------------- all-weights fp16 convert (one launch) --------------------
__global__ __launch_bounds__(256) void convert_all(
    const float* __restrict__ w0, h16* __restrict__ o0,   // qkv_w: 442368 quads
    const float* __restrict__ w1, h16* __restrict__ o1,   // out_w: 147456
    const float* __restrict__ w2, h16* __restrict__ o2,   // fc1_w: 589824
    const float* __restrict__ w3, h16* __restrict__ o3)   // fc2_w: 589824
{
    int i = blockIdx.x * 256 + threadIdx.x;
    const float* w; h16* o; int j;
    if (i < 442368)       { w = w0; o = o0; j = i; }
    else if (i < 589824)  { w = w1; o = o1; j = i - 442368; }
    else if (i < 1179648) { w = w2; o = o2; j = i - 589824; }
    else if (i < 1769472) { w = w3; o = o3; j = i - 1179648; }
    else return;
    float4 v = reinterpret_cast<const float4*>(w)[j];
    uint2 r;
    r.x = pack2(__float2half_rn(v.x), __float2half_rn(v.y));
    r.y = pack2(__float2half_rn(v.z), __float2half_rn(v.w));
    reinterpret_cast<uint2*>(o)[j] = r;
}

// -------------------- layernorm -> fp16 --------------------
__global__ __launch_bounds__(256) void ln_h(const float* __restrict__ x,
                                            const float* __restrict__ w,
                                            const float* __restrict__ b,
                                            h16* __restrict__ y)
{
    __shared__ float red[256];
    int tid = threadIdx.x;
    const float* xr = x + (size_t)blockIdx.x * DD;
    h16* yr = y + (size_t)blockIdx.x * DD;
    float v0 = xr[tid], v1 = xr[tid + 256], v2 = xr[tid + 512];
    red[tid] = v0 + v1 + v2;
    __syncthreads();
    for (int off = 128; off; off >>= 1) {
        if (tid < off) red[tid] += red[tid + off];
        __syncthreads();
    }
    float mean = red[0] * (1.0f / DD);
    __syncthreads();
    float d0 = v0 - mean, d1 = v1 - mean, d2 = v2 - mean;
    red[tid] = d0*d0 + d1*d1 + d2*d2;
    __syncthreads();
    for (int off = 128; off; off >>= 1) {
        if (tid < off) red[tid] += red[tid + off];
        __syncthreads();
    }
    float rstd = rsqrtf(red[0] * (1.0f / DD) + 1e-5f);
    yr[tid]       = __float2half_rn(d0 * rstd * w[tid]       + b[tid]);
    yr[tid + 256] = __float2half_rn(d1 * rstd * w[tid + 256] + b[tid + 256]);
    yr[tid + 512] = __float2half_rn(d2 * rstd * w[tid + 512] + b[tid + 512]);
}

// -------------------- flash attention (fp16, causal, dbl-buffered KV) ----------
// Grid: (SS/128 q-tiles reversed, BH). 8 warps, each 16 q-rows x 128-col KV tile.
// SMEM planes (128 x 144B each): Q | K0 | K1 | V0 | V1
__global__ __launch_bounds__(256) void flash_attn(
    const h16* __restrict__ qkv,
    h16* __restrict__ os)
{
    constexpr int STR = 144;
    constexpr int PL  = 128 * STR;       // 18432 per plane
    extern __shared__ __align__(128) char smem[];

    const int qt = gridDim.x - 1 - blockIdx.x;   // longest jobs first
    const int bh = blockIdx.y;
    const int b = bh / HH, h = bh % HH;
    const int tid = threadIdx.x, wid = tid >> 5, lane = tid & 31;
    const uint32_t sb = smem_u32(smem);

    const h16* Qb = qkv + (size_t)(b * SS + qt * 128) * (3 * DD) + h * HDD;
    const h16* Kb = qkv + (size_t)(b * SS) * (3 * DD) + DD + h * HDD;
    const h16* Vb = Kb + DD;

    auto loadQ = [&]() {
#pragma unroll
        for (int it = 0; it < 4; it++) {
            int idx = tid + it * 256;
            int r = idx >> 3, c = idx & 7;
            CP_ASYNC16(sb + r * STR + c * 16,
                       Qb + (size_t)r * (3 * DD) + c * 8);
        }
        CP_COMMIT();
    };
    // one group: K_j and V_j together into buffer `buf`
    auto loadKV = [&](int j, int buf) {
#pragma unroll
        for (int it = 0; it < 4; it++) {
            int idx = tid + it * 256;
            int r = idx >> 3, c = idx & 7;
            CP_ASYNC16(sb + (1 + buf) * PL + r * STR + c * 16,
                       Kb + (size_t)(j * 128 + r) * (3 * DD) + c * 8);
        }
#pragma unroll
        for (int it = 0; it < 4; it++) {
            int idx = tid + it * 256;
            int r = idx >> 3, c = idx & 7;
            CP_ASYNC16(sb + (3 + buf) * PL + r * STR + c * 16,
                       Vb + (size_t)(j * 128 + r) * (3 * DD) + c * 8);
        }
        CP_COMMIT();
    };

    loadQ();
    loadKV(0, 0);
    if (qt >= 1) loadKV(1, 1);

    // softmax state: rows r0 = wid*16 + lane>>2, r1 = r0+8
    float mo0 = -1e30f, mo1 = -1e30f;
    float l0 = 0.f, l1 = 0.f;
    float oacc[8][4];
#pragma unroll
    for (int f = 0; f < 8; f++)
#pragma unroll
        for (int c = 0; c < 4; c++) oacc[f][c] = 0.f;

    const float SCL = 0.125f * 1.4426950408889634f;  // 1/sqrt(64) * log2(e)

    for (int j = 0; j <= qt; j++) {
        const int buf = j & 1;
        if (j < qt) CP_WAIT1();   // KV_j (and Q) done; KV_{j+1} may be in flight
        else        CP_WAIT0();
        __syncthreads();

        // ---- S = Q K^T ----
        float sacc[16][4];
#pragma unroll
        for (int f = 0; f < 16; f++)
#pragma unroll
            for (int c = 0; c < 4; c++) sacc[f][c] = 0.f;

#pragma unroll
        for (int ks = 0; ks < 4; ks++) {
            uint32_t aQ[4];
            uint32_t qaddr = sb + (wid * 16 + (lane & 15)) * STR + ks * 32 + ((lane >> 4) << 4);
            ldsm_x4(aQ, qaddr);
#pragma unroll
            for (int h8 = 0; h8 < 8; h8++) {
                uint32_t row = h8 * 16 + (lane & 7) + ((lane >> 4) << 3);
                uint32_t ch  = (lane >> 3) & 1;
                uint32_t ka  = sb + (1 + buf) * PL + row * STR + ks * 32 + ch * 16;
                uint32_t bK[4];
                ldsm_x4(bK, ka);
                mma16816(sacc[2*h8],   aQ, bK);
                mma16816(sacc[2*h8+1], aQ, bK + 2);
            }
        }

        // ---- online softmax (log2 domain) ----
        const bool diag = (j == qt);
        int rl0 = wid * 16 + (lane >> 2), rl1 = rl0 + 8;
        float mn0 = mo0, mn1 = mo1;
#pragma unroll
        for (int f = 0; f < 16; f++) {
            int cl = f * 8 + (lane & 3) * 2;
            float t0 = sacc[f][0] * SCL, t1 = sacc[f][1] * SCL;
            float t2 = sacc[f][2] * SCL, t3 = sacc[f][3] * SCL;
            if (diag) {
                if (cl     > rl0) t0 = -1e30f;
                if (cl + 1 > rl0) t1 = -1e30f;
                if (cl     > rl1) t2 = -1e30f;
                if (cl + 1 > rl1) t3 = -1e30f;
            }
            sacc[f][0] = t0; sacc[f][1] = t1; sacc[f][2] = t2; sacc[f][3] = t3;
            mn0 = fmaxf(mn0, fmaxf(t0, t1));
            mn1 = fmaxf(mn1, fmaxf(t2, t3));
        }
        mn0 = fmaxf(mn0, __shfl_xor_sync(0xffffffffu, mn0, 1));
        mn0 = fmaxf(mn0, __shfl_xor_sync(0xffffffffu, mn0, 2));
        mn1 = fmaxf(mn1, __shfl_xor_sync(0xffffffffu, mn1, 1));
        mn1 = fmaxf(mn1, __shfl_xor_sync(0xffffffffu, mn1, 2));

        float f0 = exp2f(mo0 - mn0), f1 = exp2f(mo1 - mn1);
        l0 *= f0; l1 *= f1;
#pragma unroll
        for (int f = 0; f < 8; f++) {
            oacc[f][0] *= f0; oacc[f][1] *= f0;
            oacc[f][2] *= f1; oacc[f][3] *= f1;
        }
        float s0 = 0.f, s1 = 0.f;
#pragma unroll
        for (int f = 0; f < 16; f++) {
            float p0 = exp2f(sacc[f][0] - mn0);
            float p1 = exp2f(sacc[f][1] - mn0);
            float p2 = exp2f(sacc[f][2] - mn1);
            float p3 = exp2f(sacc[f][3] - mn1);
            sacc[f][0] = p0; sacc[f][1] = p1; sacc[f][2] = p2; sacc[f][3] = p3;
            s0 += p0 + p1; s1 += p2 + p3;
        }
        // reduce row-sum across the 4-lane quad (R7 fix — keep!)
        s0 += __shfl_xor_sync(0xffffffffu, s0, 1);
        s0 += __shfl_xor_sync(0xffffffffu, s0, 2);
        s1 += __shfl_xor_sync(0xffffffffu, s1, 1);
        s1 += __shfl_xor_sync(0xffffffffu, s1, 2);
        l0 += s0; l1 += s1;
        mo0 = mn0; mo1 = mn1;

        // ---- O += P V  (V_j already resident — no barrier needed after QK) ----
#pragma unroll
        for (int kk = 0; kk < 8; kk++) {
            uint32_t aP[4];
#pragma unroll
            for (int half = 0; half < 2; half++) {
                const float* pr = sacc[2*kk + half];
                aP[half*2 + 0] = pack2(__float2half_rn(pr[0]), __float2half_rn(pr[1]));
                aP[half*2 + 1] = pack2(__float2half_rn(pr[2]), __float2half_rn(pr[3]));
            }
#pragma unroll
            for (int h4 = 0; h4 < 4; h4++) {
                uint32_t row = kk * 16 + (lane & 7) + (((lane >> 3) & 1) << 3);
                uint32_t col = h4 * 16 + ((lane >> 4) << 3);
                uint32_t va  = sb + (3 + buf) * PL + row * STR + col * 2;
                uint32_t bV[4];
                ldsm_x4t(bV, va);
                mma16816(oacc[2*h4],   aP, bV);
                mma16816(oacc[2*h4+1], aP, bV + 2);
            }
        }
        __syncthreads();                 // all warps done with buffer `buf`
        if (j + 2 <= qt) loadKV(j + 2, buf);
    }

    // ---- epilogue: O /= l, write fp16 ----
    float li0 = 1.0f / l0, li1 = 1.0f / l1;
    int m0r = b * SS + qt * 128 + wid * 16 + (lane >> 2);
    h16* oh = os + (size_t)m0r * DD + h * HDD;
#pragma unroll
    for (int f = 0; f < 8; f++) {
        int n = f * 8 + (lane & 3) * 2;
        *reinterpret_cast<uint32_t*>(oh + n) =
            pack2(__float2half_rn(oacc[f][0] * li0), __float2half_rn(oacc[f][1] * li0));
        *reinterpret_cast<uint32_t*>(oh + 8 * DD + n) =
            pack2(__float2half_rn(oacc[f][2] * li1), __float2half_rn(oacc[f][3] * li1));
    }
}

// -------------------- fp16 warp-MMA GEMM, BK=64, cp.async double-buffered -----
enum { EPI_BIAS = 0, EPI_BIASRES = 1, EPI_GELU = 2 };

template<int EPI, bool OUT_HALF>
__global__ __launch_bounds__(256) void mma_gemm2(
    const h16* __restrict__ A, const h16* __restrict__ Bm,
    const float* __restrict__ bias, const float* __restrict__ resid,
    void* __restrict__ Cout,
    int K, int lda, int ldb, int ldc)
{
    constexpr int BM = 128, BN = 128, BK = 64;
    constexpr int ASTR = 144;            // 128B row + 16B pad (bank-rotating)
    constexpr int APL  = BM * ASTR;      // 18432
    constexpr int BSTR = 144;
    constexpr int BPL  = BN * BSTR;      // 18432
    constexpr int BUF  = APL + BPL;      // 36864
    constexpr int MF = 4, NF = 4;

    extern __shared__ __align__(128) char smem[];

    const int m0 = blockIdx.y * BM, n0 = blockIdx.x * BN;
    const int tid = threadIdx.x, wid = tid >> 5, lane = tid & 31;
    const int wm0 = (wid & 1) * 64;
    const int wn0 = (wid >> 1) * 32;
    const uint32_t sb = smem_u32(smem);

    float acc[MF][NF][4];
#pragma unroll
    for (int i = 0; i < MF; i++)
#pragma unroll
        for (int jj = 0; jj < NF; jj++)
#pragma unroll
            for (int c = 0; c < 4; c++) acc[i][jj][c] = 0.f;

    int NT = K / BK;

    auto load_tile = [&](int kt, int bsel) {
        uint32_t base = sb + bsel * BUF;
#pragma unroll
        for (int it = 0; it < 4; it++) {
            int idx = tid + it * 256;
            int r = idx >> 3, c = idx & 7;
            const h16* src = A + (size_t)(m0 + r) * lda + kt * BK + c * 8;
            CP_ASYNC16(base + r * ASTR + c * 16, src);
        }
#pragma unroll
        for (int it = 0; it < 4; it++) {
            int idx = tid + it * 256;
            int r = idx >> 3, c = idx & 7;
            const h16* src = Bm + (size_t)(n0 + r) * ldb + kt * BK + c * 8;
            CP_ASYNC16(base + APL + r * BSTR + c * 16, src);
        }
        CP_COMMIT();
    };

    load_tile(0, 0);

    for (int kt = 0; kt < NT; kt++) {
        int buf = kt & 1;
        CP_WAIT0();
        __syncthreads();
        if (kt + 1 < NT) load_tile(kt + 1, buf ^ 1);

        uint32_t base = sb + buf * BUF;
#pragma unroll
        for (int ks = 0; ks < 4; ks++) {
            uint32_t bB[NF][2];
#pragma unroll
            for (int hh = 0; hh < 2; hh++) {
                uint32_t row = wn0 + hh * 16 + (lane & 7) + ((lane >> 4) << 3);
                uint32_t ch  = (lane >> 3) & 1;
                uint32_t ad  = base + APL + row * BSTR + ks * 32 + ch * 16;
                uint32_t r4[4];
                ldsm_x4(r4, ad);
                bB[hh*2][0]=r4[0]; bB[hh*2][1]=r4[1]; bB[hh*2+1][0]=r4[2]; bB[hh*2+1][1]=r4[3];
            }
#pragma unroll
            for (int mf = 0; mf < MF; mf++) {
                uint32_t row = wm0 + mf * 16 + (lane & 15);
                uint32_t ch  = lane >> 4;
                uint32_t ad  = base + row * ASTR + ks * 32 + ch * 16;
                uint32_t aA[4];
                ldsm_x4(aA, ad);
#pragma unroll
                for (int nf = 0; nf < NF; nf++)
                    mma16816(acc[mf][nf], aA, bB[nf]);
            }
        }
        __syncthreads();
    }

    // -------- epilogue --------
#pragma unroll
    for (int mf = 0; mf < MF; mf++) {
#pragma unroll
        for (int half = 0; half < 2; half++) {
            int m = m0 + wm0 + mf * 16 + (lane >> 2) + half * 8;
#pragma unroll
            for (int nf = 0; nf < NF; nf++) {
                int n = n0 + wn0 + nf * 8 + (lane & 3) * 2;
                float v0 = acc[mf][nf][half*2 + 0];
                float v1 = acc[mf][nf][half*2 + 1];
                if (bias) { v0 += __ldg(&bias[n]); v1 += __ldg(&bias[n+1]); }
                if (EPI == EPI_GELU) {
                    v0 = 0.5f * v0 * (1.0f + erff(v0 * 0.70710678118654752f));
                    v1 = 0.5f * v1 * (1.0f + erff(v1 * 0.70710678118654752f));
                }
                if (EPI == EPI_BIASRES) {
                    const float* Rrow = resid + (size_t)m * ldc;
                    v0 += Rrow[n]; v1 += Rrow[n+1];
                }
                if (OUT_HALF) {
                    h16* Ch = (h16*)Cout + (size_t)m * ldc;
                    *reinterpret_cast<uint32_t*>(Ch + n) =
                        pack2(__float2half_rn(v0), __float2half_rn(v1));
                } else {
                    float* Crow = (float*)Cout + (size_t)m * ldc;
                    *reinterpret_cast<float2*>(Crow + n) = make_float2(v0, v1);
                }
            }
        }
    }
}

// -------------------- host launcher --------------------
extern "C" void kernel_launch(void* const* d_in, const int* in_sizes, int n_in,
                              void* d_out, int out_size)
{
    const float* x     = (const float*)d_in[0];
    const float* qkv_w = (const float*)d_in[2];
    const float* qkv_b = (const float*)d_in[3];
    const float* out_w = (const float*)d_in[4];
    const float* out_b = (const float*)d_in[5];
    const float* fc1_w = (const float*)d_in[6];
    const float* fc1_b = (const float*)d_in[7];
    const float* fc2_w = (const float*)d_in[8];
    const float* fc2_b = (const float*)d_in[9];
    const float* ln1_w = (const float*)d_in[10];
    const float* ln1_b = (const float*)d_in[11];
    const float* ln2_w = (const float*)d_in[12];
    const float* ln2_b = (const float*)d_in[13];
    float* out = (float*)d_out;

    void *p0,*p1,*p4,*p5,*p6,*p7,*p8,*p9,*p10,*p11;
    cudaGetSymbolAddress(&p0,  g_hx);
    cudaGetSymbolAddress(&p1,  g_qkv);
    cudaGetSymbolAddress(&p4,  g_o);
    cudaGetSymbolAddress(&p5,  g_x1);
    cudaGetSymbolAddress(&p6,  g_h2);
    cudaGetSymbolAddress(&p7,  g_ff1);
    cudaGetSymbolAddress(&p8,  g_qkvw);
    cudaGetSymbolAddress(&p9,  g_outw);
    cudaGetSymbolAddress(&p10, g_fc1w);
    cudaGetSymbolAddress(&p11, g_fc2w);
    h16* hx   = (h16*)p0;  h16* qkv  = (h16*)p1;
    h16* o    = (h16*)p4;  float* x1 = (float*)p5;
    h16* h2   = (h16*)p6;  h16* ff1  = (h16*)p7;
    h16* qkvw = (h16*)p8;  h16* outw = (h16*)p9;
    h16* fc1w = (h16*)p10; h16* fc2w = (h16*)p11;

    const int SMEM_GEMM = 2 * 36864;     // 73728
    const int SMEM_FA   = 5 * 128 * 144; // 92160

    cudaFuncSetAttribute(mma_gemm2<EPI_BIAS,   true >,
                         cudaFuncAttributeMaxDynamicSharedMemorySize, SMEM_GEMM);
    cudaFuncSetAttribute(mma_gemm2<EPI_BIASRES,false>,
                         cudaFuncAttributeMaxDynamicSharedMemorySize, SMEM_GEMM);
    cudaFuncSetAttribute(mma_gemm2<EPI_GELU,   true >,
                         cudaFuncAttributeMaxDynamicSharedMemorySize, SMEM_GEMM);
    cudaFuncSetAttribute(flash_attn,
                         cudaFuncAttributeMaxDynamicSharedMemorySize, SMEM_FA);

    // 0. all weight converts in one launch (1769472 quads)
    convert_all<<<(1769472 + 255)/256, 256>>>(qkv_w, qkvw, out_w, outw,
                                              fc1_w, fc1w, fc2_w, fc2w);

    // 1. ln1 -> hx fp16
    ln_h<<<ROWS, 256>>>(x, ln1_w, ln1_b, hx);

    // 2. QKV: [4096,768] x [2304,768]^T -> qkv fp16
    mma_gemm2<EPI_BIAS,true>
        <<<dim3(3*DD/128, ROWS/128, 1), 256, SMEM_GEMM>>>(
            hx, qkvw, qkv_b, nullptr, qkv,
            DD, DD, DD, 3*DD);

    // 3-5. flash attention -> o fp16
    flash_attn<<<dim3(SS/128, BH), 256, SMEM_FA>>>(qkv, o);

    // 6. x1 = x + O @ out_w^T + out_b   (fp32 out)
    mma_gemm2<EPI_BIASRES,false>
        <<<dim3(DD/128, ROWS/128, 1), 256, SMEM_GEMM>>>(
            o, outw, out_b, x, x1,
            DD, DD, DD, DD);

    // 7. ln2 -> h2 fp16
    ln_h<<<ROWS, 256>>>(x1, ln2_w, ln2_b, h2);

    // 8. ff1 = gelu(h2 @ fc1_w^T + fc1_b) -> fp16
    mma_gemm2<EPI_GELU,true>
        <<<dim3(FF/128, ROWS/128, 1), 256, SMEM_GEMM>>>(
            h2, fc1w, fc1_b, nullptr, ff1,
            DD, DD, DD, FF);

    // 9. out = x1 + ff1 @ fc2_w^T + fc2_b   (fp32 out)
    mma_gemm2<EPI_BIASRES,false>
        <<<dim3(DD/128, ROWS/128, 1), 256, SMEM_GEMM>>>(
            ff1, fc2w, fc2_b, x1, out,
            FF, FF, FF, DD);
}

// round 11
// speedup vs baseline: 6.8895x; 1.0208x over previous
#include <cuda_runtime.h>
#include <cuda_fp16.h>
#include <math.h>
#include <stdint.h>

typedef __half h16;

// Problem constants
#define BB 2
#define SS 2048
#define DD 768
#define HH 12
#define FF 3072
#define HDD 64
#define ROWS (BB*SS)          // 4096
#define BH (BB*HH)            // 24

// -------------------- device scratch (single fp16 activations) --------------------
__device__ __align__(16) h16  g_hx  [ROWS*DD];
__device__ __align__(16) h16  g_qkv [ROWS*3*DD];
__device__ __align__(16) h16  g_o   [ROWS*DD];
__device__ __align__(16) float g_x1 [ROWS*DD];
__device__ __align__(16) h16  g_h2  [ROWS*DD];
__device__ __align__(16) h16  g_ff1 [ROWS*FF];
__device__ __align__(16) h16  g_qkvw[3*DD*DD];
__device__ __align__(16) h16  g_outw[DD*DD];
__device__ __align__(16) h16  g_fc1w[FF*DD];
__device__ __align__(16) h16  g_fc2w[DD*FF];

// -------------------- helpers --------------------
__device__ __forceinline__ uint32_t smem_u32(const void* p){
    uint32_t a;
    asm("{ .reg .u64 t; cvta.to.shared.u64 t, %1; cvt.u32.u64 %0, t; }"
        : "=r"(a) : "l"(p));
    return a;
}
__device__ __forceinline__ void ldsm_x4(uint32_t* r, uint32_t a){
    asm volatile("ldmatrix.sync.aligned.m8n8.x4.shared.b16 {%0,%1,%2,%3}, [%4];"
        : "=r"(r[0]),"=r"(r[1]),"=r"(r[2]),"=r"(r[3]) : "r"(a));
}
__device__ __forceinline__ void ldsm_x4t(uint32_t* r, uint32_t a){
    asm volatile("ldmatrix.sync.aligned.m8n8.x4.trans.shared.b16 {%0,%1,%2,%3}, [%4];"
        : "=r"(r[0]),"=r"(r[1]),"=r"(r[2]),"=r"(r[3]) : "r"(a));
}
__device__ __forceinline__ void mma16816(float* c, const uint32_t* a, const uint32_t* b){
    asm volatile(
        "mma.sync.aligned.m16n8k16.row.col.f32.f16.f16.f32 "
        "{%0,%1,%2,%3}, {%4,%5,%6,%7}, {%8,%9}, {%0,%1,%2,%3};"
        : "+f"(c[0]),"+f"(c[1]),"+f"(c[2]),"+f"(c[3])
        : "r"(a[0]),"r"(a[1]),"r"(a[2]),"r"(a[3]), "r"(b[0]),"r"(b[1]));
}
#define CP_ASYNC16(dst, src) \
    asm volatile("cp.async.cg.shared.global [%0], [%1], 16;" :: "r"(dst), "l"(src))
#define CP_COMMIT() asm volatile("cp.async.commit_group;" ::: "memory")
#define CP_WAIT0()  asm volatile("cp.async.wait_group 0;" ::: "memory")
#define CP_WAIT1()  asm volatile("cp.async.wait_group 1;" ::: "memory")

static __device__ __forceinline__ uint32_t pack2(h16 a, h16 b){
    return (uint32_t)__half_as_ushort(a) | ((uint32_t)__half_as_ushort(b) << 16);
}

// -------------------- all-weights fp16 convert (one launch) --------------------
__global__ __launch_bounds__(256) void convert_all(
    const float* __restrict__ w0, h16* __restrict__ o0,   // qkv_w: 442368 quads
    const float* __restrict__ w1, h16* __restrict__ o1,   // out_w: 147456
    const float* __restrict__ w2, h16* __restrict__ o2,   // fc1_w: 589824
    const float* __restrict__ w3, h16* __restrict__ o3)   // fc2_w: 589824
{
    int i = blockIdx.x * 256 + threadIdx.x;
    const float* w; h16* o; int j;
    if (i < 442368)       { w = w0; o = o0; j = i; }
    else if (i < 589824)  { w = w1; o = o1; j = i - 442368; }
    else if (i < 1179648) { w = w2; o = o2; j = i - 589824; }
    else if (i < 1769472) { w = w3; o = o3; j = i - 1179648; }
    else return;
    float4 v = reinterpret_cast<const float4*>(w)[j];
    uint2 r;
    r.x = pack2(__float2half_rn(v.x), __float2half_rn(v.y));
    r.y = pack2(__float2half_rn(v.z), __float2half_rn(v.w));
    reinterpret_cast<uint2*>(o)[j] = r;
}

// -------------------- layernorm -> fp16 --------------------
__global__ __launch_bounds__(256) void ln_h(const float* __restrict__ x,
                                            const float* __restrict__ w,
                                            const float* __restrict__ b,
                                            h16* __restrict__ y)
{
    __shared__ float red[256];
    int tid = threadIdx.x;
    const float* xr = x + (size_t)blockIdx.x * DD;
    h16* yr = y + (size_t)blockIdx.x * DD;
    float v0 = xr[tid], v1 = xr[tid + 256], v2 = xr[tid + 512];
    red[tid] = v0 + v1 + v2;
    __syncthreads();
    for (int off = 128; off; off >>= 1) {
        if (tid < off) red[tid] += red[tid + off];
        __syncthreads();
    }
    float mean = red[0] * (1.0f / DD);
    __syncthreads();
    float d0 = v0 - mean, d1 = v1 - mean, d2 = v2 - mean;
    red[tid] = d0*d0 + d1*d1 + d2*d2;
    __syncthreads();
    for (int off = 128; off; off >>= 1) {
        if (tid < off) red[tid] += red[tid + off];
        __syncthreads();
    }
    float rstd = rsqrtf(red[0] * (1.0f / DD) + 1e-5f);
    yr[tid]       = __float2half_rn(d0 * rstd * w[tid]       + b[tid]);
    yr[tid + 256] = __float2half_rn(d1 * rstd * w[tid + 256] + b[tid + 256]);
    yr[tid + 512] = __float2half_rn(d2 * rstd * w[tid + 512] + b[tid + 512]);
}

// -------------------- flash attention (fp16, causal) --------------------
// Grid: (SS/128 q-tiles reversed, BH). 8 warps, each 16 q-rows x 128-col KV tile.
// SMEM: Q [0,PL), K [PL,2PL), V [2PL,3PL); stride 144B/row. 2 CTAs/SM.
__global__ __launch_bounds__(256, 2) void flash_attn(
    const h16* __restrict__ qkv,
    h16* __restrict__ os)
{
    constexpr int STR = 144;
    constexpr int PL  = 128 * STR;       // 18432 per plane
    extern __shared__ __align__(128) char smem[];

    const int qt = gridDim.x - 1 - blockIdx.x;   // longest jobs first
    const int bh = blockIdx.y;
    const int b = bh / HH, h = bh % HH;
    const int tid = threadIdx.x, wid = tid >> 5, lane = tid & 31;
    const uint32_t sb = smem_u32(smem);

    const h16* Qb = qkv + (size_t)(b * SS + qt * 128) * (3 * DD) + h * HDD;
    const h16* Kb = qkv + (size_t)(b * SS) * (3 * DD) + DD + h * HDD;
    const h16* Vb = Kb + DD;

    auto loadQ = [&]() {
#pragma unroll
        for (int it = 0; it < 4; it++) {
            int idx = tid + it * 256;
            int r = idx >> 3, c = idx & 7;
            CP_ASYNC16(sb + r * STR + c * 16,
                       Qb + (size_t)r * (3 * DD) + c * 8);
        }
        CP_COMMIT();
    };
    auto loadK = [&](int j) {
#pragma unroll
        for (int it = 0; it < 4; it++) {
            int idx = tid + it * 256;
            int r = idx >> 3, c = idx & 7;
            CP_ASYNC16(sb + PL + r * STR + c * 16,
                       Kb + (size_t)(j * 128 + r) * (3 * DD) + c * 8);
        }
        CP_COMMIT();
    };
    auto loadV = [&](int j) {
#pragma unroll
        for (int it = 0; it < 4; it++) {
            int idx = tid + it * 256;
            int r = idx >> 3, c = idx & 7;
            CP_ASYNC16(sb + 2 * PL + r * STR + c * 16,
                       Vb + (size_t)(j * 128 + r) * (3 * DD) + c * 8);
        }
        CP_COMMIT();
    };

    loadQ();
    loadK(0);
    loadV(0);

    // softmax state: rows r0 = wid*16 + lane>>2, r1 = r0+8
    float mo0 = -1e30f, mo1 = -1e30f;
    float l0 = 0.f, l1 = 0.f;
    float oacc[8][4];
#pragma unroll
    for (int f = 0; f < 8; f++)
#pragma unroll
        for (int c = 0; c < 4; c++) oacc[f][c] = 0.f;

    const float SCL = 0.125f * 1.4426950408889634f;  // 1/sqrt(64) * log2(e)

    for (int j = 0; j <= qt; j++) {
        CP_WAIT1();            // Q (first iter) + K_j arrived
        __syncthreads();

        // ---- S = Q K^T ----
        float sacc[16][4];
#pragma unroll
        for (int f = 0; f < 16; f++)
#pragma unroll
            for (int c = 0; c < 4; c++) sacc[f][c] = 0.f;

#pragma unroll
        for (int ks = 0; ks < 4; ks++) {
            uint32_t aQ[4];
            uint32_t qaddr = sb + (wid * 16 + (lane & 15)) * STR + ks * 32 + ((lane >> 4) << 4);
            ldsm_x4(aQ, qaddr);
#pragma unroll
            for (int h8 = 0; h8 < 8; h8++) {
                uint32_t row = h8 * 16 + (lane & 7) + ((lane >> 4) << 3);
                uint32_t ch  = (lane >> 3) & 1;
                uint32_t ka  = sb + PL + row * STR + ks * 32 + ch * 16;
                uint32_t bK[4];
                ldsm_x4(bK, ka);
                mma16816(sacc[2*h8],   aQ, bK);
                mma16816(sacc[2*h8+1], aQ, bK + 2);
            }
        }

        // ---- online softmax (log2 domain) ----
        const bool diag = (j == qt);
        int rl0 = wid * 16 + (lane >> 2), rl1 = rl0 + 8;
        float mn0 = mo0, mn1 = mo1;
#pragma unroll
        for (int f = 0; f < 16; f++) {
            int cl = f * 8 + (lane & 3) * 2;
            float t0 = sacc[f][0] * SCL, t1 = sacc[f][1] * SCL;
            float t2 = sacc[f][2] * SCL, t3 = sacc[f][3] * SCL;
            if (diag) {
                if (cl     > rl0) t0 = -1e30f;
                if (cl + 1 > rl0) t1 = -1e30f;
                if (cl     > rl1) t2 = -1e30f;
                if (cl + 1 > rl1) t3 = -1e30f;
            }
            sacc[f][0] = t0; sacc[f][1] = t1; sacc[f][2] = t2; sacc[f][3] = t3;
            mn0 = fmaxf(mn0, fmaxf(t0, t1));
            mn1 = fmaxf(mn1, fmaxf(t2, t3));
        }
        mn0 = fmaxf(mn0, __shfl_xor_sync(0xffffffffu, mn0, 1));
        mn0 = fmaxf(mn0, __shfl_xor_sync(0xffffffffu, mn0, 2));
        mn1 = fmaxf(mn1, __shfl_xor_sync(0xffffffffu, mn1, 1));
        mn1 = fmaxf(mn1, __shfl_xor_sync(0xffffffffu, mn1, 2));

        float f0 = exp2f(mo0 - mn0), f1 = exp2f(mo1 - mn1);
        l0 *= f0; l1 *= f1;
#pragma unroll
        for (int f = 0; f < 8; f++) {
            oacc[f][0] *= f0; oacc[f][1] *= f0;
            oacc[f][2] *= f1; oacc[f][3] *= f1;
        }
        float s0 = 0.f, s1 = 0.f;
#pragma unroll
        for (int f = 0; f < 16; f++) {
            float p0 = exp2f(sacc[f][0] - mn0);
            float p1 = exp2f(sacc[f][1] - mn0);
            float p2 = exp2f(sacc[f][2] - mn1);
            float p3 = exp2f(sacc[f][3] - mn1);
            sacc[f][0] = p0; sacc[f][1] = p1; sacc[f][2] = p2; sacc[f][3] = p3;
            s0 += p0 + p1; s1 += p2 + p3;
        }
        // reduce row-sum across the 4-lane quad (R7 fix — keep!)
        s0 += __shfl_xor_sync(0xffffffffu, s0, 1);
        s0 += __shfl_xor_sync(0xffffffffu, s0, 2);
        s1 += __shfl_xor_sync(0xffffffffu, s1, 1);
        s1 += __shfl_xor_sync(0xffffffffu, s1, 2);
        l0 += s0; l1 += s1;
        mo0 = mn0; mo1 = mn1;

        // prefetch K_{j+1}, then guarantee V_j landed (R6 fix — keep!)
        __syncthreads();
        if (j < qt) {
            loadK(j + 1);
            CP_WAIT1();
        } else {
            CP_WAIT0();
        }
        __syncthreads();

        // ---- O += P V ----
#pragma unroll
        for (int kk = 0; kk < 8; kk++) {
            uint32_t aP[4];
#pragma unroll
            for (int half = 0; half < 2; half++) {
                const float* pr = sacc[2*kk + half];
                aP[half*2 + 0] = pack2(__float2half_rn(pr[0]), __float2half_rn(pr[1]));
                aP[half*2 + 1] = pack2(__float2half_rn(pr[2]), __float2half_rn(pr[3]));
            }
#pragma unroll
            for (int h4 = 0; h4 < 4; h4++) {
                uint32_t row = kk * 16 + (lane & 7) + (((lane >> 3) & 1) << 3);
                uint32_t col = h4 * 16 + ((lane >> 4) << 3);
                uint32_t va  = sb + 2 * PL + row * STR + col * 2;
                uint32_t bV[4];
                ldsm_x4t(bV, va);
                mma16816(oacc[2*h4],   aP, bV);
                mma16816(oacc[2*h4+1], aP, bV + 2);
            }
        }
        __syncthreads();
        if (j < qt) loadV(j + 1);
    }

    // ---- epilogue: O /= l, write fp16 ----
    float li0 = 1.0f / l0, li1 = 1.0f / l1;
    int m0r = b * SS + qt * 128 + wid * 16 + (lane >> 2);
    h16* oh = os + (size_t)m0r * DD + h * HDD;
#pragma unroll
    for (int f = 0; f < 8; f++) {
        int n = f * 8 + (lane & 3) * 2;
        *reinterpret_cast<uint32_t*>(oh + n) =
            pack2(__float2half_rn(oacc[f][0] * li0), __float2half_rn(oacc[f][1] * li0));
        *reinterpret_cast<uint32_t*>(oh + 8 * DD + n) =
            pack2(__float2half_rn(oacc[f][2] * li1), __float2half_rn(oacc[f][3] * li1));
    }
}

// -------------------- fp16 warp-MMA GEMM, BK=64, cp.async double-buffered -----
enum { EPI_BIAS = 0, EPI_BIASRES = 1, EPI_GELU = 2 };

template<int EPI, bool OUT_HALF>
__global__ __launch_bounds__(256, 2) void mma_gemm2(
    const h16* __restrict__ A, const h16* __restrict__ Bm,
    const float* __restrict__ bias, const float* __restrict__ resid,
    void* __restrict__ Cout,
    int K, int lda, int ldb, int ldc)
{
    constexpr int BM = 128, BN = 128, BK = 64;
    constexpr int ASTR = 144;            // 128B row + 16B pad (bank-rotating)
    constexpr int APL  = BM * ASTR;      // 18432
    constexpr int BSTR = 144;
    constexpr int BPL  = BN * BSTR;      // 18432
    constexpr int BUF  = APL + BPL;      // 36864
    constexpr int MF = 4, NF = 4;

    extern __shared__ __align__(128) char smem[];

    const int m0 = blockIdx.y * BM, n0 = blockIdx.x * BN;
    const int tid = threadIdx.x, wid = tid >> 5, lane = tid & 31;
    const int wm0 = (wid & 1) * 64;
    const int wn0 = (wid >> 1) * 32;
    const uint32_t sb = smem_u32(smem);

    float acc[MF][NF][4];
#pragma unroll
    for (int i = 0; i < MF; i++)
#pragma unroll
        for (int jj = 0; jj < NF; jj++)
#pragma unroll
            for (int c = 0; c < 4; c++) acc[i][jj][c] = 0.f;

    int NT = K / BK;

    auto load_tile = [&](int kt, int bsel) {
        uint32_t base = sb + bsel * BUF;
#pragma unroll
        for (int it = 0; it < 4; it++) {
            int idx = tid + it * 256;
            int r = idx >> 3, c = idx & 7;
            const h16* src = A + (size_t)(m0 + r) * lda + kt * BK + c * 8;
            CP_ASYNC16(base + r * ASTR + c * 16, src);
        }
#pragma unroll
        for (int it = 0; it < 4; it++) {
            int idx = tid + it * 256;
            int r = idx >> 3, c = idx & 7;
            const h16* src = Bm + (size_t)(n0 + r) * ldb + kt * BK + c * 8;
            CP_ASYNC16(base + APL + r * BSTR + c * 16, src);
        }
        CP_COMMIT();
    };

    load_tile(0, 0);

    for (int kt = 0; kt < NT; kt++) {
        int buf = kt & 1;
        CP_WAIT0();
        __syncthreads();
        if (kt + 1 < NT) load_tile(kt + 1, buf ^ 1);

        uint32_t base = sb + buf * BUF;
#pragma unroll
        for (int ks = 0; ks < 4; ks++) {
            uint32_t bB[NF][2];
#pragma unroll
            for (int hh = 0; hh < 2; hh++) {
                uint32_t row = wn0 + hh * 16 + (lane & 7) + ((lane >> 4) << 3);
                uint32_t ch  = (lane >> 3) & 1;
                uint32_t ad  = base + APL + row * BSTR + ks * 32 + ch * 16;
                uint32_t r4[4];
                ldsm_x4(r4, ad);
                bB[hh*2][0]=r4[0]; bB[hh*2][1]=r4[1]; bB[hh*2+1][0]=r4[2]; bB[hh*2+1][1]=r4[3];
            }
#pragma unroll
            for (int mf = 0; mf < MF; mf++) {
                uint32_t row = wm0 + mf * 16 + (lane & 15);
                uint32_t ch  = lane >> 4;
                uint32_t ad  = base + row * ASTR + ks * 32 + ch * 16;
                uint32_t aA[4];
                ldsm_x4(aA, ad);
#pragma unroll
                for (int nf = 0; nf < NF; nf++)
                    mma16816(acc[mf][nf], aA, bB[nf]);
            }
        }
        __syncthreads();
    }

    // -------- epilogue --------
#pragma unroll
    for (int mf = 0; mf < MF; mf++) {
#pragma unroll
        for (int half = 0; half < 2; half++) {
            int m = m0 + wm0 + mf * 16 + (lane >> 2) + half * 8;
#pragma unroll
            for (int nf = 0; nf < NF; nf++) {
                int n = n0 + wn0 + nf * 8 + (lane & 3) * 2;
                float v0 = acc[mf][nf][half*2 + 0];
                float v1 = acc[mf][nf][half*2 + 1];
                if (bias) { v0 += __ldg(&bias[n]); v1 += __ldg(&bias[n+1]); }
                if (EPI == EPI_GELU) {
                    v0 = 0.5f * v0 * (1.0f + erff(v0 * 0.70710678118654752f));
                    v1 = 0.5f * v1 * (1.0f + erff(v1 * 0.70710678118654752f));
                }
                if (EPI == EPI_BIASRES) {
                    const float* Rrow = resid + (size_t)m * ldc;
                    v0 += Rrow[n]; v1 += Rrow[n+1];
                }
                if (OUT_HALF) {
                    h16* Ch = (h16*)Cout + (size_t)m * ldc;
                    *reinterpret_cast<uint32_t*>(Ch + n) =
                        pack2(__float2half_rn(v0), __float2half_rn(v1));
                } else {
                    float* Crow = (float*)Cout + (size_t)m * ldc;
                    *reinterpret_cast<float2*>(Crow + n) = make_float2(v0, v1);
                }
            }
        }
    }
}

// -------------------- host launcher --------------------
extern "C" void kernel_launch(void* const* d_in, const int* in_sizes, int n_in,
                              void* d_out, int out_size)
{
    const float* x     = (const float*)d_in[0];
    const float* qkv_w = (const float*)d_in[2];
    const float* qkv_b = (const float*)d_in[3];
    const float* out_w = (const float*)d_in[4];
    const float* out_b = (const float*)d_in[5];
    const float* fc1_w = (const float*)d_in[6];
    const float* fc1_b = (const float*)d_in[7];
    const float* fc2_w = (const float*)d_in[8];
    const float* fc2_b = (const float*)d_in[9];
    const float* ln1_w = (const float*)d_in[10];
    const float* ln1_b = (const float*)d_in[11];
    const float* ln2_w = (const float*)d_in[12];
    const float* ln2_b = (const float*)d_in[13];
    float* out = (float*)d_out;

    void *p0,*p1,*p4,*p5,*p6,*p7,*p8,*p9,*p10,*p11;
    cudaGetSymbolAddress(&p0,  g_hx);
    cudaGetSymbolAddress(&p1,  g_qkv);
    cudaGetSymbolAddress(&p4,  g_o);
    cudaGetSymbolAddress(&p5,  g_x1);
    cudaGetSymbolAddress(&p6,  g_h2);
    cudaGetSymbolAddress(&p7,  g_ff1);
    cudaGetSymbolAddress(&p8,  g_qkvw);
    cudaGetSymbolAddress(&p9,  g_outw);
    cudaGetSymbolAddress(&p10, g_fc1w);
    cudaGetSymbolAddress(&p11, g_fc2w);
    h16* hx   = (h16*)p0;  h16* qkv  = (h16*)p1;
    h16* o    = (h16*)p4;  float* x1 = (float*)p5;
    h16* h2   = (h16*)p6;  h16* ff1  = (h16*)p7;
    h16* qkvw = (h16*)p8;  h16* outw = (h16*)p9;
    h16* fc1w = (h16*)p10; h16* fc2w = (h16*)p11;

    const int SMEM_GEMM = 2 * 36864;     // 73728 (x2 CTAs = 147KB/SM)
    const int SMEM_FA   = 3 * 128 * 144; // 55296 (x2 CTAs = 110KB/SM)

    cudaFuncSetAttribute(mma_gemm2<EPI_BIAS,   true >,
                         cudaFuncAttributeMaxDynamicSharedMemorySize, SMEM_GEMM);
    cudaFuncSetAttribute(mma_gemm2<EPI_BIASRES,false>,
                         cudaFuncAttributeMaxDynamicSharedMemorySize, SMEM_GEMM);
    cudaFuncSetAttribute(mma_gemm2<EPI_GELU,   true >,
                         cudaFuncAttributeMaxDynamicSharedMemorySize, SMEM_GEMM);
    cudaFuncSetAttribute(flash_attn,
                         cudaFuncAttributeMaxDynamicSharedMemorySize, SMEM_FA);

    // 0. all weight converts in one launch (1769472 quads)
    convert_all<<<(1769472 + 255)/256, 256>>>(qkv_w, qkvw, out_w, outw,
                                              fc1_w, fc1w, fc2_w, fc2w);

    // 1. ln1 -> hx fp16
    ln_h<<<ROWS, 256>>>(x, ln1_w, ln1_b, hx);

    // 2. QKV: [4096,768] x [2304,768]^T -> qkv fp16
    mma_gemm2<EPI_BIAS,true>
        <<<dim3(3*DD/128, ROWS/128, 1), 256, SMEM_GEMM>>>(
            hx, qkvw, qkv_b, nullptr, qkv,
            DD, DD, DD, 3*DD);

    // 3-5. flash attention -> o fp16
    flash_attn<<<dim3(SS/128, BH), 256, SMEM_FA>>>(qkv, o);

    // 6. x1 = x + O @ out_w^T + out_b   (fp32 out)
    mma_gemm2<EPI_BIASRES,false>
        <<<dim3(DD/128, ROWS/128, 1), 256, SMEM_GEMM>>>(
            o, outw, out_b, x, x1,
            DD, DD, DD, DD);

    // 7. ln2 -> h2 fp16
    ln_h<<<ROWS, 256>>>(x1, ln2_w, ln2_b, h2);

    // 8. ff1 = gelu(h2 @ fc1_w^T + fc1_b) -> fp16
    mma_gemm2<EPI_GELU,true>
        <<<dim3(FF/128, ROWS/128, 1), 256, SMEM_GEMM>>>(
            h2, fc1w, fc1_b, nullptr, ff1,
            DD, DD, DD, FF);

    // 9. out = x1 + ff1 @ fc2_w^T + fc2_b   (fp32 out)
    mma_gemm2<EPI_BIASRES,false>
        <<<dim3(DD/128, ROWS/128, 1), 256, SMEM_GEMM>>>(
            ff1, fc2w, fc2_b, x1, out,
            FF, FF, FF, DD);
}

// round 12
// speedup vs baseline: 7.0154x; 1.0183x over previous
#include <cuda_runtime.h>
#include <cuda_fp16.h>
#include <math.h>
#include <stdint.h>

typedef __half h16;

// Problem constants
#define BB 2
#define SS 2048
#define DD 768
#define HH 12
#define FF 3072
#define HDD 64
#define ROWS (BB*SS)          // 4096
#define BH (BB*HH)            // 24

// -------------------- device scratch (single fp16 activations) --------------------
__device__ __align__(16) h16  g_hx  [ROWS*DD];
__device__ __align__(16) h16  g_qkv [ROWS*3*DD];
__device__ __align__(16) h16  g_o   [ROWS*DD];
__device__ __align__(16) float g_x1 [ROWS*DD];
__device__ __align__(16) h16  g_h2  [ROWS*DD];
__device__ __align__(16) h16  g_ff1 [ROWS*FF];
__device__ __align__(16) h16  g_qkvw[3*DD*DD];
__device__ __align__(16) h16  g_outw[DD*DD];
__device__ __align__(16) h16  g_fc1w[FF*DD];
__device__ __align__(16) h16  g_fc2w[DD*FF];

// -------------------- helpers --------------------
__device__ __forceinline__ uint32_t smem_u32(const void* p){
    uint32_t a;
    asm("{ .reg .u64 t; cvta.to.shared.u64 t, %1; cvt.u32.u64 %0, t; }"
        : "=r"(a) : "l"(p));
    return a;
}
__device__ __forceinline__ void ldsm_x4(uint32_t* r, uint32_t a){
    asm volatile("ldmatrix.sync.aligned.m8n8.x4.shared.b16 {%0,%1,%2,%3}, [%4];"
        : "=r"(r[0]),"=r"(r[1]),"=r"(r[2]),"=r"(r[3]) : "r"(a));
}
__device__ __forceinline__ void ldsm_x4t(uint32_t* r, uint32_t a){
    asm volatile("ldmatrix.sync.aligned.m8n8.x4.trans.shared.b16 {%0,%1,%2,%3}, [%4];"
        : "=r"(r[0]),"=r"(r[1]),"=r"(r[2]),"=r"(r[3]) : "r"(a));
}
__device__ __forceinline__ void mma16816(float* c, const uint32_t* a, const uint32_t* b){
    asm volatile(
        "mma.sync.aligned.m16n8k16.row.col.f32.f16.f16.f32 "
        "{%0,%1,%2,%3}, {%4,%5,%6,%7}, {%8,%9}, {%0,%1,%2,%3};"
        : "+f"(c[0]),"+f"(c[1]),"+f"(c[2]),"+f"(c[3])
        : "r"(a[0]),"r"(a[1]),"r"(a[2]),"r"(a[3]), "r"(b[0]),"r"(b[1]));
}
#define CP_ASYNC16(dst, src) \
    asm volatile("cp.async.cg.shared.global [%0], [%1], 16;" :: "r"(dst), "l"(src))
#define CP_COMMIT() asm volatile("cp.async.commit_group;" ::: "memory")
#define CP_WAIT0()  asm volatile("cp.async.wait_group 0;" ::: "memory")

static __device__ __forceinline__ uint32_t pack2(h16 a, h16 b){
    return (uint32_t)__half_as_ushort(a) | ((uint32_t)__half_as_ushort(b) << 16);
}
static __device__ __forceinline__ uint32_t packf2(float a, float b){
    __half2 h = __floats2half2_rn(a, b);
    return *reinterpret_cast<uint32_t*>(&h);
}

#define SCLQ 0.18033688011112042f   // 0.125 * log2(e), folded into Q at QKV epilogue

// -------------------- all-weights fp16 convert (one launch) --------------------
__global__ __launch_bounds__(256) void convert_all(
    const float* __restrict__ w0, h16* __restrict__ o0,
    const float* __restrict__ w1, h16* __restrict__ o1,
    const float* __restrict__ w2, h16* __restrict__ o2,
    const float* __restrict__ w3, h16* __restrict__ o3)
{
    int i = blockIdx.x * 256 + threadIdx.x;
    const float* w; h16* o; int j;
    if (i < 442368)       { w = w0; o = o0; j = i; }
    else if (i < 589824)  { w = w1; o = o1; j = i - 442368; }
    else if (i < 1179648) { w = w2; o = o2; j = i - 589824; }
    else if (i < 1769472) { w = w3; o = o3; j = i - 1179648; }
    else return;
    float4 v = reinterpret_cast<const float4*>(w)[j];
    uint2 r;
    r.x = packf2(v.x, v.y);
    r.y = packf2(v.z, v.w);
    reinterpret_cast<uint2*>(o)[j] = r;
}

// -------------------- layernorm -> fp16 --------------------
__global__ __launch_bounds__(256) void ln_h(const float* __restrict__ x,
                                            const float* __restrict__ w,
                                            const float* __restrict__ b,
                                            h16* __restrict__ y)
{
    __shared__ float red[256];
    int tid = threadIdx.x;
    const float* xr = x + (size_t)blockIdx.x * DD;
    h16* yr = y + (size_t)blockIdx.x * DD;
    float v0 = xr[tid], v1 = xr[tid + 256], v2 = xr[tid + 512];
    red[tid] = v0 + v1 + v2;
    __syncthreads();
    for (int off = 128; off; off >>= 1) {
        if (tid < off) red[tid] += red[tid + off];
        __syncthreads();
    }
    float mean = red[0] * (1.0f / DD);
    __syncthreads();
    float d0 = v0 - mean, d1 = v1 - mean, d2 = v2 - mean;
    red[tid] = d0*d0 + d1*d1 + d2*d2;
    __syncthreads();
    for (int off = 128; off; off >>= 1) {
        if (tid < off) red[tid] += red[tid + off];
        __syncthreads();
    }
    float rstd = rsqrtf(red[0] * (1.0f / DD) + 1e-5f);
    yr[tid]       = __float2half_rn(d0 * rstd * w[tid]       + b[tid]);
    yr[tid + 256] = __float2half_rn(d1 * rstd * w[tid + 256] + b[tid + 256]);
    yr[tid + 512] = __float2half_rn(d2 * rstd * w[tid + 512] + b[tid + 512]);
}

// -------------------- flash attention (fp16, causal, V dbl-buffered) ----------
// Grid: (SS/128 q-tiles reversed, BH). 8 warps, each 16 q-rows x 128-col KV tile.
// SMEM planes (128 x 144B): Q | K | V0 | V1.  Q pre-scaled by 0.125*log2e.
__global__ __launch_bounds__(256) void flash_attn(
    const h16* __restrict__ qkv,
    h16* __restrict__ os)
{
    constexpr int STR = 144;
    constexpr int PL  = 128 * STR;       // 18432 per plane
    extern __shared__ __align__(128) char smem[];

    const int qt = gridDim.x - 1 - blockIdx.x;   // longest jobs first
    const int bh = blockIdx.y;
    const int b = bh / HH, h = bh % HH;
    const int tid = threadIdx.x, wid = tid >> 5, lane = tid & 31;
    const uint32_t sb = smem_u32(smem);

    const h16* Qb = qkv + (size_t)(b * SS + qt * 128) * (3 * DD) + h * HDD;
    const h16* Kb = qkv + (size_t)(b * SS) * (3 * DD) + DD + h * HDD;
    const h16* Vb = Kb + DD;

    auto loadQ = [&]() {
#pragma unroll
        for (int it = 0; it < 4; it++) {
            int idx = tid + it * 256;
            int r = idx >> 3, c = idx & 7;
            CP_ASYNC16(sb + r * STR + c * 16,
                       Qb + (size_t)r * (3 * DD) + c * 8);
        }
        CP_COMMIT();
    };
    // K_j -> plane 1; V_j -> plane (2+vb). One commit group.
    auto loadKV = [&](int j, int vb) {
#pragma unroll
        for (int it = 0; it < 4; it++) {
            int idx = tid + it * 256;
            int r = idx >> 3, c = idx & 7;
            CP_ASYNC16(sb + PL + r * STR + c * 16,
                       Kb + (size_t)(j * 128 + r) * (3 * DD) + c * 8);
        }
#pragma unroll
        for (int it = 0; it < 4; it++) {
            int idx = tid + it * 256;
            int r = idx >> 3, c = idx & 7;
            CP_ASYNC16(sb + (2 + vb) * PL + r * STR + c * 16,
                       Vb + (size_t)(j * 128 + r) * (3 * DD) + c * 8);
        }
        CP_COMMIT();
    };

    loadQ();
    loadKV(0, 0);

    // softmax state: rows r0 = wid*16 + lane>>2, r1 = r0+8
    float mo0 = -1e30f, mo1 = -1e30f;
    float l0 = 0.f, l1 = 0.f;
    float oacc[8][4];
#pragma unroll
    for (int f = 0; f < 8; f++)
#pragma unroll
        for (int c = 0; c < 4; c++) oacc[f][c] = 0.f;

    for (int j = 0; j <= qt; j++) {
        const int vb = j & 1;
        CP_WAIT0();            // KV_j (and Q on first iter) arrived
        __syncthreads();       // cross-thread visibility

        // ---- S = Q K^T   (Q pre-scaled: sacc already in log2-exp domain) ----
        float sacc[16][4];
#pragma unroll
        for (int f = 0; f < 16; f++)
#pragma unroll
            for (int c = 0; c < 4; c++) sacc[f][c] = 0.f;

#pragma unroll
        for (int ks = 0; ks < 4; ks++) {
            uint32_t aQ[4];
            uint32_t qaddr = sb + (wid * 16 + (lane & 15)) * STR + ks * 32 + ((lane >> 4) << 4);
            ldsm_x4(aQ, qaddr);
#pragma unroll
            for (int h8 = 0; h8 < 8; h8++) {
                uint32_t row = h8 * 16 + (lane & 7) + ((lane >> 4) << 3);
                uint32_t ch  = (lane >> 3) & 1;
                uint32_t ka  = sb + PL + row * STR + ks * 32 + ch * 16;
                uint32_t bK[4];
                ldsm_x4(bK, ka);
                mma16816(sacc[2*h8],   aQ, bK);
                mma16816(sacc[2*h8+1], aQ, bK + 2);
            }
        }

        // ---- online softmax (log2 domain; no scale multiply needed) ----
        const bool diag = (j == qt);
        int rl0 = wid * 16 + (lane >> 2), rl1 = rl0 + 8;
        float mn0 = mo0, mn1 = mo1;
#pragma unroll
        for (int f = 0; f < 16; f++) {
            int cl = f * 8 + (lane & 3) * 2;
            float t0 = sacc[f][0], t1 = sacc[f][1];
            float t2 = sacc[f][2], t3 = sacc[f][3];
            if (diag) {
                if (cl     > rl0) t0 = -1e30f;
                if (cl + 1 > rl0) t1 = -1e30f;
                if (cl     > rl1) t2 = -1e30f;
                if (cl + 1 > rl1) t3 = -1e30f;
            }
            sacc[f][0] = t0; sacc[f][1] = t1; sacc[f][2] = t2; sacc[f][3] = t3;
            mn0 = fmaxf(mn0, fmaxf(t0, t1));
            mn1 = fmaxf(mn1, fmaxf(t2, t3));
        }
        mn0 = fmaxf(mn0, __shfl_xor_sync(0xffffffffu, mn0, 1));
        mn0 = fmaxf(mn0, __shfl_xor_sync(0xffffffffu, mn0, 2));
        mn1 = fmaxf(mn1, __shfl_xor_sync(0xffffffffu, mn1, 1));
        mn1 = fmaxf(mn1, __shfl_xor_sync(0xffffffffu, mn1, 2));

        float f0 = exp2f(mo0 - mn0), f1 = exp2f(mo1 - mn1);
        l0 *= f0; l1 *= f1;
#pragma unroll
        for (int f = 0; f < 8; f++) {
            oacc[f][0] *= f0; oacc[f][1] *= f0;
            oacc[f][2] *= f1; oacc[f][3] *= f1;
        }
        float s0 = 0.f, s1 = 0.f;
#pragma unroll
        for (int f = 0; f < 16; f++) {
            float p0 = exp2f(sacc[f][0] - mn0);
            float p1 = exp2f(sacc[f][1] - mn0);
            float p2 = exp2f(sacc[f][2] - mn1);
            float p3 = exp2f(sacc[f][3] - mn1);
            sacc[f][0] = p0; sacc[f][1] = p1; sacc[f][2] = p2; sacc[f][3] = p3;
            s0 += p0 + p1; s1 += p2 + p3;
        }
        // quad row-sum reduction (R7 fix — keep!)
        s0 += __shfl_xor_sync(0xffffffffu, s0, 1);
        s0 += __shfl_xor_sync(0xffffffffu, s0, 2);
        s1 += __shfl_xor_sync(0xffffffffu, s1, 1);
        s1 += __shfl_xor_sync(0xffffffffu, s1, 2);
        l0 += s0; l1 += s1;
        mo0 = mn0; mo1 = mn1;

        // all warps past QK (K_j free) and past PV_{j-1} (V buffer vb^1 free)
        __syncthreads();
        if (j < qt) loadKV(j + 1, vb ^ 1);

        // ---- O += P V_j  (V_j resident since top-of-loop wait; no stall) ----
#pragma unroll
        for (int kk = 0; kk < 8; kk++) {
            uint32_t aP[4];
#pragma unroll
            for (int half = 0; half < 2; half++) {
                const float* pr = sacc[2*kk + half];
                aP[half*2 + 0] = packf2(pr[0], pr[1]);
                aP[half*2 + 1] = packf2(pr[2], pr[3]);
            }
#pragma unroll
            for (int h4 = 0; h4 < 4; h4++) {
                uint32_t row = kk * 16 + (lane & 7) + (((lane >> 3) & 1) << 3);
                uint32_t col = h4 * 16 + ((lane >> 4) << 3);
                uint32_t va  = sb + (2 + vb) * PL + row * STR + col * 2;
                uint32_t bV[4];
                ldsm_x4t(bV, va);
                mma16816(oacc[2*h4],   aP, bV);
                mma16816(oacc[2*h4+1], aP, bV + 2);
            }
        }
    }

    // ---- epilogue: O /= l, write fp16 ----
    float li0 = 1.0f / l0, li1 = 1.0f / l1;
    int m0r = b * SS + qt * 128 + wid * 16 + (lane >> 2);
    h16* oh = os + (size_t)m0r * DD + h * HDD;
#pragma unroll
    for (int f = 0; f < 8; f++) {
        int n = f * 8 + (lane & 3) * 2;
        *reinterpret_cast<uint32_t*>(oh + n) =
            packf2(oacc[f][0] * li0, oacc[f][1] * li0);
        *reinterpret_cast<uint32_t*>(oh + 8 * DD + n) =
            packf2(oacc[f][2] * li1, oacc[f][3] * li1);
    }
}

// -------------------- fp16 warp-MMA GEMM, BK=64, cp.async double-buffered -----
enum { EPI_QKV = 0, EPI_BIASRES = 1, EPI_GELU = 2 };

template<int EPI, bool OUT_HALF>
__global__ __launch_bounds__(256, 2) void mma_gemm2(
    const h16* __restrict__ A, const h16* __restrict__ Bm,
    const float* __restrict__ bias, const float* __restrict__ resid,
    void* __restrict__ Cout,
    int K, int lda, int ldb, int ldc)
{
    constexpr int BM = 128, BN = 128, BK = 64;
    constexpr int ASTR = 144;
    constexpr int APL  = BM * ASTR;      // 18432
    constexpr int BSTR = 144;
    constexpr int BPL  = BN * BSTR;      // 18432
    constexpr int BUF  = APL + BPL;      // 36864
    constexpr int MF = 4, NF = 4;

    extern __shared__ __align__(128) char smem[];

    const int m0 = blockIdx.y * BM, n0 = blockIdx.x * BN;
    const int tid = threadIdx.x, wid = tid >> 5, lane = tid & 31;
    const int wm0 = (wid & 1) * 64;
    const int wn0 = (wid >> 1) * 32;
    const uint32_t sb = smem_u32(smem);

    float acc[MF][NF][4];
#pragma unroll
    for (int i = 0; i < MF; i++)
#pragma unroll
        for (int jj = 0; jj < NF; jj++)
#pragma unroll
            for (int c = 0; c < 4; c++) acc[i][jj][c] = 0.f;

    int NT = K / BK;

    auto load_tile = [&](int kt, int bsel) {
        uint32_t base = sb + bsel * BUF;
#pragma unroll
        for (int it = 0; it < 4; it++) {
            int idx = tid + it * 256;
            int r = idx >> 3, c = idx & 7;
            const h16* src = A + (size_t)(m0 + r) * lda + kt * BK + c * 8;
            CP_ASYNC16(base + r * ASTR + c * 16, src);
        }
#pragma unroll
        for (int it = 0; it < 4; it++) {
            int idx = tid + it * 256;
            int r = idx >> 3, c = idx & 7;
            const h16* src = Bm + (size_t)(n0 + r) * ldb + kt * BK + c * 8;
            CP_ASYNC16(base + APL + r * BSTR + c * 16, src);
        }
        CP_COMMIT();
    };

    load_tile(0, 0);

    for (int kt = 0; kt < NT; kt++) {
        int buf = kt & 1;
        CP_WAIT0();
        __syncthreads();
        if (kt + 1 < NT) load_tile(kt + 1, buf ^ 1);

        uint32_t base = sb + buf * BUF;
#pragma unroll
        for (int ks = 0; ks < 4; ks++) {
            uint32_t bB[NF][2];
#pragma unroll
            for (int hh = 0; hh < 2; hh++) {
                uint32_t row = wn0 + hh * 16 + (lane & 7) + ((lane >> 4) << 3);
                uint32_t ch  = (lane >> 3) & 1;
                uint32_t ad  = base + APL + row * BSTR + ks * 32 + ch * 16;
                uint32_t r4[4];
                ldsm_x4(r4, ad);
                bB[hh*2][0]=r4[0]; bB[hh*2][1]=r4[1]; bB[hh*2+1][0]=r4[2]; bB[hh*2+1][1]=r4[3];
            }
#pragma unroll
            for (int mf = 0; mf < MF; mf++) {
                uint32_t row = wm0 + mf * 16 + (lane & 15);
                uint32_t ch  = lane >> 4;
                uint32_t ad  = base + row * ASTR + ks * 32 + ch * 16;
                uint32_t aA[4];
                ldsm_x4(aA, ad);
#pragma unroll
                for (int nf = 0; nf < NF; nf++)
                    mma16816(acc[mf][nf], aA, bB[nf]);
            }
        }
        __syncthreads();
    }

    // -------- epilogue --------
#pragma unroll
    for (int mf = 0; mf < MF; mf++) {
#pragma unroll
        for (int half = 0; half < 2; half++) {
            int m = m0 + wm0 + mf * 16 + (lane >> 2) + half * 8;
#pragma unroll
            for (int nf = 0; nf < NF; nf++) {
                int n = n0 + wn0 + nf * 8 + (lane & 3) * 2;
                float v0 = acc[mf][nf][half*2 + 0];
                float v1 = acc[mf][nf][half*2 + 1];
                if (bias) { v0 += __ldg(&bias[n]); v1 += __ldg(&bias[n+1]); }
                if (EPI == EPI_QKV) {
                    // pre-scale Q columns by 0.125*log2(e) for flash log2-softmax
                    if (n < DD)     v0 *= SCLQ;
                    if (n + 1 < DD) v1 *= SCLQ;
                }
                if (EPI == EPI_GELU) {
                    v0 = 0.5f * v0 * (1.0f + erff(v0 * 0.70710678118654752f));
                    v1 = 0.5f * v1 * (1.0f + erff(v1 * 0.70710678118654752f));
                }
                if (EPI == EPI_BIASRES) {
                    const float* Rrow = resid + (size_t)m * ldc;
                    v0 += Rrow[n]; v1 += Rrow[n+1];
                }
                if (OUT_HALF) {
                    h16* Ch = (h16*)Cout + (size_t)m * ldc;
                    *reinterpret_cast<uint32_t*>(Ch + n) = packf2(v0, v1);
                } else {
                    float* Crow = (float*)Cout + (size_t)m * ldc;
                    *reinterpret_cast<float2*>(Crow + n) = make_float2(v0, v1);
                }
            }
        }
    }
}

// -------------------- host launcher --------------------
extern "C" void kernel_launch(void* const* d_in, const int* in_sizes, int n_in,
                              void* d_out, int out_size)
{
    const float* x     = (const float*)d_in[0];
    const float* qkv_w = (const float*)d_in[2];
    const float* qkv_b = (const float*)d_in[3];
    const float* out_w = (const float*)d_in[4];
    const float* out_b = (const float*)d_in[5];
    const float* fc1_w = (const float*)d_in[6];
    const float* fc1_b = (const float*)d_in[7];
    const float* fc2_w = (const float*)d_in[8];
    const float* fc2_b = (const float*)d_in[9];
    const float* ln1_w = (const float*)d_in[10];
    const float* ln1_b = (const float*)d_in[11];
    const float* ln2_w = (const float*)d_in[12];
    const float* ln2_b = (const float*)d_in[13];
    float* out = (float*)d_out;

    void *p0,*p1,*p4,*p5,*p6,*p7,*p8,*p9,*p10,*p11;
    cudaGetSymbolAddress(&p0,  g_hx);
    cudaGetSymbolAddress(&p1,  g_qkv);
    cudaGetSymbolAddress(&p4,  g_o);
    cudaGetSymbolAddress(&p5,  g_x1);
    cudaGetSymbolAddress(&p6,  g_h2);
    cudaGetSymbolAddress(&p7,  g_ff1);
    cudaGetSymbolAddress(&p8,  g_qkvw);
    cudaGetSymbolAddress(&p9,  g_outw);
    cudaGetSymbolAddress(&p10, g_fc1w);
    cudaGetSymbolAddress(&p11, g_fc2w);
    h16* hx   = (h16*)p0;  h16* qkv  = (h16*)p1;
    h16* o    = (h16*)p4;  float* x1 = (float*)p5;
    h16* h2   = (h16*)p6;  h16* ff1  = (h16*)p7;
    h16* qkvw = (h16*)p8;  h16* outw = (h16*)p9;
    h16* fc1w = (h16*)p10; h16* fc2w = (h16*)p11;

    const int SMEM_GEMM = 2 * 36864;     // 73728 (x2 CTAs = 147KB/SM)
    const int SMEM_FA   = 4 * 128 * 144; // 73728 (Q,K,V0,V1)

    cudaFuncSetAttribute(mma_gemm2<EPI_QKV,    true >,
                         cudaFuncAttributeMaxDynamicSharedMemorySize, SMEM_GEMM);
    cudaFuncSetAttribute(mma_gemm2<EPI_BIASRES,false>,
                         cudaFuncAttributeMaxDynamicSharedMemorySize, SMEM_GEMM);
    cudaFuncSetAttribute(mma_gemm2<EPI_GELU,   true >,
                         cudaFuncAttributeMaxDynamicSharedMemorySize, SMEM_GEMM);
    cudaFuncSetAttribute(flash_attn,
                         cudaFuncAttributeMaxDynamicSharedMemorySize, SMEM_FA);

    // 0. all weight converts in one launch
    convert_all<<<(1769472 + 255)/256, 256>>>(qkv_w, qkvw, out_w, outw,
                                              fc1_w, fc1w, fc2_w, fc2w);

    // 1. ln1 -> hx fp16
    ln_h<<<ROWS, 256>>>(x, ln1_w, ln1_b, hx);

    // 2. QKV (Q pre-scaled in epilogue)
    mma_gemm2<EPI_QKV,true>
        <<<dim3(3*DD/128, ROWS/128, 1), 256, SMEM_GEMM>>>(
            hx, qkvw, qkv_b, nullptr, qkv,
            DD, DD, DD, 3*DD);

    // 3-5. flash attention -> o fp16
    flash_attn<<<dim3(SS/128, BH), 256, SMEM_FA>>>(qkv, o);

    // 6. x1 = x + O @ out_w^T + out_b   (fp32 out)
    mma_gemm2<EPI_BIASRES,false>
        <<<dim3(DD/128, ROWS/128, 1), 256, SMEM_GEMM>>>(
            o, outw, out_b, x, x1,
            DD, DD, DD, DD);

    // 7. ln2 -> h2 fp16
    ln_h<<<ROWS, 256>>>(x1, ln2_w, ln2_b, h2);

    // 8. ff1 = gelu(h2 @ fc1_w^T + fc1_b) -> fp16
    mma_gemm2<EPI_GELU,true>
        <<<dim3(FF/128, ROWS/128, 1), 256, SMEM_GEMM>>>(
            h2, fc1w, fc1_b, nullptr, ff1,
            DD, DD, DD, FF);

    // 9. out = x1 + ff1 @ fc2_w^T + fc2_b   (fp32 out)
    mma_gemm2<EPI_BIASRES,false>
        <<<dim3(DD/128, ROWS/128, 1), 256, SMEM_GEMM>>>(
            ff1, fc2w, fc2_b, x1, out,
            FF, FF, FF, DD);
}

// round 13
// speedup vs baseline: 7.1045x; 1.0127x over previous
#include <cuda_runtime.h>
#include <cuda_fp16.h>
#include <math.h>
#include <stdint.h>

typedef __half h16;

// Problem constants
#define BB 2
#define SS 2048
#define DD 768
#define HH 12
#define FF 3072
#define HDD 64
#define ROWS (BB*SS)          // 4096
#define BH (BB*HH)            // 24

// -------------------- device scratch (single fp16 activations) --------------------
__device__ __align__(16) h16  g_hx  [ROWS*DD];
__device__ __align__(16) h16  g_qkv [ROWS*3*DD];
__device__ __align__(16) h16  g_o   [ROWS*DD];
__device__ __align__(16) float g_x1 [ROWS*DD];
__device__ __align__(16) h16  g_h2  [ROWS*DD];
__device__ __align__(16) h16  g_ff1 [ROWS*FF];
__device__ __align__(16) h16  g_qkvw[3*DD*DD];
__device__ __align__(16) h16  g_outw[DD*DD];
__device__ __align__(16) h16  g_fc1w[FF*DD];
__device__ __align__(16) h16  g_fc2w[DD*FF];

// -------------------- helpers --------------------
__device__ __forceinline__ uint32_t smem_u32(const void* p){
    uint32_t a;
    asm("{ .reg .u64 t; cvta.to.shared.u64 t, %1; cvt.u32.u64 %0, t; }"
        : "=r"(a) : "l"(p));
    return a;
}
__device__ __forceinline__ void ldsm_x4(uint32_t* r, uint32_t a){
    asm volatile("ldmatrix.sync.aligned.m8n8.x4.shared.b16 {%0,%1,%2,%3}, [%4];"
        : "=r"(r[0]),"=r"(r[1]),"=r"(r[2]),"=r"(r[3]) : "r"(a));
}
__device__ __forceinline__ void ldsm_x4t(uint32_t* r, uint32_t a){
    asm volatile("ldmatrix.sync.aligned.m8n8.x4.trans.shared.b16 {%0,%1,%2,%3}, [%4];"
        : "=r"(r[0]),"=r"(r[1]),"=r"(r[2]),"=r"(r[3]) : "r"(a));
}
__device__ __forceinline__ void mma16816(float* c, const uint32_t* a, const uint32_t* b){
    asm volatile(
        "mma.sync.aligned.m16n8k16.row.col.f32.f16.f16.f32 "
        "{%0,%1,%2,%3}, {%4,%5,%6,%7}, {%8,%9}, {%0,%1,%2,%3};"
        : "+f"(c[0]),"+f"(c[1]),"+f"(c[2]),"+f"(c[3])
        : "r"(a[0]),"r"(a[1]),"r"(a[2]),"r"(a[3]), "r"(b[0]),"r"(b[1]));
}
#define CP_ASYNC16(dst, src) \
    asm volatile("cp.async.cg.shared.global [%0], [%1], 16;" :: "r"(dst), "l"(src))
#define CP_COMMIT() asm volatile("cp.async.commit_group;" ::: "memory")
#define CP_WAIT0()  asm volatile("cp.async.wait_group 0;" ::: "memory")

static __device__ __forceinline__ uint32_t packf2(float a, float b){
    __half2 h = __floats2half2_rn(a, b);
    return *reinterpret_cast<uint32_t*>(&h);
}
static __device__ __forceinline__ __half2 u2h2(uint32_t u){
    return *reinterpret_cast<__half2*>(&u);
}
static __device__ __forceinline__ uint32_t h2u2(__half2 h){
    return *reinterpret_cast<uint32_t*>(&h);
}

#define SCLQ 0.18033688011112042f   // 0.125 * log2(e), folded into Q at QKV epilogue

// -------------------- fused weight convert + ln1 (one launch) --------------------
// blocks [0, 6912): weight fp32->fp16 convert; blocks [6912, 6912+4096): ln1 rows.
__global__ __launch_bounds__(256) void prep_all(
    const float* __restrict__ w0, h16* __restrict__ o0,
    const float* __restrict__ w1, h16* __restrict__ o1,
    const float* __restrict__ w2, h16* __restrict__ o2,
    const float* __restrict__ w3, h16* __restrict__ o3,
    const float* __restrict__ x,  const float* __restrict__ lw,
    const float* __restrict__ lb, h16* __restrict__ y)
{
    __shared__ float red[256];
    int tid = threadIdx.x;
    if (blockIdx.x < 6912) {
        int i = blockIdx.x * 256 + tid;
        const float* w; h16* o; int j;
        if (i < 442368)       { w = w0; o = o0; j = i; }
        else if (i < 589824)  { w = w1; o = o1; j = i - 442368; }
        else if (i < 1179648) { w = w2; o = o2; j = i - 589824; }
        else                  { w = w3; o = o3; j = i - 1179648; }
        float4 v = reinterpret_cast<const float4*>(w)[j];
        uint2 r;
        r.x = packf2(v.x, v.y);
        r.y = packf2(v.z, v.w);
        reinterpret_cast<uint2*>(o)[j] = r;
        return;
    }
    int row = blockIdx.x - 6912;
    const float* xr = x + (size_t)row * DD;
    h16* yr = y + (size_t)row * DD;
    float v0 = xr[tid], v1 = xr[tid + 256], v2 = xr[tid + 512];
    red[tid] = v0 + v1 + v2;
    __syncthreads();
    for (int off = 128; off; off >>= 1) {
        if (tid < off) red[tid] += red[tid + off];
        __syncthreads();
    }
    float mean = red[0] * (1.0f / DD);
    __syncthreads();
    float d0 = v0 - mean, d1 = v1 - mean, d2 = v2 - mean;
    red[tid] = d0*d0 + d1*d1 + d2*d2;
    __syncthreads();
    for (int off = 128; off; off >>= 1) {
        if (tid < off) red[tid] += red[tid + off];
        __syncthreads();
    }
    float rstd = rsqrtf(red[0] * (1.0f / DD) + 1e-5f);
    yr[tid]       = __float2half_rn(d0 * rstd * lw[tid]       + lb[tid]);
    yr[tid + 256] = __float2half_rn(d1 * rstd * lw[tid + 256] + lb[tid + 256]);
    yr[tid + 512] = __float2half_rn(d2 * rstd * lw[tid + 512] + lb[tid + 512]);
}

// -------------------- layernorm -> fp16 (ln2) --------------------
__global__ __launch_bounds__(256) void ln_h(const float* __restrict__ x,
                                            const float* __restrict__ w,
                                            const float* __restrict__ b,
                                            h16* __restrict__ y)
{
    __shared__ float red[256];
    int tid = threadIdx.x;
    const float* xr = x + (size_t)blockIdx.x * DD;
    h16* yr = y + (size_t)blockIdx.x * DD;
    float v0 = xr[tid], v1 = xr[tid + 256], v2 = xr[tid + 512];
    red[tid] = v0 + v1 + v2;
    __syncthreads();
    for (int off = 128; off; off >>= 1) {
        if (tid < off) red[tid] += red[tid + off];
        __syncthreads();
    }
    float mean = red[0] * (1.0f / DD);
    __syncthreads();
    float d0 = v0 - mean, d1 = v1 - mean, d2 = v2 - mean;
    red[tid] = d0*d0 + d1*d1 + d2*d2;
    __syncthreads();
    for (int off = 128; off; off >>= 1) {
        if (tid < off) red[tid] += red[tid + off];
        __syncthreads();
    }
    float rstd = rsqrtf(red[0] * (1.0f / DD) + 1e-5f);
    yr[tid]       = __float2half_rn(d0 * rstd * w[tid]       + b[tid]);
    yr[tid + 256] = __float2half_rn(d1 * rstd * w[tid + 256] + b[tid + 256]);
    yr[tid + 512] = __float2half_rn(d2 * rstd * w[tid + 512] + b[tid + 512]);
}

// -------------------- flash attention (fp16, causal, K+V dbl-buffered) ----------
// Grid: (SS/128 q-tiles reversed, BH). 8 warps, each 16 q-rows x 128-col KV tile.
// SMEM planes (128 x 144B): Q | K0 | K1 | V0 | V1.  Q pre-scaled by 0.125*log2e.
// ONE __syncthreads per KV tile; softmax/PV/next-QK free to skew across warps.
__global__ __launch_bounds__(256) void flash_attn(
    const h16* __restrict__ qkv,
    h16* __restrict__ os)
{
    constexpr int STR = 144;
    constexpr int PL  = 128 * STR;       // 18432 per plane
    extern __shared__ __align__(128) char smem[];

    const int qt = gridDim.x - 1 - blockIdx.x;   // longest jobs first
    const int bh = blockIdx.y;
    const int b = bh / HH, h = bh % HH;
    const int tid = threadIdx.x, wid = tid >> 5, lane = tid & 31;
    const uint32_t sb = smem_u32(smem);

    const h16* Qb = qkv + (size_t)(b * SS + qt * 128) * (3 * DD) + h * HDD;
    const h16* Kb = qkv + (size_t)(b * SS) * (3 * DD) + DD + h * HDD;
    const h16* Vb = Kb + DD;

    auto loadQ = [&]() {
#pragma unroll
        for (int it = 0; it < 4; it++) {
            int idx = tid + it * 256;
            int r = idx >> 3, c = idx & 7;
            CP_ASYNC16(sb + r * STR + c * 16,
                       Qb + (size_t)r * (3 * DD) + c * 8);
        }
        CP_COMMIT();
    };
    // K_j -> plane (1+vb); V_j -> plane (3+vb). One commit group.
    auto loadKV = [&](int j, int vb) {
#pragma unroll
        for (int it = 0; it < 4; it++) {
            int idx = tid + it * 256;
            int r = idx >> 3, c = idx & 7;
            CP_ASYNC16(sb + (1 + vb) * PL + r * STR + c * 16,
                       Kb + (size_t)(j * 128 + r) * (3 * DD) + c * 8);
        }
#pragma unroll
        for (int it = 0; it < 4; it++) {
            int idx = tid + it * 256;
            int r = idx >> 3, c = idx & 7;
            CP_ASYNC16(sb + (3 + vb) * PL + r * STR + c * 16,
                       Vb + (size_t)(j * 128 + r) * (3 * DD) + c * 8);
        }
        CP_COMMIT();
    };

    loadQ();
    loadKV(0, 0);

    // softmax state: rows r0 = wid*16 + lane>>2, r1 = r0+8
    float mo0 = -1e30f, mo1 = -1e30f;
    float l0 = 0.f, l1 = 0.f;
    float oacc[8][4];
#pragma unroll
    for (int f = 0; f < 8; f++)
#pragma unroll
        for (int c = 0; c < 4; c++) oacc[f][c] = 0.f;

    for (int j = 0; j <= qt; j++) {
        const int vb = j & 1;
        CP_WAIT0();            // KV_j (and Q on first iter) arrived
        __syncthreads();       // visibility + guards buffer reuse (see proof)

        // ---- S = Q K^T   (Q pre-scaled: sacc already in log2-exp domain) ----
        float sacc[16][4];
#pragma unroll
        for (int f = 0; f < 16; f++)
#pragma unroll
            for (int c = 0; c < 4; c++) sacc[f][c] = 0.f;

#pragma unroll
        for (int ks = 0; ks < 4; ks++) {
            uint32_t aQ[4];
            uint32_t qaddr = sb + (wid * 16 + (lane & 15)) * STR + ks * 32 + ((lane >> 4) << 4);
            ldsm_x4(aQ, qaddr);
#pragma unroll
            for (int h8 = 0; h8 < 8; h8++) {
                uint32_t row = h8 * 16 + (lane & 7) + ((lane >> 4) << 3);
                uint32_t ch  = (lane >> 3) & 1;
                uint32_t ka  = sb + (1 + vb) * PL + row * STR + ks * 32 + ch * 16;
                uint32_t bK[4];
                ldsm_x4(bK, ka);
                mma16816(sacc[2*h8],   aQ, bK);
                mma16816(sacc[2*h8+1], aQ, bK + 2);
            }
        }

        // ---- online softmax (log2 domain) ----
        const bool diag = (j == qt);
        int rl0 = wid * 16 + (lane >> 2), rl1 = rl0 + 8;
        float mn0 = mo0, mn1 = mo1;
#pragma unroll
        for (int f = 0; f < 16; f++) {
            int cl = f * 8 + (lane & 3) * 2;
            float t0 = sacc[f][0], t1 = sacc[f][1];
            float t2 = sacc[f][2], t3 = sacc[f][3];
            if (diag) {
                if (cl     > rl0) t0 = -1e30f;
                if (cl + 1 > rl0) t1 = -1e30f;
                if (cl     > rl1) t2 = -1e30f;
                if (cl + 1 > rl1) t3 = -1e30f;
            }
            sacc[f][0] = t0; sacc[f][1] = t1; sacc[f][2] = t2; sacc[f][3] = t3;
            mn0 = fmaxf(mn0, fmaxf(t0, t1));
            mn1 = fmaxf(mn1, fmaxf(t2, t3));
        }
        mn0 = fmaxf(mn0, __shfl_xor_sync(0xffffffffu, mn0, 1));
        mn0 = fmaxf(mn0, __shfl_xor_sync(0xffffffffu, mn0, 2));
        mn1 = fmaxf(mn1, __shfl_xor_sync(0xffffffffu, mn1, 1));
        mn1 = fmaxf(mn1, __shfl_xor_sync(0xffffffffu, mn1, 2));

        float f0 = exp2f(mo0 - mn0), f1 = exp2f(mo1 - mn1);
        l0 *= f0; l1 *= f1;
#pragma unroll
        for (int f = 0; f < 8; f++) {
            oacc[f][0] *= f0; oacc[f][1] *= f0;
            oacc[f][2] *= f1; oacc[f][3] *= f1;
        }
        // exp in f16x2: subtract max in fp32, pack, h2exp2; results ARE PV fragments.
        uint32_t pr0[16], pr1[16];
#pragma unroll
        for (int f = 0; f < 16; f++) {
            __half2 ha = __floats2half2_rn(sacc[f][0] - mn0, sacc[f][1] - mn0);
            __half2 hb = __floats2half2_rn(sacc[f][2] - mn1, sacc[f][3] - mn1);
            pr0[f] = h2u2(h2exp2(ha));
            pr1[f] = h2u2(h2exp2(hb));
        }
        float s0 = 0.f, s1 = 0.f;
#pragma unroll
        for (int i = 0; i < 8; i++) {
            __half2 qa = __hadd2(u2h2(pr0[2*i]), u2h2(pr0[2*i+1]));  // pair sums <= 2
            __half2 qb = __hadd2(u2h2(pr1[2*i]), u2h2(pr1[2*i+1]));
            s0 += __low2float(qa) + __high2float(qa);
            s1 += __low2float(qb) + __high2float(qb);
        }
        // quad row-sum reduction (R7 fix — keep!)
        s0 += __shfl_xor_sync(0xffffffffu, s0, 1);
        s0 += __shfl_xor_sync(0xffffffffu, s0, 2);
        s1 += __shfl_xor_sync(0xffffffffu, s1, 1);
        s1 += __shfl_xor_sync(0xffffffffu, s1, 2);
        l0 += s0; l1 += s1;
        mo0 = mn0; mo1 = mn1;

        // issue next KV load (other buffer; safe per top-of-loop barrier proof)
        if (j < qt) loadKV(j + 1, vb ^ 1);

        // ---- O += P V_j  (V_j resident; fragments pr0/pr1 ready) ----
#pragma unroll
        for (int kk = 0; kk < 8; kk++) {
            uint32_t aP[4] = { pr0[2*kk], pr1[2*kk], pr0[2*kk+1], pr1[2*kk+1] };
#pragma unroll
            for (int h4 = 0; h4 < 4; h4++) {
                uint32_t row = kk * 16 + (lane & 7) + (((lane >> 3) & 1) << 3);
                uint32_t col = h4 * 16 + ((lane >> 4) << 3);
                uint32_t va  = sb + (3 + vb) * PL + row * STR + col * 2;
                uint32_t bV[4];
                ldsm_x4t(bV, va);
                mma16816(oacc[2*h4],   aP, bV);
                mma16816(oacc[2*h4+1], aP, bV + 2);
            }
        }
        // no trailing barrier — next iteration's top sync covers reuse
    }

    // ---- epilogue: O /= l, write fp16 ----
    float li0 = 1.0f / l0, li1 = 1.0f / l1;
    int m0r = b * SS + qt * 128 + wid * 16 + (lane >> 2);
    h16* oh = os + (size_t)m0r * DD + h * HDD;
#pragma unroll
    for (int f = 0; f < 8; f++) {
        int n = f * 8 + (lane & 3) * 2;
        *reinterpret_cast<uint32_t*>(oh + n) =
            packf2(oacc[f][0] * li0, oacc[f][1] * li0);
        *reinterpret_cast<uint32_t*>(oh + 8 * DD + n) =
            packf2(oacc[f][2] * li1, oacc[f][3] * li1);
    }
}

// -------------------- fp16 warp-MMA GEMM, BK=64, cp.async double-buffered -----
enum { EPI_QKV = 0, EPI_BIASRES = 1, EPI_GELU = 2 };

template<int EPI, bool OUT_HALF>
__global__ __launch_bounds__(256, 2) void mma_gemm2(
    const h16* __restrict__ A, const h16* __restrict__ Bm,
    const float* __restrict__ bias, const float* __restrict__ resid,
    void* __restrict__ Cout,
    int K, int lda, int ldb, int ldc)
{
    constexpr int BM = 128, BN = 128, BK = 64;
    constexpr int ASTR = 144;
    constexpr int APL  = BM * ASTR;      // 18432
    constexpr int BSTR = 144;
    constexpr int BPL  = BN * BSTR;      // 18432
    constexpr int BUF  = APL + BPL;      // 36864
    constexpr int MF = 4, NF = 4;

    extern __shared__ __align__(128) char smem[];

    const int m0 = blockIdx.y * BM, n0 = blockIdx.x * BN;
    const int tid = threadIdx.x, wid = tid >> 5, lane = tid & 31;
    const int wm0 = (wid & 1) * 64;
    const int wn0 = (wid >> 1) * 32;
    const uint32_t sb = smem_u32(smem);

    float acc[MF][NF][4];
#pragma unroll
    for (int i = 0; i < MF; i++)
#pragma unroll
        for (int jj = 0; jj < NF; jj++)
#pragma unroll
            for (int c = 0; c < 4; c++) acc[i][jj][c] = 0.f;

    int NT = K / BK;

    auto load_tile = [&](int kt, int bsel) {
        uint32_t base = sb + bsel * BUF;
#pragma unroll
        for (int it = 0; it < 4; it++) {
            int idx = tid + it * 256;
            int r = idx >> 3, c = idx & 7;
            const h16* src = A + (size_t)(m0 + r) * lda + kt * BK + c * 8;
            CP_ASYNC16(base + r * ASTR + c * 16, src);
        }
#pragma unroll
        for (int it = 0; it < 4; it++) {
            int idx = tid + it * 256;
            int r = idx >> 3, c = idx & 7;
            const h16* src = Bm + (size_t)(n0 + r) * ldb + kt * BK + c * 8;
            CP_ASYNC16(base + APL + r * BSTR + c * 16, src);
        }
        CP_COMMIT();
    };

    load_tile(0, 0);

    for (int kt = 0; kt < NT; kt++) {
        int buf = kt & 1;
        CP_WAIT0();
        __syncthreads();
        if (kt + 1 < NT) load_tile(kt + 1, buf ^ 1);

        uint32_t base = sb + buf * BUF;
#pragma unroll
        for (int ks = 0; ks < 4; ks++) {
            uint32_t bB[NF][2];
#pragma unroll
            for (int hh = 0; hh < 2; hh++) {
                uint32_t row = wn0 + hh * 16 + (lane & 7) + ((lane >> 4) << 3);
                uint32_t ch  = (lane >> 3) & 1;
                uint32_t ad  = base + APL + row * BSTR + ks * 32 + ch * 16;
                uint32_t r4[4];
                ldsm_x4(r4, ad);
                bB[hh*2][0]=r4[0]; bB[hh*2][1]=r4[1]; bB[hh*2+1][0]=r4[2]; bB[hh*2+1][1]=r4[3];
            }
#pragma unroll
            for (int mf = 0; mf < MF; mf++) {
                uint32_t row = wm0 + mf * 16 + (lane & 15);
                uint32_t ch  = lane >> 4;
                uint32_t ad  = base + row * ASTR + ks * 32 + ch * 16;
                uint32_t aA[4];
                ldsm_x4(aA, ad);
#pragma unroll
                for (int nf = 0; nf < NF; nf++)
                    mma16816(acc[mf][nf], aA, bB[nf]);
            }
        }
        __syncthreads();
    }

    // -------- epilogue --------
#pragma unroll
    for (int mf = 0; mf < MF; mf++) {
#pragma unroll
        for (int half = 0; half < 2; half++) {
            int m = m0 + wm0 + mf * 16 + (lane >> 2) + half * 8;
#pragma unroll
            for (int nf = 0; nf < NF; nf++) {
                int n = n0 + wn0 + nf * 8 + (lane & 3) * 2;
                float v0 = acc[mf][nf][half*2 + 0];
                float v1 = acc[mf][nf][half*2 + 1];
                if (bias) { v0 += __ldg(&bias[n]); v1 += __ldg(&bias[n+1]); }
                if (EPI == EPI_QKV) {
                    if (n < DD)     v0 *= SCLQ;
                    if (n + 1 < DD) v1 *= SCLQ;
                }
                if (EPI == EPI_GELU) {
                    v0 = 0.5f * v0 * (1.0f + erff(v0 * 0.70710678118654752f));
                    v1 = 0.5f * v1 * (1.0f + erff(v1 * 0.70710678118654752f));
                }
                if (EPI == EPI_BIASRES) {
                    const float* Rrow = resid + (size_t)m * ldc;
                    v0 += Rrow[n]; v1 += Rrow[n+1];
                }
                if (OUT_HALF) {
                    h16* Ch = (h16*)Cout + (size_t)m * ldc;
                    *reinterpret_cast<uint32_t*>(Ch + n) = packf2(v0, v1);
                } else {
                    float* Crow = (float*)Cout + (size_t)m * ldc;
                    *reinterpret_cast<float2*>(Crow + n) = make_float2(v0, v1);
                }
            }
        }
    }
}

// -------------------- host launcher --------------------
extern "C" void kernel_launch(void* const* d_in, const int* in_sizes, int n_in,
                              void* d_out, int out_size)
{
    const float* x     = (const float*)d_in[0];
    const float* qkv_w = (const float*)d_in[2];
    const float* qkv_b = (const float*)d_in[3];
    const float* out_w = (const float*)d_in[4];
    const float* out_b = (const float*)d_in[5];
    const float* fc1_w = (const float*)d_in[6];
    const float* fc1_b = (const float*)d_in[7];
    const float* fc2_w = (const float*)d_in[8];
    const float* fc2_b = (const float*)d_in[9];
    const float* ln1_w = (const float*)d_in[10];
    const float* ln1_b = (const float*)d_in[11];
    const float* ln2_w = (const float*)d_in[12];
    const float* ln2_b = (const float*)d_in[13];
    float* out = (float*)d_out;

    void *p0,*p1,*p4,*p5,*p6,*p7,*p8,*p9,*p10,*p11;
    cudaGetSymbolAddress(&p0,  g_hx);
    cudaGetSymbolAddress(&p1,  g_qkv);
    cudaGetSymbolAddress(&p4,  g_o);
    cudaGetSymbolAddress(&p5,  g_x1);
    cudaGetSymbolAddress(&p6,  g_h2);
    cudaGetSymbolAddress(&p7,  g_ff1);
    cudaGetSymbolAddress(&p8,  g_qkvw);
    cudaGetSymbolAddress(&p9,  g_outw);
    cudaGetSymbolAddress(&p10, g_fc1w);
    cudaGetSymbolAddress(&p11, g_fc2w);
    h16* hx   = (h16*)p0;  h16* qkv  = (h16*)p1;
    h16* o    = (h16*)p4;  float* x1 = (float*)p5;
    h16* h2   = (h16*)p6;  h16* ff1  = (h16*)p7;
    h16* qkvw = (h16*)p8;  h16* outw = (h16*)p9;
    h16* fc1w = (h16*)p10; h16* fc2w = (h16*)p11;

    const int SMEM_GEMM = 2 * 36864;     // 73728 (x2 CTAs = 147KB/SM)
    const int SMEM_FA   = 5 * 128 * 144; // 92160 (Q,K0,K1,V0,V1)

    cudaFuncSetAttribute(mma_gemm2<EPI_QKV,    true >,
                         cudaFuncAttributeMaxDynamicSharedMemorySize, SMEM_GEMM);
    cudaFuncSetAttribute(mma_gemm2<EPI_BIASRES,false>,
                         cudaFuncAttributeMaxDynamicSharedMemorySize, SMEM_GEMM);
    cudaFuncSetAttribute(mma_gemm2<EPI_GELU,   true >,
                         cudaFuncAttributeMaxDynamicSharedMemorySize, SMEM_GEMM);
    cudaFuncSetAttribute(flash_attn,
                         cudaFuncAttributeMaxDynamicSharedMemorySize, SMEM_FA);

    // 0+1. weight converts + ln1 fused into one launch (independent inputs)
    prep_all<<<6912 + ROWS, 256>>>(qkv_w, qkvw, out_w, outw,
                                   fc1_w, fc1w, fc2_w, fc2w,
                                   x, ln1_w, ln1_b, hx);

    // 2. QKV (Q pre-scaled in epilogue)
    mma_gemm2<EPI_QKV,true>
        <<<dim3(3*DD/128, ROWS/128, 1), 256, SMEM_GEMM>>>(
            hx, qkvw, qkv_b, nullptr, qkv,
            DD, DD, DD, 3*DD);

    // 3-5. flash attention -> o fp16
    flash_attn<<<dim3(SS/128, BH), 256, SMEM_FA>>>(qkv, o);

    // 6. x1 = x + O @ out_w^T + out_b   (fp32 out)
    mma_gemm2<EPI_BIASRES,false>
        <<<dim3(DD/128, ROWS/128, 1), 256, SMEM_GEMM>>>(
            o, outw, out_b, x, x1,
            DD, DD, DD, DD);

    // 7. ln2 -> h2 fp16
    ln_h<<<ROWS, 256>>>(x1, ln2_w, ln2_b, h2);

    // 8. ff1 = gelu(h2 @ fc1_w^T + fc1_b) -> fp16
    mma_gemm2<EPI_GELU,true>
        <<<dim3(FF/128, ROWS/128, 1), 256, SMEM_GEMM>>>(
            h2, fc1w, fc1_b, nullptr, ff1,
            DD, DD, DD, FF);

    // 9. out = x1 + ff1 @ fc2_w^T + fc2_b   (fp32 out)
    mma_gemm2<EPI_BIASRES,false>
        <<<dim3(DD/128, ROWS/128, 1), 256, SMEM_GEMM>>>(
            ff1, fc2w, fc2_b, x1, out,
            FF, FF, FF, DD);
}

// round 14
// speedup vs baseline: 7.1480x; 1.0061x over previous
#include <cuda_runtime.h>
#include <cuda_fp16.h>
#include <math.h>
#include <stdint.h>

typedef __half h16;

// Problem constants
#define BB 2
#define SS 2048
#define DD 768
#define HH 12
#define FF 3072
#define HDD 64
#define ROWS (BB*SS)          // 4096
#define BH (BB*HH)            // 24

// -------------------- device scratch (single fp16 activations) --------------------
__device__ __align__(16) h16  g_hx  [ROWS*DD];
__device__ __align__(16) h16  g_qkv [ROWS*3*DD];
__device__ __align__(16) h16  g_o   [ROWS*DD];
__device__ __align__(16) float g_x1 [ROWS*DD];
__device__ __align__(16) h16  g_h2  [ROWS*DD];
__device__ __align__(16) h16  g_ff1 [ROWS*FF];
__device__ __align__(16) h16  g_qkvw[3*DD*DD];
__device__ __align__(16) h16  g_outw[DD*DD];
__device__ __align__(16) h16  g_fc1w[FF*DD];
__device__ __align__(16) h16  g_fc2w[DD*FF];

// -------------------- helpers --------------------
__device__ __forceinline__ uint32_t smem_u32(const void* p){
    uint32_t a;
    asm("{ .reg .u64 t; cvta.to.shared.u64 t, %1; cvt.u32.u64 %0, t; }"
        : "=r"(a) : "l"(p));
    return a;
}
__device__ __forceinline__ void ldsm_x4(uint32_t* r, uint32_t a){
    asm volatile("ldmatrix.sync.aligned.m8n8.x4.shared.b16 {%0,%1,%2,%3}, [%4];"
        : "=r"(r[0]),"=r"(r[1]),"=r"(r[2]),"=r"(r[3]) : "r"(a));
}
__device__ __forceinline__ void ldsm_x4t(uint32_t* r, uint32_t a){
    asm volatile("ldmatrix.sync.aligned.m8n8.x4.trans.shared.b16 {%0,%1,%2,%3}, [%4];"
        : "=r"(r[0]),"=r"(r[1]),"=r"(r[2]),"=r"(r[3]) : "r"(a));
}
__device__ __forceinline__ void mma16816(float* c, const uint32_t* a, const uint32_t* b){
    asm volatile(
        "mma.sync.aligned.m16n8k16.row.col.f32.f16.f16.f32 "
        "{%0,%1,%2,%3}, {%4,%5,%6,%7}, {%8,%9}, {%0,%1,%2,%3};"
        : "+f"(c[0]),"+f"(c[1]),"+f"(c[2]),"+f"(c[3])
        : "r"(a[0]),"r"(a[1]),"r"(a[2]),"r"(a[3]), "r"(b[0]),"r"(b[1]));
}
#define CP_ASYNC16(dst, src) \
    asm volatile("cp.async.cg.shared.global [%0], [%1], 16;" :: "r"(dst), "l"(src))
#define CP_COMMIT() asm volatile("cp.async.commit_group;" ::: "memory")
#define CP_WAIT0()  asm volatile("cp.async.wait_group 0;" ::: "memory")

static __device__ __forceinline__ uint32_t packf2(float a, float b){
    __half2 h = __floats2half2_rn(a, b);
    return *reinterpret_cast<uint32_t*>(&h);
}
static __device__ __forceinline__ __half2 u2h2(uint32_t u){
    return *reinterpret_cast<__half2*>(&u);
}
static __device__ __forceinline__ uint32_t h2u2(__half2 h){
    return *reinterpret_cast<uint32_t*>(&h);
}

#define SCLQ 0.18033688011112042f   // 0.125 * log2(e), folded into Q at QKV epilogue

// -------------------- fused weight convert + ln1 (one launch) --------------------
__global__ __launch_bounds__(256) void prep_all(
    const float* __restrict__ w0, h16* __restrict__ o0,
    const float* __restrict__ w1, h16* __restrict__ o1,
    const float* __restrict__ w2, h16* __restrict__ o2,
    const float* __restrict__ w3, h16* __restrict__ o3,
    const float* __restrict__ x,  const float* __restrict__ lw,
    const float* __restrict__ lb, h16* __restrict__ y)
{
    __shared__ float red[256];
    int tid = threadIdx.x;
    if (blockIdx.x < 6912) {
        int i = blockIdx.x * 256 + tid;
        const float* w; h16* o; int j;
        if (i < 442368)       { w = w0; o = o0; j = i; }
        else if (i < 589824)  { w = w1; o = o1; j = i - 442368; }
        else if (i < 1179648) { w = w2; o = o2; j = i - 589824; }
        else                  { w = w3; o = o3; j = i - 1179648; }
        float4 v = reinterpret_cast<const float4*>(w)[j];
        uint2 r;
        r.x = packf2(v.x, v.y);
        r.y = packf2(v.z, v.w);
        reinterpret_cast<uint2*>(o)[j] = r;
        return;
    }
    int row = blockIdx.x - 6912;
    const float* xr = x + (size_t)row * DD;
    h16* yr = y + (size_t)row * DD;
    float v0 = xr[tid], v1 = xr[tid + 256], v2 = xr[tid + 512];
    red[tid] = v0 + v1 + v2;
    __syncthreads();
    for (int off = 128; off; off >>= 1) {
        if (tid < off) red[tid] += red[tid + off];
        __syncthreads();
    }
    float mean = red[0] * (1.0f / DD);
    __syncthreads();
    float d0 = v0 - mean, d1 = v1 - mean, d2 = v2 - mean;
    red[tid] = d0*d0 + d1*d1 + d2*d2;
    __syncthreads();
    for (int off = 128; off; off >>= 1) {
        if (tid < off) red[tid] += red[tid + off];
        __syncthreads();
    }
    float rstd = rsqrtf(red[0] * (1.0f / DD) + 1e-5f);
    yr[tid]       = __float2half_rn(d0 * rstd * lw[tid]       + lb[tid]);
    yr[tid + 256] = __float2half_rn(d1 * rstd * lw[tid + 256] + lb[tid + 256]);
    yr[tid + 512] = __float2half_rn(d2 * rstd * lw[tid + 512] + lb[tid + 512]);
}

// -------------------- layernorm -> fp16 (ln2) --------------------
__global__ __launch_bounds__(256) void ln_h(const float* __restrict__ x,
                                            const float* __restrict__ w,
                                            const float* __restrict__ b,
                                            h16* __restrict__ y)
{
    __shared__ float red[256];
    int tid = threadIdx.x;
    const float* xr = x + (size_t)blockIdx.x * DD;
    h16* yr = y + (size_t)blockIdx.x * DD;
    float v0 = xr[tid], v1 = xr[tid + 256], v2 = xr[tid + 512];
    red[tid] = v0 + v1 + v2;
    __syncthreads();
    for (int off = 128; off; off >>= 1) {
        if (tid < off) red[tid] += red[tid + off];
        __syncthreads();
    }
    float mean = red[0] * (1.0f / DD);
    __syncthreads();
    float d0 = v0 - mean, d1 = v1 - mean, d2 = v2 - mean;
    red[tid] = d0*d0 + d1*d1 + d2*d2;
    __syncthreads();
    for (int off = 128; off; off >>= 1) {
        if (tid < off) red[tid] += red[tid + off];
        __syncthreads();
    }
    float rstd = rsqrtf(red[0] * (1.0f / DD) + 1e-5f);
    yr[tid]       = __float2half_rn(d0 * rstd * w[tid]       + b[tid]);
    yr[tid + 256] = __float2half_rn(d1 * rstd * w[tid + 256] + b[tid + 256]);
    yr[tid + 512] = __float2half_rn(d2 * rstd * w[tid + 512] + b[tid + 512]);
}

// -------------------- flash attention (fp16, causal, K+V dbl-buffered) ----------
__global__ __launch_bounds__(256) void flash_attn(
    const h16* __restrict__ qkv,
    h16* __restrict__ os)
{
    constexpr int STR = 144;
    constexpr int PL  = 128 * STR;       // 18432 per plane
    extern __shared__ __align__(128) char smem[];

    const int qt = gridDim.x - 1 - blockIdx.x;   // longest jobs first
    const int bh = blockIdx.y;
    const int b = bh / HH, h = bh % HH;
    const int tid = threadIdx.x, wid = tid >> 5, lane = tid & 31;
    const uint32_t sb = smem_u32(smem);

    const h16* Qb = qkv + (size_t)(b * SS + qt * 128) * (3 * DD) + h * HDD;
    const h16* Kb = qkv + (size_t)(b * SS) * (3 * DD) + DD + h * HDD;
    const h16* Vb = Kb + DD;

    auto loadQ = [&]() {
#pragma unroll
        for (int it = 0; it < 4; it++) {
            int idx = tid + it * 256;
            int r = idx >> 3, c = idx & 7;
            CP_ASYNC16(sb + r * STR + c * 16,
                       Qb + (size_t)r * (3 * DD) + c * 8);
        }
        CP_COMMIT();
    };
    auto loadKV = [&](int j, int vb) {
#pragma unroll
        for (int it = 0; it < 4; it++) {
            int idx = tid + it * 256;
            int r = idx >> 3, c = idx & 7;
            CP_ASYNC16(sb + (1 + vb) * PL + r * STR + c * 16,
                       Kb + (size_t)(j * 128 + r) * (3 * DD) + c * 8);
        }
#pragma unroll
        for (int it = 0; it < 4; it++) {
            int idx = tid + it * 256;
            int r = idx >> 3, c = idx & 7;
            CP_ASYNC16(sb + (3 + vb) * PL + r * STR + c * 16,
                       Vb + (size_t)(j * 128 + r) * (3 * DD) + c * 8);
        }
        CP_COMMIT();
    };

    loadQ();
    loadKV(0, 0);

    float mo0 = -1e30f, mo1 = -1e30f;
    float l0 = 0.f, l1 = 0.f;
    float oacc[8][4];
#pragma unroll
    for (int f = 0; f < 8; f++)
#pragma unroll
        for (int c = 0; c < 4; c++) oacc[f][c] = 0.f;

    for (int j = 0; j <= qt; j++) {
        const int vb = j & 1;
        CP_WAIT0();
        __syncthreads();

        // ---- S = Q K^T ----
        float sacc[16][4];
#pragma unroll
        for (int f = 0; f < 16; f++)
#pragma unroll
            for (int c = 0; c < 4; c++) sacc[f][c] = 0.f;

#pragma unroll
        for (int ks = 0; ks < 4; ks++) {
            uint32_t aQ[4];
            uint32_t qaddr = sb + (wid * 16 + (lane & 15)) * STR + ks * 32 + ((lane >> 4) << 4);
            ldsm_x4(aQ, qaddr);
#pragma unroll
            for (int h8 = 0; h8 < 8; h8++) {
                uint32_t row = h8 * 16 + (lane & 7) + ((lane >> 4) << 3);
                uint32_t ch  = (lane >> 3) & 1;
                uint32_t ka  = sb + (1 + vb) * PL + row * STR + ks * 32 + ch * 16;
                uint32_t bK[4];
                ldsm_x4(bK, ka);
                mma16816(sacc[2*h8],   aQ, bK);
                mma16816(sacc[2*h8+1], aQ, bK + 2);
            }
        }

        // ---- online softmax (log2 domain) ----
        const bool diag = (j == qt);
        int rl0 = wid * 16 + (lane >> 2), rl1 = rl0 + 8;
        float mn0 = mo0, mn1 = mo1;
#pragma unroll
        for (int f = 0; f < 16; f++) {
            int cl = f * 8 + (lane & 3) * 2;
            float t0 = sacc[f][0], t1 = sacc[f][1];
            float t2 = sacc[f][2], t3 = sacc[f][3];
            if (diag) {
                if (cl     > rl0) t0 = -1e30f;
                if (cl + 1 > rl0) t1 = -1e30f;
                if (cl     > rl1) t2 = -1e30f;
                if (cl + 1 > rl1) t3 = -1e30f;
            }
            sacc[f][0] = t0; sacc[f][1] = t1; sacc[f][2] = t2; sacc[f][3] = t3;
            mn0 = fmaxf(mn0, fmaxf(t0, t1));
            mn1 = fmaxf(mn1, fmaxf(t2, t3));
        }
        mn0 = fmaxf(mn0, __shfl_xor_sync(0xffffffffu, mn0, 1));
        mn0 = fmaxf(mn0, __shfl_xor_sync(0xffffffffu, mn0, 2));
        mn1 = fmaxf(mn1, __shfl_xor_sync(0xffffffffu, mn1, 1));
        mn1 = fmaxf(mn1, __shfl_xor_sync(0xffffffffu, mn1, 2));

        float f0 = exp2f(mo0 - mn0), f1 = exp2f(mo1 - mn1);
        l0 *= f0; l1 *= f1;
#pragma unroll
        for (int f = 0; f < 8; f++) {
            oacc[f][0] *= f0; oacc[f][1] *= f0;
            oacc[f][2] *= f1; oacc[f][3] *= f1;
        }
        uint32_t pr0[16], pr1[16];
#pragma unroll
        for (int f = 0; f < 16; f++) {
            __half2 ha = __floats2half2_rn(sacc[f][0] - mn0, sacc[f][1] - mn0);
            __half2 hb = __floats2half2_rn(sacc[f][2] - mn1, sacc[f][3] - mn1);
            pr0[f] = h2u2(h2exp2(ha));
            pr1[f] = h2u2(h2exp2(hb));
        }
        float s0 = 0.f, s1 = 0.f;
#pragma unroll
        for (int i = 0; i < 8; i++) {
            __half2 qa = __hadd2(u2h2(pr0[2*i]), u2h2(pr0[2*i+1]));
            __half2 qb = __hadd2(u2h2(pr1[2*i]), u2h2(pr1[2*i+1]));
            s0 += __low2float(qa) + __high2float(qa);
            s1 += __low2float(qb) + __high2float(qb);
        }
        s0 += __shfl_xor_sync(0xffffffffu, s0, 1);
        s0 += __shfl_xor_sync(0xffffffffu, s0, 2);
        s1 += __shfl_xor_sync(0xffffffffu, s1, 1);
        s1 += __shfl_xor_sync(0xffffffffu, s1, 2);
        l0 += s0; l1 += s1;
        mo0 = mn0; mo1 = mn1;

        if (j < qt) loadKV(j + 1, vb ^ 1);

        // ---- O += P V_j ----
#pragma unroll
        for (int kk = 0; kk < 8; kk++) {
            uint32_t aP[4] = { pr0[2*kk], pr1[2*kk], pr0[2*kk+1], pr1[2*kk+1] };
#pragma unroll
            for (int h4 = 0; h4 < 4; h4++) {
                uint32_t row = kk * 16 + (lane & 7) + (((lane >> 3) & 1) << 3);
                uint32_t col = h4 * 16 + ((lane >> 4) << 3);
                uint32_t va  = sb + (3 + vb) * PL + row * STR + col * 2;
                uint32_t bV[4];
                ldsm_x4t(bV, va);
                mma16816(oacc[2*h4],   aP, bV);
                mma16816(oacc[2*h4+1], aP, bV + 2);
            }
        }
    }

    float li0 = 1.0f / l0, li1 = 1.0f / l1;
    int m0r = b * SS + qt * 128 + wid * 16 + (lane >> 2);
    h16* oh = os + (size_t)m0r * DD + h * HDD;
#pragma unroll
    for (int f = 0; f < 8; f++) {
        int n = f * 8 + (lane & 3) * 2;
        *reinterpret_cast<uint32_t*>(oh + n) =
            packf2(oacc[f][0] * li0, oacc[f][1] * li0);
        *reinterpret_cast<uint32_t*>(oh + 8 * DD + n) =
            packf2(oacc[f][2] * li1, oacc[f][3] * li1);
    }
}

// -------------------- fp16 warp-MMA GEMM, BK=64, cp.async double-buffered -----
// BN=128: 8 warps as 2x4 (warp 64x32, MF=4). BN=64: 8 warps as 4x2 (warp 32x32, MF=2).
enum { EPI_QKV = 0, EPI_BIASRES = 1, EPI_GELU = 2 };

template<int BN, int EPI, bool OUT_HALF>
__global__ __launch_bounds__(256, 2) void mma_gemm2(
    const h16* __restrict__ A, const h16* __restrict__ Bm,
    const float* __restrict__ bias, const float* __restrict__ resid,
    void* __restrict__ Cout,
    int K, int lda, int ldb, int ldc)
{
    constexpr int BM = 128, BK = 64;
    constexpr int ASTR = 144;
    constexpr int APL  = BM * ASTR;      // 18432
    constexpr int BSTR = 144;
    constexpr int BPL  = BN * BSTR;      // 18432 / 9216
    constexpr int BUF  = APL + BPL;
    constexpr int MF = (BN == 128) ? 4 : 2;
    constexpr int NF = 4;

    extern __shared__ __align__(128) char smem[];

    const int m0 = blockIdx.y * BM, n0 = blockIdx.x * BN;
    const int tid = threadIdx.x, wid = tid >> 5, lane = tid & 31;
    const int wm0 = (BN == 128) ? (wid & 1) * 64 : (wid & 3) * 32;
    const int wn0 = (BN == 128) ? (wid >> 1) * 32 : (wid >> 2) * 32;
    const uint32_t sb = smem_u32(smem);

    float acc[MF][NF][4];
#pragma unroll
    for (int i = 0; i < MF; i++)
#pragma unroll
        for (int jj = 0; jj < NF; jj++)
#pragma unroll
            for (int c = 0; c < 4; c++) acc[i][jj][c] = 0.f;

    int NT = K / BK;

    auto load_tile = [&](int kt, int bsel) {
        uint32_t base = sb + bsel * BUF;
#pragma unroll
        for (int it = 0; it < 4; it++) {
            int idx = tid + it * 256;
            int r = idx >> 3, c = idx & 7;
            const h16* src = A + (size_t)(m0 + r) * lda + kt * BK + c * 8;
            CP_ASYNC16(base + r * ASTR + c * 16, src);
        }
#pragma unroll
        for (int it = 0; it < BN / 32; it++) {
            int idx = tid + it * 256;
            int r = idx >> 3, c = idx & 7;
            const h16* src = Bm + (size_t)(n0 + r) * ldb + kt * BK + c * 8;
            CP_ASYNC16(base + APL + r * BSTR + c * 16, src);
        }
        CP_COMMIT();
    };

    load_tile(0, 0);

    for (int kt = 0; kt < NT; kt++) {
        int buf = kt & 1;
        CP_WAIT0();
        __syncthreads();
        if (kt + 1 < NT) load_tile(kt + 1, buf ^ 1);

        uint32_t base = sb + buf * BUF;
#pragma unroll
        for (int ks = 0; ks < 4; ks++) {
            uint32_t bB[NF][2];
#pragma unroll
            for (int hh = 0; hh < 2; hh++) {
                uint32_t row = wn0 + hh * 16 + (lane & 7) + ((lane >> 4) << 3);
                uint32_t ch  = (lane >> 3) & 1;
                uint32_t ad  = base + APL + row * BSTR + ks * 32 + ch * 16;
                uint32_t r4[4];
                ldsm_x4(r4, ad);
                bB[hh*2][0]=r4[0]; bB[hh*2][1]=r4[1]; bB[hh*2+1][0]=r4[2]; bB[hh*2+1][1]=r4[3];
            }
#pragma unroll
            for (int mf = 0; mf < MF; mf++) {
                uint32_t row = wm0 + mf * 16 + (lane & 15);
                uint32_t ch  = lane >> 4;
                uint32_t ad  = base + row * ASTR + ks * 32 + ch * 16;
                uint32_t aA[4];
                ldsm_x4(aA, ad);
#pragma unroll
                for (int nf = 0; nf < NF; nf++)
                    mma16816(acc[mf][nf], aA, bB[nf]);
            }
        }
        __syncthreads();
    }

    // -------- epilogue --------
#pragma unroll
    for (int mf = 0; mf < MF; mf++) {
#pragma unroll
        for (int half = 0; half < 2; half++) {
            int m = m0 + wm0 + mf * 16 + (lane >> 2) + half * 8;
#pragma unroll
            for (int nf = 0; nf < NF; nf++) {
                int n = n0 + wn0 + nf * 8 + (lane & 3) * 2;
                float v0 = acc[mf][nf][half*2 + 0];
                float v1 = acc[mf][nf][half*2 + 1];
                if (bias) { v0 += __ldg(&bias[n]); v1 += __ldg(&bias[n+1]); }
                if (EPI == EPI_QKV) {
                    if (n < DD)     v0 *= SCLQ;
                    if (n + 1 < DD) v1 *= SCLQ;
                }
                if (EPI == EPI_GELU) {
                    v0 = 0.5f * v0 * (1.0f + erff(v0 * 0.70710678118654752f));
                    v1 = 0.5f * v1 * (1.0f + erff(v1 * 0.70710678118654752f));
                }
                if (EPI == EPI_BIASRES) {
                    const float* Rrow = resid + (size_t)m * ldc;
                    v0 += Rrow[n]; v1 += Rrow[n+1];
                }
                if (OUT_HALF) {
                    h16* Ch = (h16*)Cout + (size_t)m * ldc;
                    *reinterpret_cast<uint32_t*>(Ch + n) = packf2(v0, v1);
                } else {
                    float* Crow = (float*)Cout + (size_t)m * ldc;
                    *reinterpret_cast<float2*>(Crow + n) = make_float2(v0, v1);
                }
            }
        }
    }
}

// -------------------- host launcher --------------------
extern "C" void kernel_launch(void* const* d_in, const int* in_sizes, int n_in,
                              void* d_out, int out_size)
{
    const float* x     = (const float*)d_in[0];
    const float* qkv_w = (const float*)d_in[2];
    const float* qkv_b = (const float*)d_in[3];
    const float* out_w = (const float*)d_in[4];
    const float* out_b = (const float*)d_in[5];
    const float* fc1_w = (const float*)d_in[6];
    const float* fc1_b = (const float*)d_in[7];
    const float* fc2_w = (const float*)d_in[8];
    const float* fc2_b = (const float*)d_in[9];
    const float* ln1_w = (const float*)d_in[10];
    const float* ln1_b = (const float*)d_in[11];
    const float* ln2_w = (const float*)d_in[12];
    const float* ln2_b = (const float*)d_in[13];
    float* out = (float*)d_out;

    void *p0,*p1,*p4,*p5,*p6,*p7,*p8,*p9,*p10,*p11;
    cudaGetSymbolAddress(&p0,  g_hx);
    cudaGetSymbolAddress(&p1,  g_qkv);
    cudaGetSymbolAddress(&p4,  g_o);
    cudaGetSymbolAddress(&p5,  g_x1);
    cudaGetSymbolAddress(&p6,  g_h2);
    cudaGetSymbolAddress(&p7,  g_ff1);
    cudaGetSymbolAddress(&p8,  g_qkvw);
    cudaGetSymbolAddress(&p9,  g_outw);
    cudaGetSymbolAddress(&p10, g_fc1w);
    cudaGetSymbolAddress(&p11, g_fc2w);
    h16* hx   = (h16*)p0;  h16* qkv  = (h16*)p1;
    h16* o    = (h16*)p4;  float* x1 = (float*)p5;
    h16* h2   = (h16*)p6;  h16* ff1  = (h16*)p7;
    h16* qkvw = (h16*)p8;  h16* outw = (h16*)p9;
    h16* fc1w = (h16*)p10; h16* fc2w = (h16*)p11;

    const int SMEM_G128 = 2 * (18432 + 18432);   // 73728
    const int SMEM_G64  = 2 * (18432 + 9216);    // 55296
    const int SMEM_FA   = 5 * 128 * 144;         // 92160

    cudaFuncSetAttribute(mma_gemm2<128,EPI_QKV,    true >,
                         cudaFuncAttributeMaxDynamicSharedMemorySize, SMEM_G128);
    cudaFuncSetAttribute(mma_gemm2<64, EPI_BIASRES,false>,
                         cudaFuncAttributeMaxDynamicSharedMemorySize, SMEM_G64);
    cudaFuncSetAttribute(mma_gemm2<128,EPI_GELU,   true >,
                         cudaFuncAttributeMaxDynamicSharedMemorySize, SMEM_G128);
    cudaFuncSetAttribute(flash_attn,
                         cudaFuncAttributeMaxDynamicSharedMemorySize, SMEM_FA);

    // 0+1. weight converts + ln1 fused
    prep_all<<<6912 + ROWS, 256>>>(qkv_w, qkvw, out_w, outw,
                                   fc1_w, fc1w, fc2_w, fc2w,
                                   x, ln1_w, ln1_b, hx);

    // 2. QKV (Q pre-scaled in epilogue)
    mma_gemm2<128,EPI_QKV,true>
        <<<dim3(3*DD/128, ROWS/128, 1), 256, SMEM_G128>>>(
            hx, qkvw, qkv_b, nullptr, qkv,
            DD, DD, DD, 3*DD);

    // 3-5. flash attention -> o fp16
    flash_attn<<<dim3(SS/128, BH), 256, SMEM_FA>>>(qkv, o);

    // 6. x1 = x + O @ out_w^T + out_b   (fp32 out; BN=64: 384 CTAs)
    mma_gemm2<64,EPI_BIASRES,false>
        <<<dim3(DD/64, ROWS/128, 1), 256, SMEM_G64>>>(
            o, outw, out_b, x, x1,
            DD, DD, DD, DD);

    // 7. ln2 -> h2 fp16
    ln_h<<<ROWS, 256>>>(x1, ln2_w, ln2_b, h2);

    // 8. ff1 = gelu(h2 @ fc1_w^T + fc1_b) -> fp16
    mma_gemm2<128,EPI_GELU,true>
        <<<dim3(FF/128, ROWS/128, 1), 256, SMEM_G128>>>(
            h2, fc1w, fc1_b, nullptr, ff1,
            DD, DD, DD, FF);

    // 9. out = x1 + ff1 @ fc2_w^T + fc2_b   (fp32 out; BN=64: 384 CTAs)
    mma_gemm2<64,EPI_BIASRES,false>
        <<<dim3(DD/64, ROWS/128, 1), 256, SMEM_G64>>>(
            ff1, fc2w, fc2_b, x1, out,
            FF, FF, FF, DD);
}